// round 4
// baseline (speedup 1.0000x reference)
#include <cuda_runtime.h>
#include <cuda_fp16.h>
#include <cstdint>

#define B_ 2
#define T_ 16
#define N_ 2000
#define F_ 16
#define E_ 32000
#define H_ 4
#define C_ 32
#define D_ 64
#define FF_ 2048
#define G_ (B_*T_)      /* 32  */
#define ET_ (E_+N_)     /* 34000 */
#define BN_ (B_*N_)     /* 4000 */
#define GN_ (G_*N_)     /* 64000 */

// ---------------- scratch (static device globals; no allocation) -------------
__device__ __half g_h[(size_t)GN_ * 128];  // h: [G,N,H*C] fp16
__device__ float g_asrc[GN_ * 4];
__device__ float g_adst[GN_ * 4];
__device__ float g_prep[8];               // c_edge[0..3], ew_mean at [4]
__device__ unsigned long long g_ewsum;    // fixed-point sum of edge weights
__device__ int   g_deg[2048];
__device__ int   g_off[N_ + 1];
__device__ int   g_cur[N_];
__device__ int   g_csr[ET_];
__device__ float g_y[GN_ * D_];           // [bn][t][d]  (row rn = bn*16+t)
__device__ float g_kv[(size_t)GN_ * 128]; // [rn][0:64)=K, [64:128)=V
__device__ float g_z[BN_ * D_];           // post-LN1
__device__ __half g_ff[(size_t)BN_ * FF_]; // relu(z@W1+b1) fp16
__device__ float g_acc[4][BN_ * D_];      // ffn2 split-K partials
__device__ int   g_cnt[BN_ / 32];         // per-row-block completion counters

union HCvt { __half2 h2; uint32_t u; };

// ---------------- count (fused with edge-weight sum) -------------------------
__global__ void k_count(const int* __restrict__ ei, const float* __restrict__ ew) {
    int e = blockIdx.x * blockDim.x + threadIdx.x;
    if (e >= ET_) return;
    int d;
    if (e < E_) {
        d = ei[E_ + e];
        atomicAdd(&g_ewsum, (unsigned long long)((double)ew[e] * 4294967296.0));
    } else {
        d = e - E_;
    }
    atomicAdd(&g_deg[d], 1);
}

// ---------------- scan (+ edge consts, self-zero deg & ewsum) ----------------
__global__ void k_scan(const float* __restrict__ W_edge,
                       const float* __restrict__ att_edge) {
    __shared__ int ws[32];
    int t = threadIdx.x;                 // 1024 threads, 2 elems each
    int i0 = 2 * t, i1 = 2 * t + 1;
    int a = (i0 < N_) ? g_deg[i0] : 0;
    int b = (i1 < N_) ? g_deg[i1] : 0;
    int v = a + b;
    int lane = t & 31, wid = t >> 5;
#pragma unroll
    for (int off = 1; off < 32; off <<= 1) {
        int n = __shfl_up_sync(0xffffffffu, v, off);
        if (lane >= off) v += n;
    }
    if (lane == 31) ws[wid] = v;
    __syncthreads();
    if (t < 32) {
        int u = ws[t];
#pragma unroll
        for (int off = 1; off < 32; off <<= 1) {
            int n = __shfl_up_sync(0xffffffffu, u, off);
            if (t >= off) u += n;
        }
        ws[t] = u;
    }
    __syncthreads();
    int base = (wid > 0) ? ws[wid - 1] : 0;
    int incl = v + base;
    int ex0 = incl - a - b;
    if (i0 <= N_) { g_off[i0] = ex0; if (i0 < N_) g_cur[i0] = ex0; }
    if (i1 <= N_) { g_off[i1] = ex0 + a; if (i1 < N_) g_cur[i1] = ex0 + a; }
    g_deg[i0] = 0; g_deg[i1] = 0;        // re-zero for next launch
    if (t < 4) {
        float c = 0.f;
        for (int j = 0; j < 32; j++) c += W_edge[t * 32 + j] * att_edge[t * 32 + j];
        g_prep[t] = c;
    }
    if (t == 4) {
        g_prep[4] = (float)((double)g_ewsum / 4294967296.0 / (double)E_);
        g_ewsum = 0ull;                  // re-zero for next launch
    }
}

__global__ void k_scatter(const int* __restrict__ ei) {
    int e = blockIdx.x * blockDim.x + threadIdx.x;
    if (e >= ET_) return;
    int d = (e < E_) ? ei[E_ + e] : (e - E_);
    int pos = atomicAdd(&g_cur[d], 1);
    g_csr[pos] = e;
}

// ---------------- h = x @ W_gat (fp16 out); attn scalar terms (fp32) ---------
__global__ void __launch_bounds__(256) k_h(const float* __restrict__ x,
                                           const float* __restrict__ Wg,
                                           const float* __restrict__ as_w,
                                           const float* __restrict__ ad_w) {
    __shared__ float Wgs[16 * 128];
    __shared__ float s_as[128], s_ad[128];
    int tid = threadIdx.x;
    for (int i = tid; i < 2048; i += 256) Wgs[i] = Wg[i];
    for (int i = tid; i < 128; i += 256) { s_as[i] = as_w[i]; s_ad[i] = ad_w[i]; }
    __syncthreads();
    int w = blockIdx.x * 8 + (tid >> 5);
    if (w >= GN_) return;
    int lane = tid & 31;
    const float* xr = x + (size_t)w * 16;
    float xf = (lane < 16) ? xr[lane] : 0.f;
    float4 h4 = make_float4(0.f, 0.f, 0.f, 0.f);
    const float4* Wg4 = (const float4*)Wgs;
#pragma unroll
    for (int f = 0; f < 16; f++) {
        float xv = __shfl_sync(0xffffffffu, xf, f);
        float4 wv = Wg4[f * 32 + lane];
        h4.x += xv * wv.x; h4.y += xv * wv.y; h4.z += xv * wv.z; h4.w += xv * wv.w;
    }
    HCvt c0, c1;
    c0.h2 = __floats2half2_rn(h4.x, h4.y);
    c1.h2 = __floats2half2_rn(h4.z, h4.w);
    *(uint2*)&g_h[(size_t)w * 128 + lane * 4] = make_uint2(c0.u, c1.u);
    float4 a = ((const float4*)s_as)[lane];
    float4 d = ((const float4*)s_ad)[lane];
    float vs = h4.x * a.x + h4.y * a.y + h4.z * a.z + h4.w * a.w;
    float vd = h4.x * d.x + h4.y * d.y + h4.z * d.z + h4.w * d.w;
#pragma unroll
    for (int off = 1; off < 8; off <<= 1) {
        vs += __shfl_xor_sync(0xffffffffu, vs, off);
        vd += __shfl_xor_sync(0xffffffffu, vd, off);
    }
    if ((lane & 7) == 0) {
        g_asrc[w * 4 + (lane >> 3)] = vs;
        g_adst[w * 4 + (lane >> 3)] = vd;
    }
}

// ---------------- GAT aggregate + head-mean + bias + proj to D=64 ------------
__global__ void __launch_bounds__(256) k_agg(const int* __restrict__ ei,
                                             const float* __restrict__ ew,
                                             const float* __restrict__ gbias,
                                             const float* __restrict__ Wp,
                                             const float* __restrict__ bp) {
    __shared__ float Wps[32 * 64];
    __shared__ float bias_s[32];
    __shared__ float bp_s[64];
    __shared__ float ce_s[4];
    __shared__ float ewm_s;
    int tid = threadIdx.x;
    for (int i = tid; i < 2048; i += 256) Wps[i] = Wp[i];
    if (tid < 32) bias_s[tid] = gbias[tid];
    if (tid < 64) bp_s[tid] = bp[tid];
    if (tid < 4)  ce_s[tid] = g_prep[tid];
    if (tid == 8) ewm_s = g_prep[4];
    __syncthreads();
    int w = blockIdx.x * 8 + (tid >> 5);
    if (w >= GN_) return;
    int lane = tid & 31;
    int g = w / N_;
    int dst = w - g * N_;
    int hd = lane >> 3;
    float ad = g_adst[((size_t)g * N_ + dst) * 4 + hd];
    float ce = ce_s[hd];
    float acc0 = 0.f, acc1 = 0.f, acc2 = 0.f, acc3 = 0.f, den = 0.f;
    int beg = g_off[dst], end = g_off[dst + 1];
    const __half* hbase = g_h + (size_t)g * N_ * 128;
    const float* abase = g_asrc + (size_t)g * N_ * 4;
    // prefetch first edge's scalars
    int s = 0; float wgt = 0.f;
    if (beg < end) {
        int e = g_csr[beg];
        if (e < E_) { s = ei[e]; wgt = ew[e]; } else { s = e - E_; wgt = ewm_s; }
    }
    for (int i = beg; i < end; i++) {
        float as = abase[s * 4 + hd];
        uint2 hraw = *(const uint2*)(hbase + (size_t)s * 128 + lane * 4);
        // prefetch next edge's scalars
        int sn = 0; float wn = 0.f;
        if (i + 1 < end) {
            int en = g_csr[i + 1];
            if (en < E_) { sn = ei[en]; wn = ew[en]; } else { sn = en - E_; wn = ewm_s; }
        }
        float lg = as + ad + ce * wgt;
        lg = (lg > 0.f) ? lg : 0.2f * lg;
        float p = __expf(lg);
        den += p;
        float2 f0 = __half22float2(*(__half2*)&hraw.x);
        float2 f1 = __half22float2(*(__half2*)&hraw.y);
        acc0 += p * f0.x; acc1 += p * f0.y; acc2 += p * f1.x; acc3 += p * f1.y;
        s = sn; wgt = wn;
    }
    float inv = 1.f / (den + 1e-16f);
    acc0 *= inv; acc1 *= inv; acc2 *= inv; acc3 *= inv;
    acc0 += __shfl_xor_sync(0xffffffffu, acc0, 8);  acc0 += __shfl_xor_sync(0xffffffffu, acc0, 16);
    acc1 += __shfl_xor_sync(0xffffffffu, acc1, 8);  acc1 += __shfl_xor_sync(0xffffffffu, acc1, 16);
    acc2 += __shfl_xor_sync(0xffffffffu, acc2, 8);  acc2 += __shfl_xor_sync(0xffffffffu, acc2, 16);
    acc3 += __shfl_xor_sync(0xffffffffu, acc3, 8);  acc3 += __shfl_xor_sync(0xffffffffu, acc3, 16);
    int cb = (lane & 7) * 4;
    float og0 = acc0 * 0.25f + bias_s[cb + 0];
    float og1 = acc1 * 0.25f + bias_s[cb + 1];
    float og2 = acc2 * 0.25f + bias_s[cb + 2];
    float og3 = acc3 * 0.25f + bias_s[cb + 3];
    int d0 = lane * 2;
    float y0 = bp_s[d0], y1 = bp_s[d0 + 1];
#pragma unroll
    for (int sl = 0; sl < 8; sl++) {
        float v0 = __shfl_sync(0xffffffffu, og0, sl);
        float v1 = __shfl_sync(0xffffffffu, og1, sl);
        float v2 = __shfl_sync(0xffffffffu, og2, sl);
        float v3 = __shfl_sync(0xffffffffu, og3, sl);
        int c = sl * 4;
        float2 w0 = *(const float2*)&Wps[(c + 0) * 64 + d0];
        float2 w1 = *(const float2*)&Wps[(c + 1) * 64 + d0];
        float2 w2 = *(const float2*)&Wps[(c + 2) * 64 + d0];
        float2 w3 = *(const float2*)&Wps[(c + 3) * 64 + d0];
        y0 += v0 * w0.x + v1 * w1.x + v2 * w2.x + v3 * w3.x;
        y1 += v0 * w0.y + v1 * w1.y + v2 * w2.y + v3 * w3.y;
    }
    int b = g >> 4;
    int t = g & 15;
    float2* out = (float2*)&g_y[(((size_t)(b * N_ + dst)) * T_ + t) * D_];
    out[lane] = make_float2(y0, y1);
}

// ---------------- K,V GEMM: g_kv[rn][0:128] = g_y[rn] @ Wqkv[:,64:192] -------
__global__ void __launch_bounds__(256) k_qkv(const float* __restrict__ Wqkv,
                                             const float* __restrict__ bqkv) {
    __shared__ float Ys[64 * 64];     // [r][k]
    __shared__ float Ws[64 * 128];    // [k][c]
    int tid = threadIdx.x;
    int rb = blockIdx.x * 64;
    for (int i = tid; i < 4096; i += 256) {
        Ys[i] = g_y[((size_t)rb << 6) + i];
    }
    for (int i = tid; i < 8192; i += 256) {
        int k = i >> 7, c = i & 127;
        Ws[i] = Wqkv[k * 192 + 64 + c];
    }
    __syncthreads();
    int tx = tid & 15, ty = tid >> 4;
    int c0 = tx * 8, r0 = ty * 4;
    float acc[4][8];
#pragma unroll
    for (int i = 0; i < 4; i++)
#pragma unroll
        for (int j = 0; j < 8; j++) acc[i][j] = 0.f;
#pragma unroll 8
    for (int k = 0; k < 64; k++) {
        float a0 = Ys[(r0 + 0) * 64 + k];
        float a1 = Ys[(r0 + 1) * 64 + k];
        float a2 = Ys[(r0 + 2) * 64 + k];
        float a3 = Ys[(r0 + 3) * 64 + k];
        float4 b0 = *(const float4*)&Ws[k * 128 + c0];
        float4 b1 = *(const float4*)&Ws[k * 128 + c0 + 4];
        acc[0][0] += a0 * b0.x; acc[0][1] += a0 * b0.y; acc[0][2] += a0 * b0.z; acc[0][3] += a0 * b0.w;
        acc[0][4] += a0 * b1.x; acc[0][5] += a0 * b1.y; acc[0][6] += a0 * b1.z; acc[0][7] += a0 * b1.w;
        acc[1][0] += a1 * b0.x; acc[1][1] += a1 * b0.y; acc[1][2] += a1 * b0.z; acc[1][3] += a1 * b0.w;
        acc[1][4] += a1 * b1.x; acc[1][5] += a1 * b1.y; acc[1][6] += a1 * b1.z; acc[1][7] += a1 * b1.w;
        acc[2][0] += a2 * b0.x; acc[2][1] += a2 * b0.y; acc[2][2] += a2 * b0.z; acc[2][3] += a2 * b0.w;
        acc[2][4] += a2 * b1.x; acc[2][5] += a2 * b1.y; acc[2][6] += a2 * b1.z; acc[2][7] += a2 * b1.w;
        acc[3][0] += a3 * b0.x; acc[3][1] += a3 * b0.y; acc[3][2] += a3 * b0.z; acc[3][3] += a3 * b0.w;
        acc[3][4] += a3 * b1.x; acc[3][5] += a3 * b1.y; acc[3][6] += a3 * b1.z; acc[3][7] += a3 * b1.w;
    }
    float4 bb0 = *(const float4*)&bqkv[64 + c0];
    float4 bb1 = *(const float4*)&bqkv[64 + c0 + 4];
#pragma unroll
    for (int i = 0; i < 4; i++) {
        size_t rn = rb + r0 + i;
        *(float4*)&g_kv[rn * 128 + c0] =
            make_float4(acc[i][0] + bb0.x, acc[i][1] + bb0.y, acc[i][2] + bb0.z, acc[i][3] + bb0.w);
        *(float4*)&g_kv[rn * 128 + c0 + 4] =
            make_float4(acc[i][4] + bb1.x, acc[i][5] + bb1.y, acc[i][6] + bb1.z, acc[i][7] + bb1.w);
    }
}

// ---------------- Q (in-kernel) + attention + Wo + residual + LN1 ------------
__global__ void __launch_bounds__(256) k_attn2(const float* __restrict__ Wqkv,
                                               const float* __restrict__ bqkv,
                                               const float* __restrict__ Wo,
                                               const float* __restrict__ bo,
                                               const float* __restrict__ ln1g,
                                               const float* __restrict__ ln1b) {
    __shared__ float Wos[64 * 64];
    __shared__ float Wqs[64 * 64];
    __shared__ float bos[64], g1s[64], b1s[64], bqs[64];
    __shared__ float ys[8][64];
    __shared__ float sq[8][64];
    int tid = threadIdx.x;
    for (int i = tid; i < 4096; i += 256) {
        Wos[i] = Wo[i];
        int k = i >> 6, c = i & 63;
        Wqs[i] = Wqkv[k * 192 + c];
    }
    if (tid < 64) { bos[tid] = bo[tid]; g1s[tid] = ln1g[tid]; b1s[tid] = ln1b[tid]; bqs[tid] = bqkv[tid]; }
    __syncthreads();
    int wid = tid >> 5, lane = tid & 31;
    int r = blockIdx.x * 8 + wid;
    int dcol = lane * 2;
    // load y at t=15 for this row
    float2 yv = *(const float2*)&g_y[((size_t)(r * 16 + 15)) * 64 + dcol];
    ys[wid][dcol] = yv.x; ys[wid][dcol + 1] = yv.y;
    __syncwarp();
    // Q = y15 @ Wq + bq
    float q0 = bqs[dcol], q1 = bqs[dcol + 1];
#pragma unroll 16
    for (int j = 0; j < 64; j++) {
        float yj = ys[wid][j];
        float2 wv = *(const float2*)&Wqs[j * 64 + dcol];
        q0 += yj * wv.x; q1 += yj * wv.y;
    }
    sq[wid][dcol] = q0; sq[wid][dcol + 1] = q1;
    __syncwarp();
    int t = lane & 15, grp = lane >> 4;
    const float* kbase = &g_kv[((size_t)(r * 16 + t)) * 128 + grp * 32];
    const float* qq = &sq[wid][grp * 32];
    float s0 = 0.f, s1 = 0.f;
#pragma unroll
    for (int j4 = 0; j4 < 4; j4++) {
        float4 k0 = *(const float4*)&kbase[j4 * 4];
        float4 k1 = *(const float4*)&kbase[16 + j4 * 4];
        s0 += qq[j4 * 4 + 0] * k0.x + qq[j4 * 4 + 1] * k0.y + qq[j4 * 4 + 2] * k0.z + qq[j4 * 4 + 3] * k0.w;
        s1 += qq[16 + j4 * 4 + 0] * k1.x + qq[16 + j4 * 4 + 1] * k1.y + qq[16 + j4 * 4 + 2] * k1.z + qq[16 + j4 * 4 + 3] * k1.w;
    }
    s0 *= 0.25f; s1 *= 0.25f;
    float m0 = s0, m1 = s1;
#pragma unroll
    for (int off = 1; off < 16; off <<= 1) {
        m0 = fmaxf(m0, __shfl_xor_sync(0xffffffffu, m0, off));
        m1 = fmaxf(m1, __shfl_xor_sync(0xffffffffu, m1, off));
    }
    float p0 = __expf(s0 - m0), p1 = __expf(s1 - m1);
    float dn0 = p0, dn1 = p1;
#pragma unroll
    for (int off = 1; off < 16; off <<= 1) {
        dn0 += __shfl_xor_sync(0xffffffffu, dn0, off);
        dn1 += __shfl_xor_sync(0xffffffffu, dn1, off);
    }
    p0 /= dn0; p1 /= dn1;
    int hd = lane >> 3;
    int srcbase = (hd >> 1) * 16;
    int sel = hd & 1;
    float c0 = 0.f, c1 = 0.f;
#pragma unroll
    for (int tt = 0; tt < 16; tt++) {
        float pa = __shfl_sync(0xffffffffu, p0, srcbase + tt);
        float pb = __shfl_sync(0xffffffffu, p1, srcbase + tt);
        float pv = sel ? pb : pa;
        float2 v2 = *(const float2*)&g_kv[((size_t)(r * 16 + tt)) * 128 + 64 + dcol];
        c0 += pv * v2.x; c1 += pv * v2.y;
    }
    float o0 = bos[dcol], o1 = bos[dcol + 1];
#pragma unroll
    for (int jj = 0; jj < 32; jj++) {
        float ca = __shfl_sync(0xffffffffu, c0, jj);
        float cb = __shfl_sync(0xffffffffu, c1, jj);
        float2 wA = *(const float2*)&Wos[(2 * jj) * 64 + dcol];
        float2 wB = *(const float2*)&Wos[(2 * jj + 1) * 64 + dcol];
        o0 += ca * wA.x + cb * wB.x;
        o1 += ca * wA.y + cb * wB.y;
    }
    float r0v = ys[wid][dcol] + o0, r1v = ys[wid][dcol + 1] + o1;
    float su = r0v + r1v, s2 = r0v * r0v + r1v * r1v;
#pragma unroll
    for (int off = 1; off < 32; off <<= 1) {
        su += __shfl_xor_sync(0xffffffffu, su, off);
        s2 += __shfl_xor_sync(0xffffffffu, s2, off);
    }
    float mu = su * (1.f / 64.f);
    float var = s2 * (1.f / 64.f) - mu * mu;
    float inv = rsqrtf(var + 1e-5f);
    float2 z;
    z.x = (r0v - mu) * inv * g1s[dcol] + b1s[dcol];
    z.y = (r1v - mu) * inv * g1s[dcol + 1] + b1s[dcol + 1];
    *(float2*)&g_z[(size_t)r * 64 + dcol] = z;
}

// ---------------- FFN layer 1: relu(Z @ W1 + b1) -> fp16 ---------------------
__global__ void __launch_bounds__(256) k_ffn1(const float* __restrict__ W1,
                                              const float* __restrict__ b1) {
    __shared__ float Zs[64 * 64];    // [r][k]
    __shared__ float W1s[64 * 64];   // [k][c]
    int tid = threadIdx.x;
    int rb = blockIdx.x * 64;
    int cb = blockIdx.y * 64;
    for (int i = tid; i < 4096; i += 256) {
        int gr = rb + (i >> 6);
        Zs[i] = (gr < BN_) ? g_z[(size_t)gr * 64 + (i & 63)] : 0.f;
    }
    for (int i = tid; i < 4096; i += 256) {
        int k = i >> 6, c = i & 63;
        W1s[i] = W1[(size_t)k * FF_ + cb + c];
    }
    __syncthreads();
    int tx = tid & 15, ty = tid >> 4;
    int r0 = ty * 4, c0 = tx * 4;
    float acc[4][4];
#pragma unroll
    for (int i = 0; i < 4; i++)
#pragma unroll
        for (int j = 0; j < 4; j++) acc[i][j] = 0.f;
#pragma unroll 16
    for (int kk = 0; kk < 64; kk++) {
        float a0 = Zs[(r0 + 0) * 64 + kk];
        float a1 = Zs[(r0 + 1) * 64 + kk];
        float a2 = Zs[(r0 + 2) * 64 + kk];
        float a3 = Zs[(r0 + 3) * 64 + kk];
        float4 bv = *(const float4*)&W1s[kk * 64 + c0];
        acc[0][0] += a0 * bv.x; acc[0][1] += a0 * bv.y; acc[0][2] += a0 * bv.z; acc[0][3] += a0 * bv.w;
        acc[1][0] += a1 * bv.x; acc[1][1] += a1 * bv.y; acc[1][2] += a1 * bv.z; acc[1][3] += a1 * bv.w;
        acc[2][0] += a2 * bv.x; acc[2][1] += a2 * bv.y; acc[2][2] += a2 * bv.z; acc[2][3] += a2 * bv.w;
        acc[3][0] += a3 * bv.x; acc[3][1] += a3 * bv.y; acc[3][2] += a3 * bv.z; acc[3][3] += a3 * bv.w;
    }
    int col = cb + c0;
    float4 bb = *(const float4*)&b1[col];
#pragma unroll
    for (int i = 0; i < 4; i++) {
        int gr = rb + r0 + i;
        if (gr < BN_) {
            HCvt u0, u1;
            u0.h2 = __floats2half2_rn(fmaxf(acc[i][0] + bb.x, 0.f), fmaxf(acc[i][1] + bb.y, 0.f));
            u1.h2 = __floats2half2_rn(fmaxf(acc[i][2] + bb.z, 0.f), fmaxf(acc[i][3] + bb.w, 0.f));
            *(uint2*)&g_ff[(size_t)gr * FF_ + col] = make_uint2(u0.u, u1.u);
        }
    }
}

// ---------------- FFN layer 2 split-K + fused last-block LN2 -> out ----------
__global__ void __launch_bounds__(256) k_ffn2s(const float* __restrict__ W2,
                                               const float* __restrict__ b2,
                                               const float* __restrict__ ln2g,
                                               const float* __restrict__ ln2b,
                                               float* __restrict__ out) {
    __shared__ float Fs[32 * 64];    // [r][k]
    __shared__ float W2s[64 * 64];   // [k][d]
    __shared__ bool last_s;
    int tid = threadIdx.x;
    int rb = blockIdx.x * 32;
    int kc0 = blockIdx.y * 512;
    int tx = tid & 15, ty = tid >> 4;
    int r0 = ty * 2, c0 = tx * 4;
    float acc[2][4];
#pragma unroll
    for (int i = 0; i < 2; i++)
#pragma unroll
        for (int j = 0; j < 4; j++) acc[i][j] = 0.f;
    for (int kc = kc0; kc < kc0 + 512; kc += 64) {
        for (int i = tid; i < 512; i += 256) {
            int rr = i >> 4;
            int k4 = (i & 15) * 4;
            uint2 u = *(const uint2*)&g_ff[(size_t)(rb + rr) * FF_ + kc + k4];
            float2 f0 = __half22float2(*(__half2*)&u.x);
            float2 f1 = __half22float2(*(__half2*)&u.y);
            Fs[rr * 64 + k4 + 0] = f0.x; Fs[rr * 64 + k4 + 1] = f0.y;
            Fs[rr * 64 + k4 + 2] = f1.x; Fs[rr * 64 + k4 + 3] = f1.y;
        }
        for (int i = tid; i < 4096; i += 256) {
            int k = i >> 6, d = i & 63;
            W2s[i] = W2[(size_t)(kc + k) * 64 + d];
        }
        __syncthreads();
#pragma unroll 16
        for (int kk = 0; kk < 64; kk++) {
            float a0 = Fs[(r0 + 0) * 64 + kk];
            float a1 = Fs[(r0 + 1) * 64 + kk];
            float4 bv = *(const float4*)&W2s[kk * 64 + c0];
            acc[0][0] += a0 * bv.x; acc[0][1] += a0 * bv.y; acc[0][2] += a0 * bv.z; acc[0][3] += a0 * bv.w;
            acc[1][0] += a1 * bv.x; acc[1][1] += a1 * bv.y; acc[1][2] += a1 * bv.z; acc[1][3] += a1 * bv.w;
        }
        __syncthreads();
    }
    float* plane = g_acc[blockIdx.y];
#pragma unroll
    for (int i = 0; i < 2; i++) {
        int gr = rb + r0 + i;
        *(float4*)&plane[(size_t)gr * 64 + c0] =
            make_float4(acc[i][0], acc[i][1], acc[i][2], acc[i][3]);
    }
    // last-block-done epilogue: sum planes + b2 + residual + LN2
    __threadfence();
    __syncthreads();
    if (tid == 0) {
        int old = atomicAdd(&g_cnt[blockIdx.x], 1);
        last_s = (old == 3);
        if (last_s) g_cnt[blockIdx.x] = 0;   // reset for next launch
    }
    __syncthreads();
    if (!last_s) return;
    int wid = tid >> 5, lane = tid & 31;
    int d = lane * 2;
    for (int rr = wid; rr < 32; rr += 8) {
        int r = rb + rr;
        float2 zr = *(const float2*)&g_z[(size_t)r * 64 + d];
        float2 bb = *(const float2*)&b2[d];
        float v0 = zr.x + bb.x, v1 = zr.y + bb.y;
#pragma unroll
        for (int s = 0; s < 4; s++) {
            float2 a = *(const float2*)&g_acc[s][(size_t)r * 64 + d];
            v0 += a.x; v1 += a.y;
        }
        float su = v0 + v1, s2 = v0 * v0 + v1 * v1;
#pragma unroll
        for (int off = 1; off < 32; off <<= 1) {
            su += __shfl_xor_sync(0xffffffffu, su, off);
            s2 += __shfl_xor_sync(0xffffffffu, s2, off);
        }
        float mu = su * (1.f / 64.f);
        float var = s2 * (1.f / 64.f) - mu * mu;
        float inv = rsqrtf(var + 1e-5f);
        float2 gg = *(const float2*)&ln2g[d];
        float2 be = *(const float2*)&ln2b[d];
        float2 o;
        o.x = (v0 - mu) * inv * gg.x + be.x;
        o.y = (v1 - mu) * inv * gg.y + be.y;
        *(float2*)&out[(size_t)r * 64 + d] = o;
    }
}

// ---------------- launch ----------------------------------------------------
extern "C" void kernel_launch(void* const* d_in, const int* in_sizes, int n_in,
                              void* d_out, int out_size) {
    const float* x_seq    = (const float*)d_in[0];
    const int*   eidx     = (const int*)d_in[1];
    const float* eweight  = (const float*)d_in[2];
    const float* W_gat    = (const float*)d_in[3];
    const float* att_src  = (const float*)d_in[4];
    const float* att_dst  = (const float*)d_in[5];
    const float* W_edge   = (const float*)d_in[6];
    const float* att_edge = (const float*)d_in[7];
    const float* gat_bias = (const float*)d_in[8];
    const float* W_proj   = (const float*)d_in[9];
    const float* b_proj   = (const float*)d_in[10];
    const float* Wqkv     = (const float*)d_in[11];
    const float* bqkv     = (const float*)d_in[12];
    const float* Wo       = (const float*)d_in[13];
    const float* bo       = (const float*)d_in[14];
    const float* ln1_g    = (const float*)d_in[15];
    const float* ln1_b    = (const float*)d_in[16];
    const float* W1       = (const float*)d_in[17];
    const float* b1       = (const float*)d_in[18];
    const float* W2       = (const float*)d_in[19];
    const float* b2       = (const float*)d_in[20];
    const float* ln2_g    = (const float*)d_in[21];
    const float* ln2_b    = (const float*)d_in[22];
    float* out = (float*)d_out;

    k_h<<<GN_ / 8, 256>>>(x_seq, W_gat, att_src, att_dst);
    k_count<<<(ET_ + 255) / 256, 256>>>(eidx, eweight);
    k_scan<<<1, 1024>>>(W_edge, att_edge);
    k_scatter<<<(ET_ + 255) / 256, 256>>>(eidx);
    k_agg<<<GN_ / 8, 256>>>(eidx, eweight, gat_bias, W_proj, b_proj);
    k_qkv<<<GN_ / 64, 256>>>(Wqkv, bqkv);
    k_attn2<<<BN_ / 8, 256>>>(Wqkv, bqkv, Wo, bo, ln1_g, ln1_b);
    {
        dim3 grid((BN_ + 63) / 64, FF_ / 64);
        k_ffn1<<<grid, 256>>>(W1, b1);
    }
    {
        dim3 grid(BN_ / 32, 4);
        k_ffn2s<<<grid, 256>>>(W2, b2, ln2_g, ln2_b, out);
    }
}

// round 6
// speedup vs baseline: 1.4228x; 1.4228x over previous
#include <cuda_runtime.h>
#include <cuda_fp16.h>
#include <cstdint>

#define B_ 2
#define T_ 16
#define N_ 2000
#define F_ 16
#define E_ 32000
#define H_ 4
#define C_ 32
#define D_ 64
#define FF_ 2048
#define G_ (B_*T_)      /* 32  */
#define ET_ (E_+N_)     /* 34000 */
#define BN_ (B_*N_)     /* 4000 */
#define GN_ (G_*N_)     /* 64000 */

// ---------------- scratch (static device globals; no allocation) -------------
__device__ __half g_h[(size_t)GN_ * 128];  // h: [G,N,H*C] fp16
__device__ float g_asrc[GN_ * 4];
__device__ float g_adst[GN_ * 4];
__device__ float g_prep[8];               // c_edge[0..3], ew_mean at [4]
__device__ unsigned long long g_ewsum;    // fixed-point sum of edge weights
__device__ int   g_deg[2048];
__device__ int   g_off[N_ + 1];
__device__ int   g_cur[N_];
__device__ int   g_csr[ET_];
__device__ float g_y[GN_ * D_];           // [bn][t][d]  (row rn = bn*16+t)
__device__ float g_kv[(size_t)GN_ * 128]; // [rn][0:64)=K, [64:128)=V
__device__ float g_z[BN_ * D_];           // post-LN1
__device__ __half g_wkvh[64 * 128];       // fp16 Wqkv[:,64:192]
__device__ __half g_w1h[64 * FF_];        // fp16 W1
__device__ __half g_w2h[FF_ * 64];        // fp16 W2

union HCvt { __half2 h2; uint32_t u; };

// ---------------- mma helpers ------------------------------------------------
__device__ __forceinline__ uint32_t su32(const void* p) {
    uint32_t a;
    asm("{ .reg .u64 t; cvta.to.shared.u64 t, %1; cvt.u32.u64 %0, t; }" : "=r"(a) : "l"(p));
    return a;
}
__device__ __forceinline__ void ldsm_x4(uint32_t& r0, uint32_t& r1, uint32_t& r2, uint32_t& r3, uint32_t a) {
    asm volatile("ldmatrix.sync.aligned.m8n8.x4.shared.b16 {%0,%1,%2,%3}, [%4];"
                 : "=r"(r0), "=r"(r1), "=r"(r2), "=r"(r3) : "r"(a));
}
__device__ __forceinline__ void ldsm_x4t(uint32_t& r0, uint32_t& r1, uint32_t& r2, uint32_t& r3, uint32_t a) {
    asm volatile("ldmatrix.sync.aligned.m8n8.x4.trans.shared.b16 {%0,%1,%2,%3}, [%4];"
                 : "=r"(r0), "=r"(r1), "=r"(r2), "=r"(r3) : "r"(a));
}
__device__ __forceinline__ void mma16816(float* d, uint32_t a0, uint32_t a1, uint32_t a2, uint32_t a3,
                                         uint32_t b0, uint32_t b1) {
    asm volatile("mma.sync.aligned.m16n8k16.row.col.f32.f16.f16.f32 "
                 "{%0,%1,%2,%3}, {%4,%5,%6,%7}, {%8,%9}, {%0,%1,%2,%3};"
                 : "+f"(d[0]), "+f"(d[1]), "+f"(d[2]), "+f"(d[3])
                 : "r"(a0), "r"(a1), "r"(a2), "r"(a3), "r"(b0), "r"(b1));
}

// ---------------- weight conversion to fp16 ----------------------------------
__global__ void k_cvt(const float* __restrict__ Wqkv, const float* __restrict__ W1,
                      const float* __restrict__ W2) {
    int i = blockIdx.x * 256 + threadIdx.x;
    if (i < 64 * 128) {
        int k = i >> 7, c = i & 127;
        g_wkvh[i] = __float2half(Wqkv[k * 192 + 64 + c]);
    }
    if (i < 64 * FF_) {
        g_w1h[i] = __float2half(W1[i]);
        g_w2h[i] = __float2half(W2[i]);
    }
}

// ---------------- count (fused with edge-weight sum) -------------------------
__global__ void k_count(const int* __restrict__ ei, const float* __restrict__ ew) {
    int e = blockIdx.x * blockDim.x + threadIdx.x;
    if (e >= ET_) return;
    int d;
    if (e < E_) {
        d = ei[E_ + e];
        atomicAdd(&g_ewsum, (unsigned long long)((double)ew[e] * 4294967296.0));
    } else {
        d = e - E_;
    }
    atomicAdd(&g_deg[d], 1);
}

// ---------------- scan (+ edge consts, self-zero deg & ewsum) ----------------
__global__ void k_scan(const float* __restrict__ W_edge,
                       const float* __restrict__ att_edge) {
    __shared__ int ws[32];
    int t = threadIdx.x;
    int i0 = 2 * t, i1 = 2 * t + 1;
    int a = (i0 < N_) ? g_deg[i0] : 0;
    int b = (i1 < N_) ? g_deg[i1] : 0;
    int v = a + b;
    int lane = t & 31, wid = t >> 5;
#pragma unroll
    for (int off = 1; off < 32; off <<= 1) {
        int n = __shfl_up_sync(0xffffffffu, v, off);
        if (lane >= off) v += n;
    }
    if (lane == 31) ws[wid] = v;
    __syncthreads();
    if (t < 32) {
        int u = ws[t];
#pragma unroll
        for (int off = 1; off < 32; off <<= 1) {
            int n = __shfl_up_sync(0xffffffffu, u, off);
            if (t >= off) u += n;
        }
        ws[t] = u;
    }
    __syncthreads();
    int base = (wid > 0) ? ws[wid - 1] : 0;
    int incl = v + base;
    int ex0 = incl - a - b;
    if (i0 <= N_) { g_off[i0] = ex0; if (i0 < N_) g_cur[i0] = ex0; }
    if (i1 <= N_) { g_off[i1] = ex0 + a; if (i1 < N_) g_cur[i1] = ex0 + a; }
    g_deg[i0] = 0; g_deg[i1] = 0;
    if (t < 4) {
        float c = 0.f;
        for (int j = 0; j < 32; j++) c += W_edge[t * 32 + j] * att_edge[t * 32 + j];
        g_prep[t] = c;
    }
    if (t == 4) {
        g_prep[4] = (float)((double)g_ewsum / 4294967296.0 / (double)E_);
        g_ewsum = 0ull;
    }
}

__global__ void k_scatter(const int* __restrict__ ei) {
    int e = blockIdx.x * blockDim.x + threadIdx.x;
    if (e >= ET_) return;
    int d = (e < E_) ? ei[E_ + e] : (e - E_);
    int pos = atomicAdd(&g_cur[d], 1);
    g_csr[pos] = e;
}

// ---------------- h = x @ W_gat (fp16 out); attn scalar terms (fp32) ---------
__global__ void __launch_bounds__(256) k_h(const float* __restrict__ x,
                                           const float* __restrict__ Wg,
                                           const float* __restrict__ as_w,
                                           const float* __restrict__ ad_w) {
    __shared__ float Wgs[16 * 128];
    __shared__ float s_as[128], s_ad[128];
    int tid = threadIdx.x;
    for (int i = tid; i < 2048; i += 256) Wgs[i] = Wg[i];
    for (int i = tid; i < 128; i += 256) { s_as[i] = as_w[i]; s_ad[i] = ad_w[i]; }
    __syncthreads();
    int w = blockIdx.x * 8 + (tid >> 5);
    if (w >= GN_) return;
    int lane = tid & 31;
    const float* xr = x + (size_t)w * 16;
    float xf = (lane < 16) ? xr[lane] : 0.f;
    float4 h4 = make_float4(0.f, 0.f, 0.f, 0.f);
    const float4* Wg4 = (const float4*)Wgs;
#pragma unroll
    for (int f = 0; f < 16; f++) {
        float xv = __shfl_sync(0xffffffffu, xf, f);
        float4 wv = Wg4[f * 32 + lane];
        h4.x += xv * wv.x; h4.y += xv * wv.y; h4.z += xv * wv.z; h4.w += xv * wv.w;
    }
    HCvt c0, c1;
    c0.h2 = __floats2half2_rn(h4.x, h4.y);
    c1.h2 = __floats2half2_rn(h4.z, h4.w);
    *(uint2*)&g_h[(size_t)w * 128 + lane * 4] = make_uint2(c0.u, c1.u);
    float4 a = ((const float4*)s_as)[lane];
    float4 d = ((const float4*)s_ad)[lane];
    float vs = h4.x * a.x + h4.y * a.y + h4.z * a.z + h4.w * a.w;
    float vd = h4.x * d.x + h4.y * d.y + h4.z * d.z + h4.w * d.w;
#pragma unroll
    for (int off = 1; off < 8; off <<= 1) {
        vs += __shfl_xor_sync(0xffffffffu, vs, off);
        vd += __shfl_xor_sync(0xffffffffu, vd, off);
    }
    if ((lane & 7) == 0) {
        g_asrc[w * 4 + (lane >> 3)] = vs;
        g_adst[w * 4 + (lane >> 3)] = vd;
    }
}

// ---------------- GAT aggregate + head-mean + bias + proj to D=64 ------------
__global__ void __launch_bounds__(256) k_agg(const int* __restrict__ ei,
                                             const float* __restrict__ ew,
                                             const float* __restrict__ gbias,
                                             const float* __restrict__ Wp,
                                             const float* __restrict__ bp) {
    __shared__ float Wps[32 * 64];
    __shared__ float bias_s[32];
    __shared__ float bp_s[64];
    __shared__ float ce_s[4];
    __shared__ float ewm_s;
    int tid = threadIdx.x;
    for (int i = tid; i < 2048; i += 256) Wps[i] = Wp[i];
    if (tid < 32) bias_s[tid] = gbias[tid];
    if (tid < 64) bp_s[tid] = bp[tid];
    if (tid < 4)  ce_s[tid] = g_prep[tid];
    if (tid == 8) ewm_s = g_prep[4];
    __syncthreads();
    int w = blockIdx.x * 8 + (tid >> 5);
    if (w >= GN_) return;
    int lane = tid & 31;
    int g = w / N_;
    int dst = w - g * N_;
    int hd = lane >> 3;
    float ad = g_adst[((size_t)g * N_ + dst) * 4 + hd];
    float ce = ce_s[hd];
    float acc0 = 0.f, acc1 = 0.f, acc2 = 0.f, acc3 = 0.f, den = 0.f;
    int beg = g_off[dst], end = g_off[dst + 1];
    const __half* hbase = g_h + (size_t)g * N_ * 128;
    const float* abase = g_asrc + (size_t)g * N_ * 4;
    int s = 0; float wgt = 0.f;
    if (beg < end) {
        int e = g_csr[beg];
        if (e < E_) { s = ei[e]; wgt = ew[e]; } else { s = e - E_; wgt = ewm_s; }
    }
    for (int i = beg; i < end; i++) {
        float as = abase[s * 4 + hd];
        uint2 hraw = *(const uint2*)(hbase + (size_t)s * 128 + lane * 4);
        int sn = 0; float wn = 0.f;
        if (i + 1 < end) {
            int en = g_csr[i + 1];
            if (en < E_) { sn = ei[en]; wn = ew[en]; } else { sn = en - E_; wn = ewm_s; }
        }
        float lg = as + ad + ce * wgt;
        lg = (lg > 0.f) ? lg : 0.2f * lg;
        float p = __expf(lg);
        den += p;
        float2 f0 = __half22float2(*(__half2*)&hraw.x);
        float2 f1 = __half22float2(*(__half2*)&hraw.y);
        acc0 += p * f0.x; acc1 += p * f0.y; acc2 += p * f1.x; acc3 += p * f1.y;
        s = sn; wgt = wn;
    }
    float inv = 1.f / (den + 1e-16f);
    acc0 *= inv; acc1 *= inv; acc2 *= inv; acc3 *= inv;
    acc0 += __shfl_xor_sync(0xffffffffu, acc0, 8);  acc0 += __shfl_xor_sync(0xffffffffu, acc0, 16);
    acc1 += __shfl_xor_sync(0xffffffffu, acc1, 8);  acc1 += __shfl_xor_sync(0xffffffffu, acc1, 16);
    acc2 += __shfl_xor_sync(0xffffffffu, acc2, 8);  acc2 += __shfl_xor_sync(0xffffffffu, acc2, 16);
    acc3 += __shfl_xor_sync(0xffffffffu, acc3, 8);  acc3 += __shfl_xor_sync(0xffffffffu, acc3, 16);
    int cb = (lane & 7) * 4;
    float og0 = acc0 * 0.25f + bias_s[cb + 0];
    float og1 = acc1 * 0.25f + bias_s[cb + 1];
    float og2 = acc2 * 0.25f + bias_s[cb + 2];
    float og3 = acc3 * 0.25f + bias_s[cb + 3];
    int d0 = lane * 2;
    float y0 = bp_s[d0], y1 = bp_s[d0 + 1];
#pragma unroll
    for (int sl = 0; sl < 8; sl++) {
        float v0 = __shfl_sync(0xffffffffu, og0, sl);
        float v1 = __shfl_sync(0xffffffffu, og1, sl);
        float v2 = __shfl_sync(0xffffffffu, og2, sl);
        float v3 = __shfl_sync(0xffffffffu, og3, sl);
        int c = sl * 4;
        float2 w0 = *(const float2*)&Wps[(c + 0) * 64 + d0];
        float2 w1 = *(const float2*)&Wps[(c + 1) * 64 + d0];
        float2 w2 = *(const float2*)&Wps[(c + 2) * 64 + d0];
        float2 w3 = *(const float2*)&Wps[(c + 3) * 64 + d0];
        y0 += v0 * w0.x + v1 * w1.x + v2 * w2.x + v3 * w3.x;
        y1 += v0 * w0.y + v1 * w1.y + v2 * w2.y + v3 * w3.y;
    }
    int b = g >> 4;
    int t = g & 15;
    float2* out = (float2*)&g_y[(((size_t)(b * N_ + dst)) * T_ + t) * D_];
    out[lane] = make_float2(y0, y1);
}

// ---------------- K,V GEMM via HMMA: g_kv = y @ Wkv + b ----------------------
#define SA_ 72
#define SB_ 136
__global__ void __launch_bounds__(256) k_qkv_mma(const float* __restrict__ bqkv) {
    __shared__ __half Ah[64 * SA_];
    __shared__ __half Bs[64 * SB_];
    __shared__ float bqs[128];
    int tid = threadIdx.x, wid = tid >> 5, lane = tid & 31;
    int rb = blockIdx.x * 64;
    for (int i = tid; i < 64 * 16; i += 256) {
        int r = i >> 4, s4 = i & 15;
        float4 v = *(const float4*)&g_y[((size_t)(rb + r)) * 64 + s4 * 4];
        HCvt h0, h1;
        h0.h2 = __floats2half2_rn(v.x, v.y);
        h1.h2 = __floats2half2_rn(v.z, v.w);
        *(uint2*)&Ah[r * SA_ + s4 * 4] = make_uint2(h0.u, h1.u);
    }
    for (int i = tid; i < 64 * 16; i += 256) {
        int r = i >> 4, s = i & 15;
        *(uint4*)&Bs[r * SB_ + s * 8] = *(const uint4*)&g_wkvh[r * 128 + s * 8];
    }
    if (tid < 128) bqs[tid] = bqkv[64 + tid];
    __syncthreads();
    int mi = wid >> 1;            // 0..3 (m16 tile)
    int nb = (wid & 1) * 64;      // n base
    float o[4][2][4];
#pragma unroll
    for (int j = 0; j < 4; j++)
#pragma unroll
        for (int n8 = 0; n8 < 2; n8++)
#pragma unroll
            for (int q = 0; q < 4; q++) o[j][n8][q] = 0.f;
    uint32_t abase = su32(Ah) + ((mi * 16 + (lane & 15)) * SA_ + (lane >> 4) * 8) * 2;
    uint32_t bbase = su32(Bs) + (((lane & 15)) * SB_ + nb + (lane >> 4) * 8) * 2;
#pragma unroll
    for (int k = 0; k < 4; k++) {
        uint32_t a0, a1, a2, a3;
        ldsm_x4(a0, a1, a2, a3, abase + k * 32);
#pragma unroll
        for (int j = 0; j < 4; j++) {
            uint32_t b0, b1, b2, b3;
            ldsm_x4t(b0, b1, b2, b3, bbase + (k * 16 * SB_ + j * 16) * 2);
            mma16816(o[j][0], a0, a1, a2, a3, b0, b1);
            mma16816(o[j][1], a0, a1, a2, a3, b2, b3);
        }
    }
    int r0 = lane >> 2, c0 = (lane & 3) * 2;
#pragma unroll
    for (int j = 0; j < 4; j++)
#pragma unroll
        for (int n8 = 0; n8 < 2; n8++)
#pragma unroll
            for (int hm = 0; hm < 2; hm++) {
                int row = rb + mi * 16 + r0 + hm * 8;
                int col = nb + j * 16 + n8 * 8 + c0;
                float2 v = make_float2(o[j][n8][hm * 2 + 0] + bqs[col],
                                       o[j][n8][hm * 2 + 1] + bqs[col + 1]);
                *(float2*)&g_kv[(size_t)row * 128 + col] = v;
            }
}

// ---------------- Q (in-kernel) + attention + Wo + residual + LN1 ------------
__global__ void __launch_bounds__(256) k_attn2(const float* __restrict__ Wqkv,
                                               const float* __restrict__ bqkv,
                                               const float* __restrict__ Wo,
                                               const float* __restrict__ bo,
                                               const float* __restrict__ ln1g,
                                               const float* __restrict__ ln1b) {
    __shared__ float Wos[64 * 64];
    __shared__ float Wqs[64 * 64];
    __shared__ float bos[64], g1s[64], b1s[64], bqs[64];
    __shared__ float ys[8][64];
    __shared__ float sq[8][64];
    int tid = threadIdx.x;
    for (int i = tid; i < 4096; i += 256) {
        Wos[i] = Wo[i];
        int k = i >> 6, c = i & 63;
        Wqs[i] = Wqkv[k * 192 + c];
    }
    if (tid < 64) { bos[tid] = bo[tid]; g1s[tid] = ln1g[tid]; b1s[tid] = ln1b[tid]; bqs[tid] = bqkv[tid]; }
    __syncthreads();
    int wid = tid >> 5, lane = tid & 31;
    int r = blockIdx.x * 8 + wid;
    int dcol = lane * 2;
    float2 yv = *(const float2*)&g_y[((size_t)(r * 16 + 15)) * 64 + dcol];
    ys[wid][dcol] = yv.x; ys[wid][dcol + 1] = yv.y;
    __syncwarp();
    float q0 = bqs[dcol], q1 = bqs[dcol + 1];
#pragma unroll 16
    for (int j = 0; j < 64; j++) {
        float yj = ys[wid][j];
        float2 wv = *(const float2*)&Wqs[j * 64 + dcol];
        q0 += yj * wv.x; q1 += yj * wv.y;
    }
    sq[wid][dcol] = q0; sq[wid][dcol + 1] = q1;
    __syncwarp();
    int t = lane & 15, grp = lane >> 4;
    const float* kbase = &g_kv[((size_t)(r * 16 + t)) * 128 + grp * 32];
    const float* qq = &sq[wid][grp * 32];
    float s0 = 0.f, s1 = 0.f;
#pragma unroll
    for (int j4 = 0; j4 < 4; j4++) {
        float4 k0 = *(const float4*)&kbase[j4 * 4];
        float4 k1 = *(const float4*)&kbase[16 + j4 * 4];
        s0 += qq[j4 * 4 + 0] * k0.x + qq[j4 * 4 + 1] * k0.y + qq[j4 * 4 + 2] * k0.z + qq[j4 * 4 + 3] * k0.w;
        s1 += qq[16 + j4 * 4 + 0] * k1.x + qq[16 + j4 * 4 + 1] * k1.y + qq[16 + j4 * 4 + 2] * k1.z + qq[16 + j4 * 4 + 3] * k1.w;
    }
    s0 *= 0.25f; s1 *= 0.25f;
    float m0 = s0, m1 = s1;
#pragma unroll
    for (int off = 1; off < 16; off <<= 1) {
        m0 = fmaxf(m0, __shfl_xor_sync(0xffffffffu, m0, off));
        m1 = fmaxf(m1, __shfl_xor_sync(0xffffffffu, m1, off));
    }
    float p0 = __expf(s0 - m0), p1 = __expf(s1 - m1);
    float dn0 = p0, dn1 = p1;
#pragma unroll
    for (int off = 1; off < 16; off <<= 1) {
        dn0 += __shfl_xor_sync(0xffffffffu, dn0, off);
        dn1 += __shfl_xor_sync(0xffffffffu, dn1, off);
    }
    p0 /= dn0; p1 /= dn1;
    int hd = lane >> 3;
    int srcbase = (hd >> 1) * 16;
    int sel = hd & 1;
    float c0 = 0.f, c1 = 0.f;
#pragma unroll
    for (int tt = 0; tt < 16; tt++) {
        float pa = __shfl_sync(0xffffffffu, p0, srcbase + tt);
        float pb = __shfl_sync(0xffffffffu, p1, srcbase + tt);
        float pv = sel ? pb : pa;
        float2 v2 = *(const float2*)&g_kv[((size_t)(r * 16 + tt)) * 128 + 64 + dcol];
        c0 += pv * v2.x; c1 += pv * v2.y;
    }
    float o0 = bos[dcol], o1 = bos[dcol + 1];
#pragma unroll
    for (int jj = 0; jj < 32; jj++) {
        float ca = __shfl_sync(0xffffffffu, c0, jj);
        float cb = __shfl_sync(0xffffffffu, c1, jj);
        float2 wA = *(const float2*)&Wos[(2 * jj) * 64 + dcol];
        float2 wB = *(const float2*)&Wos[(2 * jj + 1) * 64 + dcol];
        o0 += ca * wA.x + cb * wB.x;
        o1 += ca * wA.y + cb * wB.y;
    }
    float r0v = ys[wid][dcol] + o0, r1v = ys[wid][dcol + 1] + o1;
    float su = r0v + r1v, s2 = r0v * r0v + r1v * r1v;
#pragma unroll
    for (int off = 1; off < 32; off <<= 1) {
        su += __shfl_xor_sync(0xffffffffu, su, off);
        s2 += __shfl_xor_sync(0xffffffffu, s2, off);
    }
    float mu = su * (1.f / 64.f);
    float var = s2 * (1.f / 64.f) - mu * mu;
    float inv = rsqrtf(var + 1e-5f);
    float2 z;
    z.x = (r0v - mu) * inv * g1s[dcol] + b1s[dcol];
    z.y = (r1v - mu) * inv * g1s[dcol + 1] + b1s[dcol + 1];
    *(float2*)&g_z[(size_t)r * 64 + dcol] = z;
}

// ---------------- fused FFN: out = LN2(z + relu(z@W1+b1)@W2 + b2) ------------
__global__ void __launch_bounds__(256) k_ffn(const float* __restrict__ b1,
                                             const float* __restrict__ b2,
                                             const float* __restrict__ ln2g,
                                             const float* __restrict__ ln2b,
                                             float* __restrict__ out) {
    __shared__ __half Ah[32 * SA_];
    __shared__ __half Sh[32 * SA_];
    __shared__ __half W1s[64 * SA_];
    __shared__ __half W2s[64 * SA_];
    __shared__ float OUTf[32 * 64];
    __shared__ float b1s[FF_];
    int tid = threadIdx.x, wid = tid >> 5, lane = tid & 31;
    int rb = blockIdx.x * 32;
    // stage A = z rows (fp32 -> fp16)
    for (int i = tid; i < 32 * 16; i += 256) {
        int r = i >> 4, s4 = i & 15;
        float4 v = *(const float4*)&g_z[((size_t)(rb + r)) * 64 + s4 * 4];
        HCvt h0, h1;
        h0.h2 = __floats2half2_rn(v.x, v.y);
        h1.h2 = __floats2half2_rn(v.z, v.w);
        *(uint2*)&Ah[r * SA_ + s4 * 4] = make_uint2(h0.u, h1.u);
    }
    for (int i = tid; i < FF_; i += 256) b1s[i] = b1[i];
    int mi = wid & 1, ni = wid >> 1;     // mi: m16 tile (0..1), ni: n16 tile (0..3)
    float o[2][4];
#pragma unroll
    for (int n8 = 0; n8 < 2; n8++)
#pragma unroll
        for (int q = 0; q < 4; q++) o[n8][q] = 0.f;
    int r0 = lane >> 2, c0 = (lane & 3) * 2;
    uint32_t a1base = su32(Ah) + ((mi * 16 + (lane & 15)) * SA_ + (lane >> 4) * 8) * 2;
    uint32_t a2base = su32(Sh) + ((mi * 16 + (lane & 15)) * SA_ + (lane >> 4) * 8) * 2;
    uint32_t w1base = su32(W1s) + (((lane & 15)) * SA_ + ni * 16 + (lane >> 4) * 8) * 2;
    uint32_t w2base = su32(W2s) + (((lane & 15)) * SA_ + ni * 16 + (lane >> 4) * 8) * 2;
    for (int cb = 0; cb < FF_; cb += 64) {
        __syncthreads();   // prior GEMM2 reads done; staging (A, b1s) done on first iter
        for (int i = tid; i < 512; i += 256) {
            int r = i >> 3, s = i & 7;
            *(uint4*)&W1s[r * SA_ + s * 8] = *(const uint4*)&g_w1h[(size_t)r * FF_ + cb + s * 8];
            *(uint4*)&W2s[r * SA_ + s * 8] = *(const uint4*)&g_w2h[(size_t)(cb + r) * 64 + s * 8];
        }
        __syncthreads();
        // GEMM1: S = relu(A @ W1c + b1c)
        float d[2][4];
#pragma unroll
        for (int n8 = 0; n8 < 2; n8++)
#pragma unroll
            for (int q = 0; q < 4; q++) d[n8][q] = 0.f;
#pragma unroll
        for (int k = 0; k < 4; k++) {
            uint32_t a0, a1, a2, a3, b0v, b1v, b2v, b3v;
            ldsm_x4(a0, a1, a2, a3, a1base + k * 32);
            ldsm_x4t(b0v, b1v, b2v, b3v, w1base + k * 16 * SA_ * 2);
            mma16816(d[0], a0, a1, a2, a3, b0v, b1v);
            mma16816(d[1], a0, a1, a2, a3, b2v, b3v);
        }
#pragma unroll
        for (int n8 = 0; n8 < 2; n8++) {
            int col = ni * 16 + n8 * 8 + c0;
            float bb0 = b1s[cb + col], bb1 = b1s[cb + col + 1];
            HCvt v0, v1;
            v0.h2 = __floats2half2_rn(fmaxf(d[n8][0] + bb0, 0.f), fmaxf(d[n8][1] + bb1, 0.f));
            v1.h2 = __floats2half2_rn(fmaxf(d[n8][2] + bb0, 0.f), fmaxf(d[n8][3] + bb1, 0.f));
            *(uint32_t*)&Sh[(mi * 16 + r0) * SA_ + col] = v0.u;
            *(uint32_t*)&Sh[(mi * 16 + r0 + 8) * SA_ + col] = v1.u;
        }
        __syncthreads();
        // GEMM2: o += S @ W2c
#pragma unroll
        for (int k = 0; k < 4; k++) {
            uint32_t a0, a1, a2, a3, b0v, b1v, b2v, b3v;
            ldsm_x4(a0, a1, a2, a3, a2base + k * 32);
            ldsm_x4t(b0v, b1v, b2v, b3v, w2base + k * 16 * SA_ * 2);
            mma16816(o[0], a0, a1, a2, a3, b0v, b1v);
            mma16816(o[1], a0, a1, a2, a3, b2v, b3v);
        }
    }
    __syncthreads();
#pragma unroll
    for (int n8 = 0; n8 < 2; n8++) {
        int col = ni * 16 + n8 * 8 + c0;
        *(float2*)&OUTf[(mi * 16 + r0) * 64 + col] = make_float2(o[n8][0], o[n8][1]);
        *(float2*)&OUTf[(mi * 16 + r0 + 8) * 64 + col] = make_float2(o[n8][2], o[n8][3]);
    }
    __syncthreads();
    // LN2 epilogue: rows rb..rb+31
    int d2 = lane * 2;
    for (int rr = wid; rr < 32; rr += 8) {
        int r = rb + rr;
        float2 zr = *(const float2*)&g_z[(size_t)r * 64 + d2];
        float2 ov = *(const float2*)&OUTf[rr * 64 + d2];
        float v0 = zr.x + ov.x + b2[d2];
        float v1 = zr.y + ov.y + b2[d2 + 1];
        float su = v0 + v1, s2 = v0 * v0 + v1 * v1;
#pragma unroll
        for (int off = 1; off < 32; off <<= 1) {
            su += __shfl_xor_sync(0xffffffffu, su, off);
            s2 += __shfl_xor_sync(0xffffffffu, s2, off);
        }
        float mu = su * (1.f / 64.f);
        float var = s2 * (1.f / 64.f) - mu * mu;
        float inv = rsqrtf(var + 1e-5f);
        float2 oo;
        oo.x = (v0 - mu) * inv * ln2g[d2] + ln2b[d2];
        oo.y = (v1 - mu) * inv * ln2g[d2 + 1] + ln2b[d2 + 1];
        *(float2*)&out[(size_t)r * 64 + d2] = oo;
    }
}

// ---------------- launch ----------------------------------------------------
extern "C" void kernel_launch(void* const* d_in, const int* in_sizes, int n_in,
                              void* d_out, int out_size) {
    const float* x_seq    = (const float*)d_in[0];
    const int*   eidx     = (const int*)d_in[1];
    const float* eweight  = (const float*)d_in[2];
    const float* W_gat    = (const float*)d_in[3];
    const float* att_src  = (const float*)d_in[4];
    const float* att_dst  = (const float*)d_in[5];
    const float* W_edge   = (const float*)d_in[6];
    const float* att_edge = (const float*)d_in[7];
    const float* gat_bias = (const float*)d_in[8];
    const float* W_proj   = (const float*)d_in[9];
    const float* b_proj   = (const float*)d_in[10];
    const float* Wqkv     = (const float*)d_in[11];
    const float* bqkv     = (const float*)d_in[12];
    const float* Wo       = (const float*)d_in[13];
    const float* bo       = (const float*)d_in[14];
    const float* ln1_g    = (const float*)d_in[15];
    const float* ln1_b    = (const float*)d_in[16];
    const float* W1       = (const float*)d_in[17];
    const float* b1       = (const float*)d_in[18];
    const float* W2       = (const float*)d_in[19];
    const float* b2       = (const float*)d_in[20];
    const float* ln2_g    = (const float*)d_in[21];
    const float* ln2_b    = (const float*)d_in[22];
    float* out = (float*)d_out;

    k_cvt<<<512, 256>>>(Wqkv, W1, W2);
    k_h<<<GN_ / 8, 256>>>(x_seq, W_gat, att_src, att_dst);
    k_count<<<(ET_ + 255) / 256, 256>>>(eidx, eweight);
    k_scan<<<1, 1024>>>(W_edge, att_edge);
    k_scatter<<<(ET_ + 255) / 256, 256>>>(eidx);
    k_agg<<<GN_ / 8, 256>>>(eidx, eweight, gat_bias, W_proj, b_proj);
    k_qkv_mma<<<GN_ / 64, 256>>>(bqkv);
    k_attn2<<<BN_ / 8, 256>>>(Wqkv, bqkv, Wo, bo, ln1_g, ln1_b);
    k_ffn<<<BN_ / 32, 256>>>(b1, b2, ln2_g, ln2_b, out);
}

// round 7
// speedup vs baseline: 1.6052x; 1.1281x over previous
#include <cuda_runtime.h>
#include <cuda_fp16.h>
#include <cstdint>

#define B_ 2
#define T_ 16
#define N_ 2000
#define F_ 16
#define E_ 32000
#define H_ 4
#define C_ 32
#define D_ 64
#define FF_ 2048
#define G_ (B_*T_)      /* 32  */
#define ET_ (E_+N_)     /* 34000 */
#define BN_ (B_*N_)     /* 4000 */
#define GN_ (G_*N_)     /* 64000 */

// ---------------- scratch (static device globals; no allocation) -------------
__device__ __half g_h[(size_t)GN_ * 128];  // h: [G,N,H*C] fp16
__device__ float g_asrc[GN_ * 4];
__device__ float g_adst[GN_ * 4];
__device__ float g_prep[8];               // c_edge[0..3], ew_mean at [4]
__device__ unsigned long long g_ewsum;    // fixed-point sum of edge weights
__device__ int   g_deg[2048];
__device__ int   g_off[N_ + 1];
__device__ int   g_cur[N_];
__device__ int   g_csr[ET_];
__device__ __half g_y[GN_ * D_];          // fp16 [bn][t][d]  (row rn = bn*16+t)
__device__ __half g_kv[(size_t)GN_ * 128];// fp16 [rn][0:64)=K, [64:128)=V
__device__ float g_z[BN_ * D_];           // post-LN1
__device__ __half g_wkvh[64 * 128];       // fp16 Wqkv[:,64:192]
__device__ __half g_w1h[64 * FF_];        // fp16 W1
__device__ __half g_w2h[FF_ * 64];        // fp16 W2

union HCvt { __half2 h2; uint32_t u; };

// ---------------- mma helpers ------------------------------------------------
__device__ __forceinline__ uint32_t su32(const void* p) {
    uint32_t a;
    asm("{ .reg .u64 t; cvta.to.shared.u64 t, %1; cvt.u32.u64 %0, t; }" : "=r"(a) : "l"(p));
    return a;
}
__device__ __forceinline__ void ldsm_x4(uint32_t& r0, uint32_t& r1, uint32_t& r2, uint32_t& r3, uint32_t a) {
    asm volatile("ldmatrix.sync.aligned.m8n8.x4.shared.b16 {%0,%1,%2,%3}, [%4];"
                 : "=r"(r0), "=r"(r1), "=r"(r2), "=r"(r3) : "r"(a));
}
__device__ __forceinline__ void ldsm_x4t(uint32_t& r0, uint32_t& r1, uint32_t& r2, uint32_t& r3, uint32_t a) {
    asm volatile("ldmatrix.sync.aligned.m8n8.x4.trans.shared.b16 {%0,%1,%2,%3}, [%4];"
                 : "=r"(r0), "=r"(r1), "=r"(r2), "=r"(r3) : "r"(a));
}
__device__ __forceinline__ void mma16816(float* d, uint32_t a0, uint32_t a1, uint32_t a2, uint32_t a3,
                                         uint32_t b0, uint32_t b1) {
    asm volatile("mma.sync.aligned.m16n8k16.row.col.f32.f16.f16.f32 "
                 "{%0,%1,%2,%3}, {%4,%5,%6,%7}, {%8,%9}, {%0,%1,%2,%3};"
                 : "+f"(d[0]), "+f"(d[1]), "+f"(d[2]), "+f"(d[3])
                 : "r"(a0), "r"(a1), "r"(a2), "r"(a3), "r"(b0), "r"(b1));
}

// ---------------- weight conversion to fp16 ----------------------------------
__global__ void k_cvt(const float* __restrict__ Wqkv, const float* __restrict__ W1,
                      const float* __restrict__ W2) {
    int i = blockIdx.x * 256 + threadIdx.x;
    if (i < 64 * 128) {
        int k = i >> 7, c = i & 127;
        g_wkvh[i] = __float2half(Wqkv[k * 192 + 64 + c]);
    }
    if (i < 64 * FF_) {
        g_w1h[i] = __float2half(W1[i]);
        g_w2h[i] = __float2half(W2[i]);
    }
}

// ---------------- count (fused with edge-weight sum) -------------------------
__global__ void k_count(const int* __restrict__ ei, const float* __restrict__ ew) {
    int e = blockIdx.x * blockDim.x + threadIdx.x;
    if (e >= ET_) return;
    int d;
    if (e < E_) {
        d = ei[E_ + e];
        atomicAdd(&g_ewsum, (unsigned long long)((double)ew[e] * 4294967296.0));
    } else {
        d = e - E_;
    }
    atomicAdd(&g_deg[d], 1);
}

// ---------------- scan (+ edge consts, self-zero deg & ewsum) ----------------
__global__ void k_scan(const float* __restrict__ W_edge,
                       const float* __restrict__ att_edge) {
    __shared__ int ws[32];
    int t = threadIdx.x;
    int i0 = 2 * t, i1 = 2 * t + 1;
    int a = (i0 < N_) ? g_deg[i0] : 0;
    int b = (i1 < N_) ? g_deg[i1] : 0;
    int v = a + b;
    int lane = t & 31, wid = t >> 5;
#pragma unroll
    for (int off = 1; off < 32; off <<= 1) {
        int n = __shfl_up_sync(0xffffffffu, v, off);
        if (lane >= off) v += n;
    }
    if (lane == 31) ws[wid] = v;
    __syncthreads();
    if (t < 32) {
        int u = ws[t];
#pragma unroll
        for (int off = 1; off < 32; off <<= 1) {
            int n = __shfl_up_sync(0xffffffffu, u, off);
            if (t >= off) u += n;
        }
        ws[t] = u;
    }
    __syncthreads();
    int base = (wid > 0) ? ws[wid - 1] : 0;
    int incl = v + base;
    int ex0 = incl - a - b;
    if (i0 <= N_) { g_off[i0] = ex0; if (i0 < N_) g_cur[i0] = ex0; }
    if (i1 <= N_) { g_off[i1] = ex0 + a; if (i1 < N_) g_cur[i1] = ex0 + a; }
    g_deg[i0] = 0; g_deg[i1] = 0;
    if (t < 4) {
        float c = 0.f;
        for (int j = 0; j < 32; j++) c += W_edge[t * 32 + j] * att_edge[t * 32 + j];
        g_prep[t] = c;
    }
    if (t == 4) {
        g_prep[4] = (float)((double)g_ewsum / 4294967296.0 / (double)E_);
        g_ewsum = 0ull;
    }
}

__global__ void k_scatter(const int* __restrict__ ei) {
    int e = blockIdx.x * blockDim.x + threadIdx.x;
    if (e >= ET_) return;
    int d = (e < E_) ? ei[E_ + e] : (e - E_);
    int pos = atomicAdd(&g_cur[d], 1);
    g_csr[pos] = e;
}

// ---------------- h = x @ W_gat (fp16 out); attn scalar terms (fp32) ---------
__global__ void __launch_bounds__(256) k_h(const float* __restrict__ x,
                                           const float* __restrict__ Wg,
                                           const float* __restrict__ as_w,
                                           const float* __restrict__ ad_w) {
    __shared__ float Wgs[16 * 128];
    __shared__ float s_as[128], s_ad[128];
    int tid = threadIdx.x;
    for (int i = tid; i < 2048; i += 256) Wgs[i] = Wg[i];
    for (int i = tid; i < 128; i += 256) { s_as[i] = as_w[i]; s_ad[i] = ad_w[i]; }
    __syncthreads();
    int w = blockIdx.x * 8 + (tid >> 5);
    if (w >= GN_) return;
    int lane = tid & 31;
    const float* xr = x + (size_t)w * 16;
    float xf = (lane < 16) ? xr[lane] : 0.f;
    float4 h4 = make_float4(0.f, 0.f, 0.f, 0.f);
    const float4* Wg4 = (const float4*)Wgs;
#pragma unroll
    for (int f = 0; f < 16; f++) {
        float xv = __shfl_sync(0xffffffffu, xf, f);
        float4 wv = Wg4[f * 32 + lane];
        h4.x += xv * wv.x; h4.y += xv * wv.y; h4.z += xv * wv.z; h4.w += xv * wv.w;
    }
    HCvt c0, c1;
    c0.h2 = __floats2half2_rn(h4.x, h4.y);
    c1.h2 = __floats2half2_rn(h4.z, h4.w);
    *(uint2*)&g_h[(size_t)w * 128 + lane * 4] = make_uint2(c0.u, c1.u);
    float4 a = ((const float4*)s_as)[lane];
    float4 d = ((const float4*)s_ad)[lane];
    float vs = h4.x * a.x + h4.y * a.y + h4.z * a.z + h4.w * a.w;
    float vd = h4.x * d.x + h4.y * d.y + h4.z * d.z + h4.w * d.w;
#pragma unroll
    for (int off = 1; off < 8; off <<= 1) {
        vs += __shfl_xor_sync(0xffffffffu, vs, off);
        vd += __shfl_xor_sync(0xffffffffu, vd, off);
    }
    if ((lane & 7) == 0) {
        g_asrc[w * 4 + (lane >> 3)] = vs;
        g_adst[w * 4 + (lane >> 3)] = vd;
    }
}

// ---------------- GAT aggregate (pipelined) + head-mean + proj ---------------
#define FETCH_SW(idx, S, W) \
    if ((idx) < end) { int e_ = g_csr[idx]; \
        if (e_ < E_) { S = ei[e_]; W = ew[e_]; } else { S = e_ - E_; W = ewm_s; } } \
    else { S = 0; W = 0.f; }

__global__ void __launch_bounds__(256) k_agg(const int* __restrict__ ei,
                                             const float* __restrict__ ew,
                                             const float* __restrict__ gbias,
                                             const float* __restrict__ Wp,
                                             const float* __restrict__ bp) {
    __shared__ float Wps[32 * 64];
    __shared__ float bias_s[32];
    __shared__ float bp_s[64];
    __shared__ float ce_s[4];
    __shared__ float ewm_sh;
    int tid = threadIdx.x;
    for (int i = tid; i < 2048; i += 256) Wps[i] = Wp[i];
    if (tid < 32) bias_s[tid] = gbias[tid];
    if (tid < 64) bp_s[tid] = bp[tid];
    if (tid < 4)  ce_s[tid] = g_prep[tid];
    if (tid == 8) ewm_sh = g_prep[4];
    __syncthreads();
    int w = blockIdx.x * 8 + (tid >> 5);
    if (w >= GN_) return;
    float ewm_s = ewm_sh;
    int lane = tid & 31;
    int g = w / N_;
    int dst = w - g * N_;
    int hd = lane >> 3;
    float ad = g_adst[((size_t)g * N_ + dst) * 4 + hd];
    float ce = ce_s[hd];
    float acc0 = 0.f, acc1 = 0.f, acc2 = 0.f, acc3 = 0.f, den = 0.f;
    int beg = g_off[dst], end = g_off[dst + 1];
    const __half* hbase = g_h + (size_t)g * N_ * 128;
    const float* abase = g_asrc + (size_t)g * N_ * 4;
    // pipeline: scalars fetched 3 ahead, h-row + asrc issued 2 ahead
    int sc, sA, sB; float wc, wA, wB;
    FETCH_SW(beg,     sc, wc);
    FETCH_SW(beg + 1, sA, wA);
    FETCH_SW(beg + 2, sB, wB);
    uint2 hc = *(const uint2*)(hbase + (size_t)sc * 128 + lane * 4);
    float asc = abase[sc * 4 + hd];
    uint2 hn = *(const uint2*)(hbase + (size_t)sA * 128 + lane * 4);
    float asn = abase[sA * 4 + hd];
    for (int i = beg; i < end; i++) {
        float lg = asc + ad + ce * wc;
        lg = (lg > 0.f) ? lg : 0.2f * lg;
        float p = __expf(lg);
        den += p;
        float2 f0 = __half22float2(*(__half2*)&hc.x);
        float2 f1 = __half22float2(*(__half2*)&hc.y);
        acc0 += p * f0.x; acc1 += p * f0.y; acc2 += p * f1.x; acc3 += p * f1.y;
        // rotate pipeline
        sc = sA; wc = wA; hc = hn; asc = asn;
        sA = sB; wA = wB;
        hn = *(const uint2*)(hbase + (size_t)sA * 128 + lane * 4);
        asn = abase[sA * 4 + hd];
        FETCH_SW(i + 3, sB, wB);
    }
    float inv = 1.f / (den + 1e-16f);
    acc0 *= inv; acc1 *= inv; acc2 *= inv; acc3 *= inv;
    acc0 += __shfl_xor_sync(0xffffffffu, acc0, 8);  acc0 += __shfl_xor_sync(0xffffffffu, acc0, 16);
    acc1 += __shfl_xor_sync(0xffffffffu, acc1, 8);  acc1 += __shfl_xor_sync(0xffffffffu, acc1, 16);
    acc2 += __shfl_xor_sync(0xffffffffu, acc2, 8);  acc2 += __shfl_xor_sync(0xffffffffu, acc2, 16);
    acc3 += __shfl_xor_sync(0xffffffffu, acc3, 8);  acc3 += __shfl_xor_sync(0xffffffffu, acc3, 16);
    int cb = (lane & 7) * 4;
    float og0 = acc0 * 0.25f + bias_s[cb + 0];
    float og1 = acc1 * 0.25f + bias_s[cb + 1];
    float og2 = acc2 * 0.25f + bias_s[cb + 2];
    float og3 = acc3 * 0.25f + bias_s[cb + 3];
    int d0 = lane * 2;
    float y0 = bp_s[d0], y1 = bp_s[d0 + 1];
#pragma unroll
    for (int sl = 0; sl < 8; sl++) {
        float v0 = __shfl_sync(0xffffffffu, og0, sl);
        float v1 = __shfl_sync(0xffffffffu, og1, sl);
        float v2 = __shfl_sync(0xffffffffu, og2, sl);
        float v3 = __shfl_sync(0xffffffffu, og3, sl);
        int c = sl * 4;
        float2 w0 = *(const float2*)&Wps[(c + 0) * 64 + d0];
        float2 w1 = *(const float2*)&Wps[(c + 1) * 64 + d0];
        float2 w2 = *(const float2*)&Wps[(c + 2) * 64 + d0];
        float2 w3 = *(const float2*)&Wps[(c + 3) * 64 + d0];
        y0 += v0 * w0.x + v1 * w1.x + v2 * w2.x + v3 * w3.x;
        y1 += v0 * w0.y + v1 * w1.y + v2 * w2.y + v3 * w3.y;
    }
    int b = g >> 4;
    int t = g & 15;
    HCvt yo; yo.h2 = __floats2half2_rn(y0, y1);
    *(uint32_t*)&g_y[(((size_t)(b * N_ + dst)) * T_ + t) * D_ + d0] = yo.u;
}

// ---------------- K,V GEMM via HMMA: g_kv = y @ Wkv + b (fp16 out) -----------
#define SA_ 72
#define SB_ 136
__global__ void __launch_bounds__(256) k_qkv_mma(const float* __restrict__ bqkv) {
    __shared__ __half Ah[64 * SA_];
    __shared__ __half Bs[64 * SB_];
    __shared__ float bqs[128];
    int tid = threadIdx.x, wid = tid >> 5, lane = tid & 31;
    int rb = blockIdx.x * 64;
    for (int i = tid; i < 512; i += 256) {
        int r = i >> 3, s = i & 7;
        *(uint4*)&Ah[r * SA_ + s * 8] = *(const uint4*)&g_y[((size_t)(rb + r)) * 64 + s * 8];
    }
    for (int i = tid; i < 64 * 16; i += 256) {
        int r = i >> 4, s = i & 15;
        *(uint4*)&Bs[r * SB_ + s * 8] = *(const uint4*)&g_wkvh[r * 128 + s * 8];
    }
    if (tid < 128) bqs[tid] = bqkv[64 + tid];
    __syncthreads();
    int mi = wid >> 1;
    int nb = (wid & 1) * 64;
    float o[4][2][4];
#pragma unroll
    for (int j = 0; j < 4; j++)
#pragma unroll
        for (int n8 = 0; n8 < 2; n8++)
#pragma unroll
            for (int q = 0; q < 4; q++) o[j][n8][q] = 0.f;
    uint32_t abase = su32(Ah) + ((mi * 16 + (lane & 15)) * SA_ + (lane >> 4) * 8) * 2;
    uint32_t bbase = su32(Bs) + (((lane & 15)) * SB_ + nb + (lane >> 4) * 8) * 2;
#pragma unroll
    for (int k = 0; k < 4; k++) {
        uint32_t a0, a1, a2, a3;
        ldsm_x4(a0, a1, a2, a3, abase + k * 32);
#pragma unroll
        for (int j = 0; j < 4; j++) {
            uint32_t b0, b1, b2, b3;
            ldsm_x4t(b0, b1, b2, b3, bbase + (k * 16 * SB_ + j * 16) * 2);
            mma16816(o[j][0], a0, a1, a2, a3, b0, b1);
            mma16816(o[j][1], a0, a1, a2, a3, b2, b3);
        }
    }
    int r0 = lane >> 2, c0 = (lane & 3) * 2;
#pragma unroll
    for (int j = 0; j < 4; j++)
#pragma unroll
        for (int n8 = 0; n8 < 2; n8++)
#pragma unroll
            for (int hm = 0; hm < 2; hm++) {
                int row = rb + mi * 16 + r0 + hm * 8;
                int col = nb + j * 16 + n8 * 8 + c0;
                HCvt v; v.h2 = __floats2half2_rn(o[j][n8][hm * 2 + 0] + bqs[col],
                                                 o[j][n8][hm * 2 + 1] + bqs[col + 1]);
                *(uint32_t*)&g_kv[(size_t)row * 128 + col] = v.u;
            }
}

// ---------------- Q (in-kernel) + attention + Wo + residual + LN1 ------------
__global__ void __launch_bounds__(256) k_attn2(const float* __restrict__ Wqkv,
                                               const float* __restrict__ bqkv,
                                               const float* __restrict__ Wo,
                                               const float* __restrict__ bo,
                                               const float* __restrict__ ln1g,
                                               const float* __restrict__ ln1b) {
    __shared__ float Wos[64 * 64];
    __shared__ float Wqs[64 * 64];
    __shared__ float bos[64], g1s[64], b1s[64], bqs[64];
    __shared__ float ys[8][64];
    __shared__ float sq[8][64];
    int tid = threadIdx.x;
    for (int i = tid; i < 4096; i += 256) {
        Wos[i] = Wo[i];
        int k = i >> 6, c = i & 63;
        Wqs[i] = Wqkv[k * 192 + c];
    }
    if (tid < 64) { bos[tid] = bo[tid]; g1s[tid] = ln1g[tid]; b1s[tid] = ln1b[tid]; bqs[tid] = bqkv[tid]; }
    __syncthreads();
    int wid = tid >> 5, lane = tid & 31;
    int dcol = lane * 2;
    for (int rr = 0; rr < 2; rr++) {
        int r = blockIdx.x * 16 + wid * 2 + rr;
        // load y at t=15 (fp16) for this row
        __half2 yh = *(const __half2*)&g_y[((size_t)(r * 16 + 15)) * 64 + dcol];
        float2 yv = __half22float2(yh);
        ys[wid][dcol] = yv.x; ys[wid][dcol + 1] = yv.y;
        __syncwarp();
        float q0 = bqs[dcol], q1 = bqs[dcol + 1];
#pragma unroll 16
        for (int j = 0; j < 64; j++) {
            float yj = ys[wid][j];
            float2 wv = *(const float2*)&Wqs[j * 64 + dcol];
            q0 += yj * wv.x; q1 += yj * wv.y;
        }
        sq[wid][dcol] = q0; sq[wid][dcol + 1] = q1;
        __syncwarp();
        int t = lane & 15, grp = lane >> 4;
        const __half* kbase = &g_kv[((size_t)(r * 16 + t)) * 128 + grp * 32];
        const float* qq = &sq[wid][grp * 32];
        uint4 kr0 = *(const uint4*)&kbase[0];
        uint4 kr1 = *(const uint4*)&kbase[8];
        uint4 kr2 = *(const uint4*)&kbase[16];
        uint4 kr3 = *(const uint4*)&kbase[24];
        float s0 = 0.f, s1 = 0.f;
        {
            const uint32_t* kw0 = &kr0.x;
            const uint32_t* kw1 = &kr1.x;
#pragma unroll
            for (int j2 = 0; j2 < 4; j2++) {
                float2 f0 = __half22float2(*(const __half2*)&kw0[j2]);
                float2 f1 = __half22float2(*(const __half2*)&kw1[j2]);
                s0 += qq[j2 * 2 + 0] * f0.x + qq[j2 * 2 + 1] * f0.y;
                s0 += qq[8 + j2 * 2 + 0] * f1.x + qq[8 + j2 * 2 + 1] * f1.y;
            }
            const uint32_t* kw2 = &kr2.x;
            const uint32_t* kw3 = &kr3.x;
#pragma unroll
            for (int j2 = 0; j2 < 4; j2++) {
                float2 f2 = __half22float2(*(const __half2*)&kw2[j2]);
                float2 f3 = __half22float2(*(const __half2*)&kw3[j2]);
                s1 += qq[16 + j2 * 2 + 0] * f2.x + qq[16 + j2 * 2 + 1] * f2.y;
                s1 += qq[24 + j2 * 2 + 0] * f3.x + qq[24 + j2 * 2 + 1] * f3.y;
            }
        }
        s0 *= 0.25f; s1 *= 0.25f;
        float m0 = s0, m1 = s1;
#pragma unroll
        for (int off = 1; off < 16; off <<= 1) {
            m0 = fmaxf(m0, __shfl_xor_sync(0xffffffffu, m0, off));
            m1 = fmaxf(m1, __shfl_xor_sync(0xffffffffu, m1, off));
        }
        float p0 = __expf(s0 - m0), p1 = __expf(s1 - m1);
        float dn0 = p0, dn1 = p1;
#pragma unroll
        for (int off = 1; off < 16; off <<= 1) {
            dn0 += __shfl_xor_sync(0xffffffffu, dn0, off);
            dn1 += __shfl_xor_sync(0xffffffffu, dn1, off);
        }
        p0 /= dn0; p1 /= dn1;
        int hd = lane >> 3;
        int srcbase = (hd >> 1) * 16;
        int sel = hd & 1;
        float c0 = 0.f, c1 = 0.f;
#pragma unroll
        for (int tt = 0; tt < 16; tt++) {
            float pa = __shfl_sync(0xffffffffu, p0, srcbase + tt);
            float pb = __shfl_sync(0xffffffffu, p1, srcbase + tt);
            float pv = sel ? pb : pa;
            __half2 v2h = *(const __half2*)&g_kv[((size_t)(r * 16 + tt)) * 128 + 64 + dcol];
            float2 v2 = __half22float2(v2h);
            c0 += pv * v2.x; c1 += pv * v2.y;
        }
        float o0 = bos[dcol], o1 = bos[dcol + 1];
#pragma unroll
        for (int jj = 0; jj < 32; jj++) {
            float ca = __shfl_sync(0xffffffffu, c0, jj);
            float cb = __shfl_sync(0xffffffffu, c1, jj);
            float2 wA = *(const float2*)&Wos[(2 * jj) * 64 + dcol];
            float2 wB = *(const float2*)&Wos[(2 * jj + 1) * 64 + dcol];
            o0 += ca * wA.x + cb * wB.x;
            o1 += ca * wA.y + cb * wB.y;
        }
        float r0v = ys[wid][dcol] + o0, r1v = ys[wid][dcol + 1] + o1;
        float su = r0v + r1v, s2 = r0v * r0v + r1v * r1v;
#pragma unroll
        for (int off = 1; off < 32; off <<= 1) {
            su += __shfl_xor_sync(0xffffffffu, su, off);
            s2 += __shfl_xor_sync(0xffffffffu, s2, off);
        }
        float mu = su * (1.f / 64.f);
        float var = s2 * (1.f / 64.f) - mu * mu;
        float inv = rsqrtf(var + 1e-5f);
        float2 z;
        z.x = (r0v - mu) * inv * g1s[dcol] + b1s[dcol];
        z.y = (r1v - mu) * inv * g1s[dcol + 1] + b1s[dcol + 1];
        *(float2*)&g_z[(size_t)r * 64 + dcol] = z;
    }
}

// ---------------- fused FFN: out = LN2(z + relu(z@W1+b1)@W2 + b2) ------------
__global__ void __launch_bounds__(256) k_ffn(const float* __restrict__ b1,
                                             const float* __restrict__ b2,
                                             const float* __restrict__ ln2g,
                                             const float* __restrict__ ln2b,
                                             float* __restrict__ out) {
    __shared__ __half Ah[32 * SA_];
    __shared__ __half Sh[32 * SA_];
    __shared__ __half W1s[64 * SA_];
    __shared__ __half W2s[64 * SA_];
    __shared__ float OUTf[32 * 64];
    __shared__ float b1s[FF_];
    int tid = threadIdx.x, wid = tid >> 5, lane = tid & 31;
    int rb = blockIdx.x * 32;
    for (int i = tid; i < 32 * 16; i += 256) {
        int r = i >> 4, s4 = i & 15;
        float4 v = *(const float4*)&g_z[((size_t)(rb + r)) * 64 + s4 * 4];
        HCvt h0, h1;
        h0.h2 = __floats2half2_rn(v.x, v.y);
        h1.h2 = __floats2half2_rn(v.z, v.w);
        *(uint2*)&Ah[r * SA_ + s4 * 4] = make_uint2(h0.u, h1.u);
    }
    for (int i = tid; i < FF_; i += 256) b1s[i] = b1[i];
    int mi = wid & 1, ni = wid >> 1;
    float o[2][4];
#pragma unroll
    for (int n8 = 0; n8 < 2; n8++)
#pragma unroll
        for (int q = 0; q < 4; q++) o[n8][q] = 0.f;
    int r0 = lane >> 2, c0 = (lane & 3) * 2;
    uint32_t a1base = su32(Ah) + ((mi * 16 + (lane & 15)) * SA_ + (lane >> 4) * 8) * 2;
    uint32_t a2base = su32(Sh) + ((mi * 16 + (lane & 15)) * SA_ + (lane >> 4) * 8) * 2;
    uint32_t w1base = su32(W1s) + (((lane & 15)) * SA_ + ni * 16 + (lane >> 4) * 8) * 2;
    uint32_t w2base = su32(W2s) + (((lane & 15)) * SA_ + ni * 16 + (lane >> 4) * 8) * 2;
    for (int cb = 0; cb < FF_; cb += 64) {
        __syncthreads();
        for (int i = tid; i < 512; i += 256) {
            int r = i >> 3, s = i & 7;
            *(uint4*)&W1s[r * SA_ + s * 8] = *(const uint4*)&g_w1h[(size_t)r * FF_ + cb + s * 8];
            *(uint4*)&W2s[r * SA_ + s * 8] = *(const uint4*)&g_w2h[(size_t)(cb + r) * 64 + s * 8];
        }
        __syncthreads();
        float d[2][4];
#pragma unroll
        for (int n8 = 0; n8 < 2; n8++)
#pragma unroll
            for (int q = 0; q < 4; q++) d[n8][q] = 0.f;
#pragma unroll
        for (int k = 0; k < 4; k++) {
            uint32_t a0, a1, a2, a3, b0v, b1v, b2v, b3v;
            ldsm_x4(a0, a1, a2, a3, a1base + k * 32);
            ldsm_x4t(b0v, b1v, b2v, b3v, w1base + k * 16 * SA_ * 2);
            mma16816(d[0], a0, a1, a2, a3, b0v, b1v);
            mma16816(d[1], a0, a1, a2, a3, b2v, b3v);
        }
#pragma unroll
        for (int n8 = 0; n8 < 2; n8++) {
            int col = ni * 16 + n8 * 8 + c0;
            float bb0 = b1s[cb + col], bb1 = b1s[cb + col + 1];
            HCvt v0, v1;
            v0.h2 = __floats2half2_rn(fmaxf(d[n8][0] + bb0, 0.f), fmaxf(d[n8][1] + bb1, 0.f));
            v1.h2 = __floats2half2_rn(fmaxf(d[n8][2] + bb0, 0.f), fmaxf(d[n8][3] + bb1, 0.f));
            *(uint32_t*)&Sh[(mi * 16 + r0) * SA_ + col] = v0.u;
            *(uint32_t*)&Sh[(mi * 16 + r0 + 8) * SA_ + col] = v1.u;
        }
        __syncthreads();
#pragma unroll
        for (int k = 0; k < 4; k++) {
            uint32_t a0, a1, a2, a3, b0v, b1v, b2v, b3v;
            ldsm_x4(a0, a1, a2, a3, a2base + k * 32);
            ldsm_x4t(b0v, b1v, b2v, b3v, w2base + k * 16 * SA_ * 2);
            mma16816(o[0], a0, a1, a2, a3, b0v, b1v);
            mma16816(o[1], a0, a1, a2, a3, b2v, b3v);
        }
    }
    __syncthreads();
#pragma unroll
    for (int n8 = 0; n8 < 2; n8++) {
        int col = ni * 16 + n8 * 8 + c0;
        *(float2*)&OUTf[(mi * 16 + r0) * 64 + col] = make_float2(o[n8][0], o[n8][1]);
        *(float2*)&OUTf[(mi * 16 + r0 + 8) * 64 + col] = make_float2(o[n8][2], o[n8][3]);
    }
    __syncthreads();
    int d2 = lane * 2;
    for (int rr = wid; rr < 32; rr += 8) {
        int r = rb + rr;
        float2 zr = *(const float2*)&g_z[(size_t)r * 64 + d2];
        float2 ov = *(const float2*)&OUTf[rr * 64 + d2];
        float v0 = zr.x + ov.x + b2[d2];
        float v1 = zr.y + ov.y + b2[d2 + 1];
        float su = v0 + v1, s2 = v0 * v0 + v1 * v1;
#pragma unroll
        for (int off = 1; off < 32; off <<= 1) {
            su += __shfl_xor_sync(0xffffffffu, su, off);
            s2 += __shfl_xor_sync(0xffffffffu, s2, off);
        }
        float mu = su * (1.f / 64.f);
        float var = s2 * (1.f / 64.f) - mu * mu;
        float inv = rsqrtf(var + 1e-5f);
        float2 oo;
        oo.x = (v0 - mu) * inv * ln2g[d2] + ln2b[d2];
        oo.y = (v1 - mu) * inv * ln2g[d2 + 1] + ln2b[d2 + 1];
        *(float2*)&out[(size_t)r * 64 + d2] = oo;
    }
}

// ---------------- launch ----------------------------------------------------
extern "C" void kernel_launch(void* const* d_in, const int* in_sizes, int n_in,
                              void* d_out, int out_size) {
    const float* x_seq    = (const float*)d_in[0];
    const int*   eidx     = (const int*)d_in[1];
    const float* eweight  = (const float*)d_in[2];
    const float* W_gat    = (const float*)d_in[3];
    const float* att_src  = (const float*)d_in[4];
    const float* att_dst  = (const float*)d_in[5];
    const float* W_edge   = (const float*)d_in[6];
    const float* att_edge = (const float*)d_in[7];
    const float* gat_bias = (const float*)d_in[8];
    const float* W_proj   = (const float*)d_in[9];
    const float* b_proj   = (const float*)d_in[10];
    const float* Wqkv     = (const float*)d_in[11];
    const float* bqkv     = (const float*)d_in[12];
    const float* Wo       = (const float*)d_in[13];
    const float* bo       = (const float*)d_in[14];
    const float* ln1_g    = (const float*)d_in[15];
    const float* ln1_b    = (const float*)d_in[16];
    const float* W1       = (const float*)d_in[17];
    const float* b1       = (const float*)d_in[18];
    const float* W2       = (const float*)d_in[19];
    const float* b2       = (const float*)d_in[20];
    const float* ln2_g    = (const float*)d_in[21];
    const float* ln2_b    = (const float*)d_in[22];
    float* out = (float*)d_out;

    k_cvt<<<512, 256>>>(Wqkv, W1, W2);
    k_h<<<GN_ / 8, 256>>>(x_seq, W_gat, att_src, att_dst);
    k_count<<<(ET_ + 255) / 256, 256>>>(eidx, eweight);
    k_scan<<<1, 1024>>>(W_edge, att_edge);
    k_scatter<<<(ET_ + 255) / 256, 256>>>(eidx);
    k_agg<<<GN_ / 8, 256>>>(eidx, eweight, gat_bias, W_proj, b_proj);
    k_qkv_mma<<<GN_ / 64, 256>>>(bqkv);
    k_attn2<<<BN_ / 16, 256>>>(Wqkv, bqkv, Wo, bo, ln1_g, ln1_b);
    k_ffn<<<BN_ / 32, 256>>>(b1, b2, ln2_g, ln2_b, out);
}

// round 8
// speedup vs baseline: 1.6611x; 1.0349x over previous
#include <cuda_runtime.h>
#include <cuda_fp16.h>
#include <cstdint>

#define B_ 2
#define T_ 16
#define N_ 2000
#define F_ 16
#define E_ 32000
#define H_ 4
#define C_ 32
#define D_ 64
#define FF_ 2048
#define G_ (B_*T_)      /* 32  */
#define ET_ (E_+N_)     /* 34000 */
#define BN_ (B_*N_)     /* 4000 */
#define GN_ (G_*N_)     /* 64000 */

// ---------------- scratch (static device globals; no allocation) -------------
__device__ __half g_h[(size_t)GN_ * 128];  // h: [G,N,H*C] fp16
__device__ float g_asrc[GN_ * 4];
__device__ float g_adst[GN_ * 4];
__device__ float g_prep[8];               // c_edge[0..3], ew_mean at [4]
__device__ unsigned long long g_ewsum;    // fixed-point sum of edge weights
__device__ int   g_deg[2048];
__device__ int   g_off[N_ + 1];
__device__ int   g_cur[N_];
__device__ int   g_csr[ET_];
__device__ __half g_y[GN_ * D_];          // fp16 [bn][t][d]  (row rn = bn*16+t)
__device__ __half g_kv[(size_t)GN_ * 128];// fp16 [rn][0:64)=K, [64:128)=V
__device__ float g_z[BN_ * D_];           // post-LN1
__device__ __half g_wkvh[64 * 128];       // fp16 Wqkv[:,64:192]
__device__ __half g_w1h[64 * FF_];        // fp16 W1
__device__ __half g_w2h[FF_ * 64];        // fp16 W2

union HCvt { __half2 h2; uint32_t u; };

// ---------------- mma helpers ------------------------------------------------
__device__ __forceinline__ uint32_t su32(const void* p) {
    uint32_t a;
    asm("{ .reg .u64 t; cvta.to.shared.u64 t, %1; cvt.u32.u64 %0, t; }" : "=r"(a) : "l"(p));
    return a;
}
__device__ __forceinline__ void ldsm_x4(uint32_t& r0, uint32_t& r1, uint32_t& r2, uint32_t& r3, uint32_t a) {
    asm volatile("ldmatrix.sync.aligned.m8n8.x4.shared.b16 {%0,%1,%2,%3}, [%4];"
                 : "=r"(r0), "=r"(r1), "=r"(r2), "=r"(r3) : "r"(a));
}
__device__ __forceinline__ void ldsm_x4t(uint32_t& r0, uint32_t& r1, uint32_t& r2, uint32_t& r3, uint32_t a) {
    asm volatile("ldmatrix.sync.aligned.m8n8.x4.trans.shared.b16 {%0,%1,%2,%3}, [%4];"
                 : "=r"(r0), "=r"(r1), "=r"(r2), "=r"(r3) : "r"(a));
}
__device__ __forceinline__ void mma16816(float* d, uint32_t a0, uint32_t a1, uint32_t a2, uint32_t a3,
                                         uint32_t b0, uint32_t b1) {
    asm volatile("mma.sync.aligned.m16n8k16.row.col.f32.f16.f16.f32 "
                 "{%0,%1,%2,%3}, {%4,%5,%6,%7}, {%8,%9}, {%0,%1,%2,%3};"
                 : "+f"(d[0]), "+f"(d[1]), "+f"(d[2]), "+f"(d[3])
                 : "r"(a0), "r"(a1), "r"(a2), "r"(a3), "r"(b0), "r"(b1));
}

// ---------------- weight conversion to fp16 ----------------------------------
__global__ void k_cvt(const float* __restrict__ Wqkv, const float* __restrict__ W1,
                      const float* __restrict__ W2) {
    int i = blockIdx.x * 256 + threadIdx.x;
    if (i < 64 * 128) {
        int k = i >> 7, c = i & 127;
        g_wkvh[i] = __float2half(Wqkv[k * 192 + 64 + c]);
    }
    if (i < 64 * FF_) {
        g_w1h[i] = __float2half(W1[i]);
        g_w2h[i] = __float2half(W2[i]);
    }
}

// ---------------- count (fused with edge-weight sum) -------------------------
__global__ void k_count(const int* __restrict__ ei, const float* __restrict__ ew) {
    int e = blockIdx.x * blockDim.x + threadIdx.x;
    if (e >= ET_) return;
    int d;
    if (e < E_) {
        d = ei[E_ + e];
        atomicAdd(&g_ewsum, (unsigned long long)((double)ew[e] * 4294967296.0));
    } else {
        d = e - E_;
    }
    atomicAdd(&g_deg[d], 1);
}

// ---------------- scan (+ edge consts, self-zero deg & ewsum) ----------------
__global__ void k_scan(const float* __restrict__ W_edge,
                       const float* __restrict__ att_edge) {
    __shared__ int ws[32];
    int t = threadIdx.x;
    int i0 = 2 * t, i1 = 2 * t + 1;
    int a = (i0 < N_) ? g_deg[i0] : 0;
    int b = (i1 < N_) ? g_deg[i1] : 0;
    int v = a + b;
    int lane = t & 31, wid = t >> 5;
#pragma unroll
    for (int off = 1; off < 32; off <<= 1) {
        int n = __shfl_up_sync(0xffffffffu, v, off);
        if (lane >= off) v += n;
    }
    if (lane == 31) ws[wid] = v;
    __syncthreads();
    if (t < 32) {
        int u = ws[t];
#pragma unroll
        for (int off = 1; off < 32; off <<= 1) {
            int n = __shfl_up_sync(0xffffffffu, u, off);
            if (t >= off) u += n;
        }
        ws[t] = u;
    }
    __syncthreads();
    int base = (wid > 0) ? ws[wid - 1] : 0;
    int incl = v + base;
    int ex0 = incl - a - b;
    if (i0 <= N_) { g_off[i0] = ex0; if (i0 < N_) g_cur[i0] = ex0; }
    if (i1 <= N_) { g_off[i1] = ex0 + a; if (i1 < N_) g_cur[i1] = ex0 + a; }
    g_deg[i0] = 0; g_deg[i1] = 0;
    if (t < 4) {
        float c = 0.f;
        for (int j = 0; j < 32; j++) c += W_edge[t * 32 + j] * att_edge[t * 32 + j];
        g_prep[t] = c;
    }
    if (t == 4) {
        g_prep[4] = (float)((double)g_ewsum / 4294967296.0 / (double)E_);
        g_ewsum = 0ull;
    }
}

__global__ void k_scatter(const int* __restrict__ ei) {
    int e = blockIdx.x * blockDim.x + threadIdx.x;
    if (e >= ET_) return;
    int d = (e < E_) ? ei[E_ + e] : (e - E_);
    int pos = atomicAdd(&g_cur[d], 1);
    g_csr[pos] = e;
}

// ---------------- h = x @ W_gat (fp16 out); attn scalar terms (fp32) ---------
__global__ void __launch_bounds__(256) k_h(const float* __restrict__ x,
                                           const float* __restrict__ Wg,
                                           const float* __restrict__ as_w,
                                           const float* __restrict__ ad_w) {
    __shared__ float Wgs[16 * 128];
    __shared__ float s_as[128], s_ad[128];
    int tid = threadIdx.x;
    for (int i = tid; i < 2048; i += 256) Wgs[i] = Wg[i];
    for (int i = tid; i < 128; i += 256) { s_as[i] = as_w[i]; s_ad[i] = ad_w[i]; }
    __syncthreads();
    int w = blockIdx.x * 8 + (tid >> 5);
    if (w >= GN_) return;
    int lane = tid & 31;
    const float* xr = x + (size_t)w * 16;
    float xf = (lane < 16) ? xr[lane] : 0.f;
    float4 h4 = make_float4(0.f, 0.f, 0.f, 0.f);
    const float4* Wg4 = (const float4*)Wgs;
#pragma unroll
    for (int f = 0; f < 16; f++) {
        float xv = __shfl_sync(0xffffffffu, xf, f);
        float4 wv = Wg4[f * 32 + lane];
        h4.x += xv * wv.x; h4.y += xv * wv.y; h4.z += xv * wv.z; h4.w += xv * wv.w;
    }
    HCvt c0, c1;
    c0.h2 = __floats2half2_rn(h4.x, h4.y);
    c1.h2 = __floats2half2_rn(h4.z, h4.w);
    *(uint2*)&g_h[(size_t)w * 128 + lane * 4] = make_uint2(c0.u, c1.u);
    float4 a = ((const float4*)s_as)[lane];
    float4 d = ((const float4*)s_ad)[lane];
    float vs = h4.x * a.x + h4.y * a.y + h4.z * a.z + h4.w * a.w;
    float vd = h4.x * d.x + h4.y * d.y + h4.z * d.z + h4.w * d.w;
#pragma unroll
    for (int off = 1; off < 8; off <<= 1) {
        vs += __shfl_xor_sync(0xffffffffu, vs, off);
        vd += __shfl_xor_sync(0xffffffffu, vd, off);
    }
    if ((lane & 7) == 0) {
        g_asrc[w * 4 + (lane >> 3)] = vs;
        g_adst[w * 4 + (lane >> 3)] = vd;
    }
}

// ---------------- GAT aggregate (2-wide pipelined) + head-mean + proj --------
#define FETCH_SW(idx, S, W) \
    if ((idx) < end) { int e_ = g_csr[idx]; \
        if (e_ < E_) { S = ei[e_]; W = ew[e_]; } else { S = e_ - E_; W = ewm_s; } } \
    else { S = 0; W = 0.f; }

__global__ void __launch_bounds__(256) k_agg(const int* __restrict__ ei,
                                             const float* __restrict__ ew,
                                             const float* __restrict__ gbias,
                                             const float* __restrict__ Wp,
                                             const float* __restrict__ bp) {
    __shared__ float Wps[32 * 64];
    __shared__ float bias_s[32];
    __shared__ float bp_s[64];
    __shared__ float ce_s[4];
    __shared__ float ewm_sh;
    int tid = threadIdx.x;
    for (int i = tid; i < 2048; i += 256) Wps[i] = Wp[i];
    if (tid < 32) bias_s[tid] = gbias[tid];
    if (tid < 64) bp_s[tid] = bp[tid];
    if (tid < 4)  ce_s[tid] = g_prep[tid];
    if (tid == 8) ewm_sh = g_prep[4];
    __syncthreads();
    int w = blockIdx.x * 8 + (tid >> 5);
    if (w >= GN_) return;
    float ewm_s = ewm_sh;
    int lane = tid & 31;
    int g = w / N_;
    int dst = w - g * N_;
    int hd = lane >> 3;
    float ad = g_adst[((size_t)g * N_ + dst) * 4 + hd];
    float ce = ce_s[hd];
    float acc0 = 0.f, acc1 = 0.f, acc2 = 0.f, acc3 = 0.f, den = 0.f;
    int beg = g_off[dst], end = g_off[dst + 1];
    const __half* hbase = g_h + (size_t)g * N_ * 128;
    const float* abase = g_asrc + (size_t)g * N_ * 4;
    // 2-wide pipeline: cur pair fully loaded, next pair scalars prefetched
    int s0, s1, ns0, ns1; float w0, w1, nw0, nw1;
    FETCH_SW(beg,     s0, w0);
    FETCH_SW(beg + 1, s1, w1);
    FETCH_SW(beg + 2, ns0, nw0);
    FETCH_SW(beg + 3, ns1, nw1);
    uint2 h0 = *(const uint2*)(hbase + (size_t)s0 * 128 + lane * 4);
    float a0 = abase[s0 * 4 + hd];
    uint2 h1 = *(const uint2*)(hbase + (size_t)s1 * 128 + lane * 4);
    float a1 = abase[s1 * 4 + hd];
    int i = beg;
    for (; i + 1 < end; i += 2) {
        // issue next pair's payload loads (independent, both in flight)
        uint2 nh0 = *(const uint2*)(hbase + (size_t)ns0 * 128 + lane * 4);
        float na0 = abase[ns0 * 4 + hd];
        uint2 nh1 = *(const uint2*)(hbase + (size_t)ns1 * 128 + lane * 4);
        float na1 = abase[ns1 * 4 + hd];
        // compute current pair
        float lg0 = a0 + ad + ce * w0;
        lg0 = (lg0 > 0.f) ? lg0 : 0.2f * lg0;
        float p0 = __expf(lg0);
        float lg1 = a1 + ad + ce * w1;
        lg1 = (lg1 > 0.f) ? lg1 : 0.2f * lg1;
        float p1 = __expf(lg1);
        den += p0 + p1;
        float2 e00 = __half22float2(*(__half2*)&h0.x);
        float2 e01 = __half22float2(*(__half2*)&h0.y);
        float2 e10 = __half22float2(*(__half2*)&h1.x);
        float2 e11 = __half22float2(*(__half2*)&h1.y);
        acc0 += p0 * e00.x + p1 * e10.x;
        acc1 += p0 * e00.y + p1 * e10.y;
        acc2 += p0 * e01.x + p1 * e11.x;
        acc3 += p0 * e01.y + p1 * e11.y;
        // rotate pipeline
        s0 = ns0; w0 = nw0; h0 = nh0; a0 = na0;
        s1 = ns1; w1 = nw1; h1 = nh1; a1 = na1;
        FETCH_SW(i + 4, ns0, nw0);
        FETCH_SW(i + 5, ns1, nw1);
    }
    if (i < end) {
        float lg0 = a0 + ad + ce * w0;
        lg0 = (lg0 > 0.f) ? lg0 : 0.2f * lg0;
        float p0 = __expf(lg0);
        den += p0;
        float2 e00 = __half22float2(*(__half2*)&h0.x);
        float2 e01 = __half22float2(*(__half2*)&h0.y);
        acc0 += p0 * e00.x; acc1 += p0 * e00.y;
        acc2 += p0 * e01.x; acc3 += p0 * e01.y;
    }
    float inv = 1.f / (den + 1e-16f);
    acc0 *= inv; acc1 *= inv; acc2 *= inv; acc3 *= inv;
    acc0 += __shfl_xor_sync(0xffffffffu, acc0, 8);  acc0 += __shfl_xor_sync(0xffffffffu, acc0, 16);
    acc1 += __shfl_xor_sync(0xffffffffu, acc1, 8);  acc1 += __shfl_xor_sync(0xffffffffu, acc1, 16);
    acc2 += __shfl_xor_sync(0xffffffffu, acc2, 8);  acc2 += __shfl_xor_sync(0xffffffffu, acc2, 16);
    acc3 += __shfl_xor_sync(0xffffffffu, acc3, 8);  acc3 += __shfl_xor_sync(0xffffffffu, acc3, 16);
    int cb = (lane & 7) * 4;
    float og0 = acc0 * 0.25f + bias_s[cb + 0];
    float og1 = acc1 * 0.25f + bias_s[cb + 1];
    float og2 = acc2 * 0.25f + bias_s[cb + 2];
    float og3 = acc3 * 0.25f + bias_s[cb + 3];
    int d0 = lane * 2;
    float y0 = bp_s[d0], y1 = bp_s[d0 + 1];
#pragma unroll
    for (int sl = 0; sl < 8; sl++) {
        float v0 = __shfl_sync(0xffffffffu, og0, sl);
        float v1 = __shfl_sync(0xffffffffu, og1, sl);
        float v2 = __shfl_sync(0xffffffffu, og2, sl);
        float v3 = __shfl_sync(0xffffffffu, og3, sl);
        int c = sl * 4;
        float2 w0v = *(const float2*)&Wps[(c + 0) * 64 + d0];
        float2 w1v = *(const float2*)&Wps[(c + 1) * 64 + d0];
        float2 w2v = *(const float2*)&Wps[(c + 2) * 64 + d0];
        float2 w3v = *(const float2*)&Wps[(c + 3) * 64 + d0];
        y0 += v0 * w0v.x + v1 * w1v.x + v2 * w2v.x + v3 * w3v.x;
        y1 += v0 * w0v.y + v1 * w1v.y + v2 * w2v.y + v3 * w3v.y;
    }
    int b = g >> 4;
    int t = g & 15;
    HCvt yo; yo.h2 = __floats2half2_rn(y0, y1);
    *(uint32_t*)&g_y[(((size_t)(b * N_ + dst)) * T_ + t) * D_ + d0] = yo.u;
}

// ---------------- K,V GEMM via HMMA: g_kv = y @ Wkv + b (fp16 out) -----------
#define SA_ 72
#define SB_ 136
__global__ void __launch_bounds__(256) k_qkv_mma(const float* __restrict__ bqkv) {
    __shared__ __half Ah[64 * SA_];
    __shared__ __half Bs[64 * SB_];
    __shared__ float bqs[128];
    int tid = threadIdx.x, wid = tid >> 5, lane = tid & 31;
    int rb = blockIdx.x * 64;
    for (int i = tid; i < 512; i += 256) {
        int r = i >> 3, s = i & 7;
        *(uint4*)&Ah[r * SA_ + s * 8] = *(const uint4*)&g_y[((size_t)(rb + r)) * 64 + s * 8];
    }
    for (int i = tid; i < 64 * 16; i += 256) {
        int r = i >> 4, s = i & 15;
        *(uint4*)&Bs[r * SB_ + s * 8] = *(const uint4*)&g_wkvh[r * 128 + s * 8];
    }
    if (tid < 128) bqs[tid] = bqkv[64 + tid];
    __syncthreads();
    int mi = wid >> 1;
    int nb = (wid & 1) * 64;
    float o[4][2][4];
#pragma unroll
    for (int j = 0; j < 4; j++)
#pragma unroll
        for (int n8 = 0; n8 < 2; n8++)
#pragma unroll
            for (int q = 0; q < 4; q++) o[j][n8][q] = 0.f;
    uint32_t abase = su32(Ah) + ((mi * 16 + (lane & 15)) * SA_ + (lane >> 4) * 8) * 2;
    uint32_t bbase = su32(Bs) + (((lane & 15)) * SB_ + nb + (lane >> 4) * 8) * 2;
#pragma unroll
    for (int k = 0; k < 4; k++) {
        uint32_t a0, a1, a2, a3;
        ldsm_x4(a0, a1, a2, a3, abase + k * 32);
#pragma unroll
        for (int j = 0; j < 4; j++) {
            uint32_t b0, b1, b2, b3;
            ldsm_x4t(b0, b1, b2, b3, bbase + (k * 16 * SB_ + j * 16) * 2);
            mma16816(o[j][0], a0, a1, a2, a3, b0, b1);
            mma16816(o[j][1], a0, a1, a2, a3, b2, b3);
        }
    }
    int r0 = lane >> 2, c0 = (lane & 3) * 2;
#pragma unroll
    for (int j = 0; j < 4; j++)
#pragma unroll
        for (int n8 = 0; n8 < 2; n8++)
#pragma unroll
            for (int hm = 0; hm < 2; hm++) {
                int row = rb + mi * 16 + r0 + hm * 8;
                int col = nb + j * 16 + n8 * 8 + c0;
                HCvt v; v.h2 = __floats2half2_rn(o[j][n8][hm * 2 + 0] + bqs[col],
                                                 o[j][n8][hm * 2 + 1] + bqs[col + 1]);
                *(uint32_t*)&g_kv[(size_t)row * 128 + col] = v.u;
            }
}

// ---------------- Q (in-kernel) + attention + Wo + residual + LN1 ------------
__global__ void __launch_bounds__(256) k_attn2(const float* __restrict__ Wqkv,
                                               const float* __restrict__ bqkv,
                                               const float* __restrict__ Wo,
                                               const float* __restrict__ bo,
                                               const float* __restrict__ ln1g,
                                               const float* __restrict__ ln1b) {
    __shared__ float Wos[64 * 64];
    __shared__ float Wqs[64 * 64];
    __shared__ float bos[64], g1s[64], b1s[64], bqs[64];
    __shared__ float ys[8][64];
    __shared__ float sq[8][64];
    int tid = threadIdx.x;
    for (int i = tid; i < 4096; i += 256) {
        Wos[i] = Wo[i];
        int k = i >> 6, c = i & 63;
        Wqs[i] = Wqkv[k * 192 + c];
    }
    if (tid < 64) { bos[tid] = bo[tid]; g1s[tid] = ln1g[tid]; b1s[tid] = ln1b[tid]; bqs[tid] = bqkv[tid]; }
    __syncthreads();
    int wid = tid >> 5, lane = tid & 31;
    int dcol = lane * 2;
    for (int rr = 0; rr < 2; rr++) {
        int r = blockIdx.x * 16 + wid * 2 + rr;
        __half2 yh = *(const __half2*)&g_y[((size_t)(r * 16 + 15)) * 64 + dcol];
        float2 yv = __half22float2(yh);
        ys[wid][dcol] = yv.x; ys[wid][dcol + 1] = yv.y;
        __syncwarp();
        float q0 = bqs[dcol], q1 = bqs[dcol + 1];
#pragma unroll 16
        for (int j = 0; j < 64; j++) {
            float yj = ys[wid][j];
            float2 wv = *(const float2*)&Wqs[j * 64 + dcol];
            q0 += yj * wv.x; q1 += yj * wv.y;
        }
        sq[wid][dcol] = q0; sq[wid][dcol + 1] = q1;
        __syncwarp();
        int t = lane & 15, grp = lane >> 4;
        const __half* kbase = &g_kv[((size_t)(r * 16 + t)) * 128 + grp * 32];
        const float* qq = &sq[wid][grp * 32];
        uint4 kr0 = *(const uint4*)&kbase[0];
        uint4 kr1 = *(const uint4*)&kbase[8];
        uint4 kr2 = *(const uint4*)&kbase[16];
        uint4 kr3 = *(const uint4*)&kbase[24];
        float s0 = 0.f, s1 = 0.f;
        {
            const uint32_t* kw0 = &kr0.x;
            const uint32_t* kw1 = &kr1.x;
#pragma unroll
            for (int j2 = 0; j2 < 4; j2++) {
                float2 f0 = __half22float2(*(const __half2*)&kw0[j2]);
                float2 f1 = __half22float2(*(const __half2*)&kw1[j2]);
                s0 += qq[j2 * 2 + 0] * f0.x + qq[j2 * 2 + 1] * f0.y;
                s0 += qq[8 + j2 * 2 + 0] * f1.x + qq[8 + j2 * 2 + 1] * f1.y;
            }
            const uint32_t* kw2 = &kr2.x;
            const uint32_t* kw3 = &kr3.x;
#pragma unroll
            for (int j2 = 0; j2 < 4; j2++) {
                float2 f2 = __half22float2(*(const __half2*)&kw2[j2]);
                float2 f3 = __half22float2(*(const __half2*)&kw3[j2]);
                s1 += qq[16 + j2 * 2 + 0] * f2.x + qq[16 + j2 * 2 + 1] * f2.y;
                s1 += qq[24 + j2 * 2 + 0] * f3.x + qq[24 + j2 * 2 + 1] * f3.y;
            }
        }
        s0 *= 0.25f; s1 *= 0.25f;
        float m0 = s0, m1 = s1;
#pragma unroll
        for (int off = 1; off < 16; off <<= 1) {
            m0 = fmaxf(m0, __shfl_xor_sync(0xffffffffu, m0, off));
            m1 = fmaxf(m1, __shfl_xor_sync(0xffffffffu, m1, off));
        }
        float p0 = __expf(s0 - m0), p1 = __expf(s1 - m1);
        float dn0 = p0, dn1 = p1;
#pragma unroll
        for (int off = 1; off < 16; off <<= 1) {
            dn0 += __shfl_xor_sync(0xffffffffu, dn0, off);
            dn1 += __shfl_xor_sync(0xffffffffu, dn1, off);
        }
        p0 /= dn0; p1 /= dn1;
        int hd = lane >> 3;
        int srcbase = (hd >> 1) * 16;
        int sel = hd & 1;
        float c0 = 0.f, c1 = 0.f;
#pragma unroll
        for (int tt = 0; tt < 16; tt++) {
            float pa = __shfl_sync(0xffffffffu, p0, srcbase + tt);
            float pb = __shfl_sync(0xffffffffu, p1, srcbase + tt);
            float pv = sel ? pb : pa;
            __half2 v2h = *(const __half2*)&g_kv[((size_t)(r * 16 + tt)) * 128 + 64 + dcol];
            float2 v2 = __half22float2(v2h);
            c0 += pv * v2.x; c1 += pv * v2.y;
        }
        float o0 = bos[dcol], o1 = bos[dcol + 1];
#pragma unroll
        for (int jj = 0; jj < 32; jj++) {
            float ca = __shfl_sync(0xffffffffu, c0, jj);
            float cb = __shfl_sync(0xffffffffu, c1, jj);
            float2 wA = *(const float2*)&Wos[(2 * jj) * 64 + dcol];
            float2 wB = *(const float2*)&Wos[(2 * jj + 1) * 64 + dcol];
            o0 += ca * wA.x + cb * wB.x;
            o1 += ca * wA.y + cb * wB.y;
        }
        float r0v = ys[wid][dcol] + o0, r1v = ys[wid][dcol + 1] + o1;
        float su = r0v + r1v, s2 = r0v * r0v + r1v * r1v;
#pragma unroll
        for (int off = 1; off < 32; off <<= 1) {
            su += __shfl_xor_sync(0xffffffffu, su, off);
            s2 += __shfl_xor_sync(0xffffffffu, s2, off);
        }
        float mu = su * (1.f / 64.f);
        float var = s2 * (1.f / 64.f) - mu * mu;
        float inv = rsqrtf(var + 1e-5f);
        float2 z;
        z.x = (r0v - mu) * inv * g1s[dcol] + b1s[dcol];
        z.y = (r1v - mu) * inv * g1s[dcol + 1] + b1s[dcol + 1];
        *(float2*)&g_z[(size_t)r * 64 + dcol] = z;
    }
}

// ---------------- fused FFN: out = LN2(z + relu(z@W1+b1)@W2 + b2) ------------
__global__ void __launch_bounds__(256) k_ffn(const float* __restrict__ b1,
                                             const float* __restrict__ b2,
                                             const float* __restrict__ ln2g,
                                             const float* __restrict__ ln2b,
                                             float* __restrict__ out) {
    __shared__ __half Ah[32 * SA_];
    __shared__ __half Sh[32 * SA_];
    __shared__ __half W1s[64 * SA_];
    __shared__ __half W2s[64 * SA_];
    __shared__ float OUTf[32 * 64];
    __shared__ float b1s[FF_];
    int tid = threadIdx.x, wid = tid >> 5, lane = tid & 31;
    int rb = blockIdx.x * 32;
    for (int i = tid; i < 32 * 16; i += 256) {
        int r = i >> 4, s4 = i & 15;
        float4 v = *(const float4*)&g_z[((size_t)(rb + r)) * 64 + s4 * 4];
        HCvt h0, h1;
        h0.h2 = __floats2half2_rn(v.x, v.y);
        h1.h2 = __floats2half2_rn(v.z, v.w);
        *(uint2*)&Ah[r * SA_ + s4 * 4] = make_uint2(h0.u, h1.u);
    }
    for (int i = tid; i < FF_; i += 256) b1s[i] = b1[i];
    int mi = wid & 1, ni = wid >> 1;
    float o[2][4];
#pragma unroll
    for (int n8 = 0; n8 < 2; n8++)
#pragma unroll
        for (int q = 0; q < 4; q++) o[n8][q] = 0.f;
    int r0 = lane >> 2, c0 = (lane & 3) * 2;
    uint32_t a1base = su32(Ah) + ((mi * 16 + (lane & 15)) * SA_ + (lane >> 4) * 8) * 2;
    uint32_t a2base = su32(Sh) + ((mi * 16 + (lane & 15)) * SA_ + (lane >> 4) * 8) * 2;
    uint32_t w1base = su32(W1s) + (((lane & 15)) * SA_ + ni * 16 + (lane >> 4) * 8) * 2;
    uint32_t w2base = su32(W2s) + (((lane & 15)) * SA_ + ni * 16 + (lane >> 4) * 8) * 2;
    for (int cb = 0; cb < FF_; cb += 64) {
        __syncthreads();
        for (int i = tid; i < 512; i += 256) {
            int r = i >> 3, s = i & 7;
            *(uint4*)&W1s[r * SA_ + s * 8] = *(const uint4*)&g_w1h[(size_t)r * FF_ + cb + s * 8];
            *(uint4*)&W2s[r * SA_ + s * 8] = *(const uint4*)&g_w2h[(size_t)(cb + r) * 64 + s * 8];
        }
        __syncthreads();
        float d[2][4];
#pragma unroll
        for (int n8 = 0; n8 < 2; n8++)
#pragma unroll
            for (int q = 0; q < 4; q++) d[n8][q] = 0.f;
#pragma unroll
        for (int k = 0; k < 4; k++) {
            uint32_t a0, a1, a2, a3, b0v, b1v, b2v, b3v;
            ldsm_x4(a0, a1, a2, a3, a1base + k * 32);
            ldsm_x4t(b0v, b1v, b2v, b3v, w1base + k * 16 * SA_ * 2);
            mma16816(d[0], a0, a1, a2, a3, b0v, b1v);
            mma16816(d[1], a0, a1, a2, a3, b2v, b3v);
        }
#pragma unroll
        for (int n8 = 0; n8 < 2; n8++) {
            int col = ni * 16 + n8 * 8 + c0;
            float bb0 = b1s[cb + col], bb1 = b1s[cb + col + 1];
            HCvt v0, v1;
            v0.h2 = __floats2half2_rn(fmaxf(d[n8][0] + bb0, 0.f), fmaxf(d[n8][1] + bb1, 0.f));
            v1.h2 = __floats2half2_rn(fmaxf(d[n8][2] + bb0, 0.f), fmaxf(d[n8][3] + bb1, 0.f));
            *(uint32_t*)&Sh[(mi * 16 + r0) * SA_ + col] = v0.u;
            *(uint32_t*)&Sh[(mi * 16 + r0 + 8) * SA_ + col] = v1.u;
        }
        __syncthreads();
#pragma unroll
        for (int k = 0; k < 4; k++) {
            uint32_t a0, a1, a2, a3, b0v, b1v, b2v, b3v;
            ldsm_x4(a0, a1, a2, a3, a2base + k * 32);
            ldsm_x4t(b0v, b1v, b2v, b3v, w2base + k * 16 * SA_ * 2);
            mma16816(o[0], a0, a1, a2, a3, b0v, b1v);
            mma16816(o[1], a0, a1, a2, a3, b2v, b3v);
        }
    }
    __syncthreads();
#pragma unroll
    for (int n8 = 0; n8 < 2; n8++) {
        int col = ni * 16 + n8 * 8 + c0;
        *(float2*)&OUTf[(mi * 16 + r0) * 64 + col] = make_float2(o[n8][0], o[n8][1]);
        *(float2*)&OUTf[(mi * 16 + r0 + 8) * 64 + col] = make_float2(o[n8][2], o[n8][3]);
    }
    __syncthreads();
    int d2 = lane * 2;
    for (int rr = wid; rr < 32; rr += 8) {
        int r = rb + rr;
        float2 zr = *(const float2*)&g_z[(size_t)r * 64 + d2];
        float2 ov = *(const float2*)&OUTf[rr * 64 + d2];
        float v0 = zr.x + ov.x + b2[d2];
        float v1 = zr.y + ov.y + b2[d2 + 1];
        float su = v0 + v1, s2 = v0 * v0 + v1 * v1;
#pragma unroll
        for (int off = 1; off < 32; off <<= 1) {
            su += __shfl_xor_sync(0xffffffffu, su, off);
            s2 += __shfl_xor_sync(0xffffffffu, s2, off);
        }
        float mu = su * (1.f / 64.f);
        float var = s2 * (1.f / 64.f) - mu * mu;
        float inv = rsqrtf(var + 1e-5f);
        float2 oo;
        oo.x = (v0 - mu) * inv * ln2g[d2] + ln2b[d2];
        oo.y = (v1 - mu) * inv * ln2g[d2 + 1] + ln2b[d2 + 1];
        *(float2*)&out[(size_t)r * 64 + d2] = oo;
    }
}

// ---------------- launch (graph-parallel branches via fork-join) -------------
extern "C" void kernel_launch(void* const* d_in, const int* in_sizes, int n_in,
                              void* d_out, int out_size) {
    const float* x_seq    = (const float*)d_in[0];
    const int*   eidx     = (const int*)d_in[1];
    const float* eweight  = (const float*)d_in[2];
    const float* W_gat    = (const float*)d_in[3];
    const float* att_src  = (const float*)d_in[4];
    const float* att_dst  = (const float*)d_in[5];
    const float* W_edge   = (const float*)d_in[6];
    const float* att_edge = (const float*)d_in[7];
    const float* gat_bias = (const float*)d_in[8];
    const float* W_proj   = (const float*)d_in[9];
    const float* b_proj   = (const float*)d_in[10];
    const float* Wqkv     = (const float*)d_in[11];
    const float* bqkv     = (const float*)d_in[12];
    const float* Wo       = (const float*)d_in[13];
    const float* bo       = (const float*)d_in[14];
    const float* ln1_g    = (const float*)d_in[15];
    const float* ln1_b    = (const float*)d_in[16];
    const float* W1       = (const float*)d_in[17];
    const float* b1       = (const float*)d_in[18];
    const float* W2       = (const float*)d_in[19];
    const float* b2       = (const float*)d_in[20];
    const float* ln2_g    = (const float*)d_in[21];
    const float* ln2_b    = (const float*)d_in[22];
    float* out = (float*)d_out;

    static cudaStream_t sB = nullptr, sC = nullptr;
    static cudaEvent_t evRoot = nullptr, evB = nullptr, evC = nullptr;
    if (sB == nullptr) {
        cudaStreamCreateWithFlags(&sB, cudaStreamNonBlocking);
        cudaStreamCreateWithFlags(&sC, cudaStreamNonBlocking);
        cudaEventCreateWithFlags(&evRoot, cudaEventDisableTiming);
        cudaEventCreateWithFlags(&evB, cudaEventDisableTiming);
        cudaEventCreateWithFlags(&evC, cudaEventDisableTiming);
    }

    // fork side branches off the main (captured) stream
    cudaEventRecord(evRoot, 0);
    cudaStreamWaitEvent(sB, evRoot, 0);
    cudaStreamWaitEvent(sC, evRoot, 0);

    // branch B: CSR build (feeds k_agg)
    k_count<<<(ET_ + 255) / 256, 256, 0, sB>>>(eidx, eweight);
    k_scan<<<1, 1024, 0, sB>>>(W_edge, att_edge);
    k_scatter<<<(ET_ + 255) / 256, 256, 0, sB>>>(eidx);
    cudaEventRecord(evB, sB);

    // branch C: fp16 weight conversion (feeds k_qkv_mma / k_ffn)
    k_cvt<<<512, 256, 0, sC>>>(Wqkv, W1, W2);
    cudaEventRecord(evC, sC);

    // main branch: node features
    k_h<<<GN_ / 8, 256>>>(x_seq, W_gat, att_src, att_dst);

    // join B, then aggregate
    cudaStreamWaitEvent(0, evB, 0);
    k_agg<<<GN_ / 8, 256>>>(eidx, eweight, gat_bias, W_proj, b_proj);

    // join C, then transformer
    cudaStreamWaitEvent(0, evC, 0);
    k_qkv_mma<<<GN_ / 64, 256>>>(bqkv);
    k_attn2<<<BN_ / 16, 256>>>(Wqkv, bqkv, Wo, bo, ln1_g, ln1_b);
    k_ffn<<<BN_ / 32, 256>>>(b1, b2, ln2_g, ln2_b, out);
}

// round 9
// speedup vs baseline: 1.9478x; 1.1726x over previous
#include <cuda_runtime.h>
#include <cuda_fp16.h>
#include <cstdint>

#define B_ 2
#define T_ 16
#define N_ 2000
#define F_ 16
#define E_ 32000
#define H_ 4
#define C_ 32
#define D_ 64
#define FF_ 2048
#define G_ (B_*T_)      /* 32  */
#define ET_ (E_+N_)     /* 34000 */
#define BN_ (B_*N_)     /* 4000 */
#define GN_ (G_*N_)     /* 64000 */

// ---------------- scratch (static device globals; no allocation) -------------
__device__ __half g_h[(size_t)GN_ * 128];  // h: [G,N,H*C] fp16
__device__ float g_asrc[GN_ * 4];
__device__ float g_adst[GN_ * 4];
__device__ float g_prep[8];               // c_edge[0..3], ew_mean at [4]
__device__ unsigned long long g_ewsum;    // fixed-point sum of edge weights
__device__ int   g_deg[2048];
__device__ int   g_off[N_ + 1];
__device__ int   g_cur[N_];
__device__ int   g_csr[ET_];
__device__ __half g_y[GN_ * D_];          // fp16 [bn][t][d]  (row rn = bn*16+t)
__device__ __half g_kv[(size_t)GN_ * 128];// fp16 [rn][0:64)=K, [64:128)=V
__device__ float g_z[BN_ * D_];           // post-LN1
__device__ __half g_wkvh[64 * 128];       // fp16 Wqkv[:,64:192]
__device__ __half g_wqh[64 * 64];         // fp16 Wqkv[:,0:64]
__device__ __half g_woh[64 * 64];         // fp16 Wo
__device__ __half g_w1h[64 * FF_];        // fp16 W1
__device__ __half g_w2h[FF_ * 64];        // fp16 W2
__device__ float g_acc[2][BN_ * D_];      // ffn split-K planes
__device__ int   g_cnt[BN_ / 32];         // per-row-block completion counters

union HCvt { __half2 h2; uint32_t u; };

// ---------------- mma helpers ------------------------------------------------
__device__ __forceinline__ uint32_t su32(const void* p) {
    uint32_t a;
    asm("{ .reg .u64 t; cvta.to.shared.u64 t, %1; cvt.u32.u64 %0, t; }" : "=r"(a) : "l"(p));
    return a;
}
__device__ __forceinline__ void ldsm_x4(uint32_t& r0, uint32_t& r1, uint32_t& r2, uint32_t& r3, uint32_t a) {
    asm volatile("ldmatrix.sync.aligned.m8n8.x4.shared.b16 {%0,%1,%2,%3}, [%4];"
                 : "=r"(r0), "=r"(r1), "=r"(r2), "=r"(r3) : "r"(a));
}
__device__ __forceinline__ void ldsm_x4t(uint32_t& r0, uint32_t& r1, uint32_t& r2, uint32_t& r3, uint32_t a) {
    asm volatile("ldmatrix.sync.aligned.m8n8.x4.trans.shared.b16 {%0,%1,%2,%3}, [%4];"
                 : "=r"(r0), "=r"(r1), "=r"(r2), "=r"(r3) : "r"(a));
}
__device__ __forceinline__ void mma16816(float* d, uint32_t a0, uint32_t a1, uint32_t a2, uint32_t a3,
                                         uint32_t b0, uint32_t b1) {
    asm volatile("mma.sync.aligned.m16n8k16.row.col.f32.f16.f16.f32 "
                 "{%0,%1,%2,%3}, {%4,%5,%6,%7}, {%8,%9}, {%0,%1,%2,%3};"
                 : "+f"(d[0]), "+f"(d[1]), "+f"(d[2]), "+f"(d[3])
                 : "r"(a0), "r"(a1), "r"(a2), "r"(a3), "r"(b0), "r"(b1));
}

// ---------------- weight conversion to fp16 ----------------------------------
__global__ void k_cvt(const float* __restrict__ Wqkv, const float* __restrict__ W1,
                      const float* __restrict__ W2, const float* __restrict__ Wo) {
    int i = blockIdx.x * 256 + threadIdx.x;
    if (i < 64 * 128) {
        int k = i >> 7, c = i & 127;
        g_wkvh[i] = __float2half(Wqkv[k * 192 + 64 + c]);
    }
    if (i < 64 * 64) {
        int k = i >> 6, c = i & 63;
        g_wqh[i] = __float2half(Wqkv[k * 192 + c]);
        g_woh[i] = __float2half(Wo[i]);
    }
    if (i < 64 * FF_) {
        g_w1h[i] = __float2half(W1[i]);
        g_w2h[i] = __float2half(W2[i]);
    }
}

// ---------------- count (fused with edge-weight sum) -------------------------
__global__ void k_count(const int* __restrict__ ei, const float* __restrict__ ew) {
    int e = blockIdx.x * blockDim.x + threadIdx.x;
    if (e >= ET_) return;
    int d;
    if (e < E_) {
        d = ei[E_ + e];
        atomicAdd(&g_ewsum, (unsigned long long)((double)ew[e] * 4294967296.0));
    } else {
        d = e - E_;
    }
    atomicAdd(&g_deg[d], 1);
}

// ---------------- scan (+ edge consts, self-zero deg & ewsum) ----------------
__global__ void k_scan(const float* __restrict__ W_edge,
                       const float* __restrict__ att_edge) {
    __shared__ int ws[32];
    int t = threadIdx.x;
    int i0 = 2 * t, i1 = 2 * t + 1;
    int a = (i0 < N_) ? g_deg[i0] : 0;
    int b = (i1 < N_) ? g_deg[i1] : 0;
    int v = a + b;
    int lane = t & 31, wid = t >> 5;
#pragma unroll
    for (int off = 1; off < 32; off <<= 1) {
        int n = __shfl_up_sync(0xffffffffu, v, off);
        if (lane >= off) v += n;
    }
    if (lane == 31) ws[wid] = v;
    __syncthreads();
    if (t < 32) {
        int u = ws[t];
#pragma unroll
        for (int off = 1; off < 32; off <<= 1) {
            int n = __shfl_up_sync(0xffffffffu, u, off);
            if (t >= off) u += n;
        }
        ws[t] = u;
    }
    __syncthreads();
    int base = (wid > 0) ? ws[wid - 1] : 0;
    int incl = v + base;
    int ex0 = incl - a - b;
    if (i0 <= N_) { g_off[i0] = ex0; if (i0 < N_) g_cur[i0] = ex0; }
    if (i1 <= N_) { g_off[i1] = ex0 + a; if (i1 < N_) g_cur[i1] = ex0 + a; }
    g_deg[i0] = 0; g_deg[i1] = 0;
    if (t < 4) {
        float c = 0.f;
        for (int j = 0; j < 32; j++) c += W_edge[t * 32 + j] * att_edge[t * 32 + j];
        g_prep[t] = c;
    }
    if (t == 4) {
        g_prep[4] = (float)((double)g_ewsum / 4294967296.0 / (double)E_);
        g_ewsum = 0ull;
    }
}

__global__ void k_scatter(const int* __restrict__ ei) {
    int e = blockIdx.x * blockDim.x + threadIdx.x;
    if (e >= ET_) return;
    int d = (e < E_) ? ei[E_ + e] : (e - E_);
    int pos = atomicAdd(&g_cur[d], 1);
    g_csr[pos] = e;
}

// ---------------- h = x @ W_gat (fp16 out); attn scalar terms (fp32) ---------
__global__ void __launch_bounds__(256) k_h(const float* __restrict__ x,
                                           const float* __restrict__ Wg,
                                           const float* __restrict__ as_w,
                                           const float* __restrict__ ad_w) {
    __shared__ float Wgs[16 * 128];
    __shared__ float s_as[128], s_ad[128];
    int tid = threadIdx.x;
    for (int i = tid; i < 2048; i += 256) Wgs[i] = Wg[i];
    for (int i = tid; i < 128; i += 256) { s_as[i] = as_w[i]; s_ad[i] = ad_w[i]; }
    __syncthreads();
    int w = blockIdx.x * 8 + (tid >> 5);
    if (w >= GN_) return;
    int lane = tid & 31;
    const float* xr = x + (size_t)w * 16;
    float xf = (lane < 16) ? xr[lane] : 0.f;
    float4 h4 = make_float4(0.f, 0.f, 0.f, 0.f);
    const float4* Wg4 = (const float4*)Wgs;
#pragma unroll
    for (int f = 0; f < 16; f++) {
        float xv = __shfl_sync(0xffffffffu, xf, f);
        float4 wv = Wg4[f * 32 + lane];
        h4.x += xv * wv.x; h4.y += xv * wv.y; h4.z += xv * wv.z; h4.w += xv * wv.w;
    }
    HCvt c0, c1;
    c0.h2 = __floats2half2_rn(h4.x, h4.y);
    c1.h2 = __floats2half2_rn(h4.z, h4.w);
    *(uint2*)&g_h[(size_t)w * 128 + lane * 4] = make_uint2(c0.u, c1.u);
    float4 a = ((const float4*)s_as)[lane];
    float4 d = ((const float4*)s_ad)[lane];
    float vs = h4.x * a.x + h4.y * a.y + h4.z * a.z + h4.w * a.w;
    float vd = h4.x * d.x + h4.y * d.y + h4.z * d.z + h4.w * d.w;
#pragma unroll
    for (int off = 1; off < 8; off <<= 1) {
        vs += __shfl_xor_sync(0xffffffffu, vs, off);
        vd += __shfl_xor_sync(0xffffffffu, vd, off);
    }
    if ((lane & 7) == 0) {
        g_asrc[w * 4 + (lane >> 3)] = vs;
        g_adst[w * 4 + (lane >> 3)] = vd;
    }
}

// ---------------- GAT aggregate v2: two edges/warp, 8 ch/lane ----------------
__global__ void __launch_bounds__(256) k_agg(const int* __restrict__ ei,
                                             const float* __restrict__ ew,
                                             const float* __restrict__ gbias,
                                             const float* __restrict__ Wp,
                                             const float* __restrict__ bp) {
    __shared__ float Wps[32 * 64];
    __shared__ float bias_s[32];
    __shared__ float bp_s[64];
    __shared__ float ce_s[4];
    __shared__ float ewm_sh;
    __shared__ float sog[8][32];
    int tid = threadIdx.x;
    for (int i = tid; i < 2048; i += 256) Wps[i] = Wp[i];
    if (tid < 32) bias_s[tid] = gbias[tid];
    if (tid < 64) bp_s[tid] = bp[tid];
    if (tid < 4)  ce_s[tid] = g_prep[tid];
    if (tid == 8) ewm_sh = g_prep[4];
    __syncthreads();
    int w = blockIdx.x * 8 + (tid >> 5);
    int wid = tid >> 5;
    float ewm_s = ewm_sh;
    int lane = tid & 31;
    int hf = lane >> 4;          // edge parity (0: even edges, 1: odd edges)
    int ll = lane & 15;          // channel-group within edge: ch = ll*8..ll*8+7
    int hd = ll >> 2;            // head of this lane's channels
    int g = w / N_;
    int dst = w - g * N_;
    float ad = g_adst[((size_t)g * N_ + dst) * 4 + hd];
    float ce = ce_s[hd];
    float acc[8];
#pragma unroll
    for (int j = 0; j < 8; j++) acc[j] = 0.f;
    float den = 0.f;
    int beg = g_off[dst], end = g_off[dst + 1];
    const __half* hbase = g_h + (size_t)g * N_ * 128;
    const float* abase = g_asrc + (size_t)g * N_ * 4;
    int i = beg + hf;
    bool v = (i < end);
    int e0 = v ? g_csr[i] : 0;
    int s; float wgt;
    if (e0 < E_) { s = ei[e0]; wgt = ew[e0]; } else { s = e0 - E_; wgt = ewm_s; }
    float as = abase[s * 4 + hd];
    uint4 hr = *(const uint4*)(hbase + (size_t)s * 128 + ll * 8);
    int cnt = (end - beg + 1) >> 1;
    for (int it = 0; it < cnt; it++) {
        int in_ = i + 2;
        bool vn = (in_ < end);
        int en = vn ? g_csr[in_] : 0;
        int sn; float wn;
        if (en < E_) { sn = ei[en]; wn = ew[en]; } else { sn = en - E_; wn = ewm_s; }
        float asn = abase[sn * 4 + hd];
        uint4 hrn = *(const uint4*)(hbase + (size_t)sn * 128 + ll * 8);
        float lg = as + ad + ce * wgt;
        lg = (lg > 0.f) ? lg : 0.2f * lg;
        float p = v ? __expf(lg) : 0.f;
        den += p;
        const uint32_t* hw = &hr.x;
#pragma unroll
        for (int j2 = 0; j2 < 4; j2++) {
            float2 f = __half22float2(*(const __half2*)&hw[j2]);
            acc[j2 * 2 + 0] += p * f.x;
            acc[j2 * 2 + 1] += p * f.y;
        }
        i = in_; v = vn; s = sn; wgt = wn; as = asn; hr = hrn;
    }
    // combine halves (same channels, opposite edge parity)
    den += __shfl_xor_sync(0xffffffffu, den, 16);
    float inv = 1.f / (den + 1e-16f);
#pragma unroll
    for (int j = 0; j < 8; j++) {
        acc[j] += __shfl_xor_sync(0xffffffffu, acc[j], 16);
        acc[j] *= inv;                               // per-head normalize
        acc[j] += __shfl_xor_sync(0xffffffffu, acc[j], 4);   // sum heads
        acc[j] += __shfl_xor_sync(0xffffffffu, acc[j], 8);
        acc[j] = acc[j] * 0.25f + bias_s[(ll & 3) * 8 + j];  // mean + bias
    }
    if (lane < 4) {
#pragma unroll
        for (int j = 0; j < 8; j++) sog[wid][lane * 8 + j] = acc[j];
    }
    __syncwarp();
    int d0 = lane * 2;
    float y0 = bp_s[d0], y1 = bp_s[d0 + 1];
#pragma unroll
    for (int c = 0; c < 32; c++) {
        float vv = sog[wid][c];
        float2 wv = *(const float2*)&Wps[c * 64 + d0];
        y0 += vv * wv.x; y1 += vv * wv.y;
    }
    int b = g >> 4;
    int t = g & 15;
    HCvt yo; yo.h2 = __floats2half2_rn(y0, y1);
    *(uint32_t*)&g_y[(((size_t)(b * N_ + dst)) * T_ + t) * D_ + d0] = yo.u;
}

// ---------------- K,V GEMM via HMMA: g_kv = y @ Wkv + b (fp16 out) -----------
#define SA_ 72
#define SB_ 136
__global__ void __launch_bounds__(256) k_qkv_mma(const float* __restrict__ bqkv) {
    __shared__ __half Ah[64 * SA_];
    __shared__ __half Bs[64 * SB_];
    __shared__ float bqs[128];
    int tid = threadIdx.x, wid = tid >> 5, lane = tid & 31;
    int rb = blockIdx.x * 64;
    for (int i = tid; i < 512; i += 256) {
        int r = i >> 3, s = i & 7;
        *(uint4*)&Ah[r * SA_ + s * 8] = *(const uint4*)&g_y[((size_t)(rb + r)) * 64 + s * 8];
    }
    for (int i = tid; i < 64 * 16; i += 256) {
        int r = i >> 4, s = i & 15;
        *(uint4*)&Bs[r * SB_ + s * 8] = *(const uint4*)&g_wkvh[r * 128 + s * 8];
    }
    if (tid < 128) bqs[tid] = bqkv[64 + tid];
    __syncthreads();
    int mi = wid >> 1;
    int nb = (wid & 1) * 64;
    float o[4][2][4];
#pragma unroll
    for (int j = 0; j < 4; j++)
#pragma unroll
        for (int n8 = 0; n8 < 2; n8++)
#pragma unroll
            for (int q = 0; q < 4; q++) o[j][n8][q] = 0.f;
    uint32_t abase = su32(Ah) + ((mi * 16 + (lane & 15)) * SA_ + (lane >> 4) * 8) * 2;
    uint32_t bbase = su32(Bs) + (((lane & 15)) * SB_ + nb + (lane >> 4) * 8) * 2;
#pragma unroll
    for (int k = 0; k < 4; k++) {
        uint32_t a0, a1, a2, a3;
        ldsm_x4(a0, a1, a2, a3, abase + k * 32);
#pragma unroll
        for (int j = 0; j < 4; j++) {
            uint32_t b0, b1, b2, b3;
            ldsm_x4t(b0, b1, b2, b3, bbase + (k * 16 * SB_ + j * 16) * 2);
            mma16816(o[j][0], a0, a1, a2, a3, b0, b1);
            mma16816(o[j][1], a0, a1, a2, a3, b2, b3);
        }
    }
    int r0 = lane >> 2, c0 = (lane & 3) * 2;
#pragma unroll
    for (int j = 0; j < 4; j++)
#pragma unroll
        for (int n8 = 0; n8 < 2; n8++)
#pragma unroll
            for (int hm = 0; hm < 2; hm++) {
                int row = rb + mi * 16 + r0 + hm * 8;
                int col = nb + j * 16 + n8 * 8 + c0;
                HCvt v; v.h2 = __floats2half2_rn(o[j][n8][hm * 2 + 0] + bqs[col],
                                                 o[j][n8][hm * 2 + 1] + bqs[col + 1]);
                *(uint32_t*)&g_kv[(size_t)row * 128 + col] = v.u;
            }
}

// ---------------- Q (in-kernel) + attention + Wo + residual + LN1 ------------
__global__ void __launch_bounds__(256) k_attn2(const float* __restrict__ bqkv,
                                               const float* __restrict__ bo,
                                               const float* __restrict__ ln1g,
                                               const float* __restrict__ ln1b) {
    __shared__ __half2 Wos2[64 * 32];
    __shared__ __half2 Wqs2[64 * 32];
    __shared__ float bos[64], g1s[64], b1s[64], bqs[64];
    __shared__ float ys[8][64];
    __shared__ float sq[8][64];
    int tid = threadIdx.x;
    for (int i = tid; i < 512; i += 256) {
        ((uint4*)Wos2)[i] = ((const uint4*)g_woh)[i];
        ((uint4*)Wqs2)[i] = ((const uint4*)g_wqh)[i];
    }
    if (tid < 64) { bos[tid] = bo[tid]; g1s[tid] = ln1g[tid]; b1s[tid] = ln1b[tid]; bqs[tid] = bqkv[tid]; }
    __syncthreads();
    int wid = tid >> 5, lane = tid & 31;
    int dcol = lane * 2;
    for (int rr = 0; rr < 2; rr++) {
        int r = blockIdx.x * 16 + wid * 2 + rr;
        __half2 yh = *(const __half2*)&g_y[((size_t)(r * 16 + 15)) * 64 + dcol];
        float2 yv = __half22float2(yh);
        ys[wid][dcol] = yv.x; ys[wid][dcol + 1] = yv.y;
        __syncwarp();
        float q0 = bqs[dcol], q1 = bqs[dcol + 1];
#pragma unroll 16
        for (int j = 0; j < 64; j++) {
            float yj = ys[wid][j];
            float2 wv = __half22float2(Wqs2[j * 32 + lane]);
            q0 += yj * wv.x; q1 += yj * wv.y;
        }
        sq[wid][dcol] = q0; sq[wid][dcol + 1] = q1;
        __syncwarp();
        int t = lane & 15, grp = lane >> 4;
        const __half* kbase = &g_kv[((size_t)(r * 16 + t)) * 128 + grp * 32];
        const float* qq = &sq[wid][grp * 32];
        uint4 kr0 = *(const uint4*)&kbase[0];
        uint4 kr1 = *(const uint4*)&kbase[8];
        uint4 kr2 = *(const uint4*)&kbase[16];
        uint4 kr3 = *(const uint4*)&kbase[24];
        float s0 = 0.f, s1 = 0.f;
        {
            const uint32_t* kw0 = &kr0.x;
            const uint32_t* kw1 = &kr1.x;
#pragma unroll
            for (int j2 = 0; j2 < 4; j2++) {
                float2 f0 = __half22float2(*(const __half2*)&kw0[j2]);
                float2 f1 = __half22float2(*(const __half2*)&kw1[j2]);
                s0 += qq[j2 * 2 + 0] * f0.x + qq[j2 * 2 + 1] * f0.y;
                s0 += qq[8 + j2 * 2 + 0] * f1.x + qq[8 + j2 * 2 + 1] * f1.y;
            }
            const uint32_t* kw2 = &kr2.x;
            const uint32_t* kw3 = &kr3.x;
#pragma unroll
            for (int j2 = 0; j2 < 4; j2++) {
                float2 f2 = __half22float2(*(const __half2*)&kw2[j2]);
                float2 f3 = __half22float2(*(const __half2*)&kw3[j2]);
                s1 += qq[16 + j2 * 2 + 0] * f2.x + qq[16 + j2 * 2 + 1] * f2.y;
                s1 += qq[24 + j2 * 2 + 0] * f3.x + qq[24 + j2 * 2 + 1] * f3.y;
            }
        }
        s0 *= 0.25f; s1 *= 0.25f;
        float m0 = s0, m1 = s1;
#pragma unroll
        for (int off = 1; off < 16; off <<= 1) {
            m0 = fmaxf(m0, __shfl_xor_sync(0xffffffffu, m0, off));
            m1 = fmaxf(m1, __shfl_xor_sync(0xffffffffu, m1, off));
        }
        float p0 = __expf(s0 - m0), p1 = __expf(s1 - m1);
        float dn0 = p0, dn1 = p1;
#pragma unroll
        for (int off = 1; off < 16; off <<= 1) {
            dn0 += __shfl_xor_sync(0xffffffffu, dn0, off);
            dn1 += __shfl_xor_sync(0xffffffffu, dn1, off);
        }
        p0 /= dn0; p1 /= dn1;
        int hd = lane >> 3;
        int srcbase = (hd >> 1) * 16;
        int sel = hd & 1;
        float c0 = 0.f, c1 = 0.f;
#pragma unroll
        for (int tt = 0; tt < 16; tt++) {
            float pa = __shfl_sync(0xffffffffu, p0, srcbase + tt);
            float pb = __shfl_sync(0xffffffffu, p1, srcbase + tt);
            float pv = sel ? pb : pa;
            __half2 v2h = *(const __half2*)&g_kv[((size_t)(r * 16 + tt)) * 128 + 64 + dcol];
            float2 v2 = __half22float2(v2h);
            c0 += pv * v2.x; c1 += pv * v2.y;
        }
        float o0 = bos[dcol], o1 = bos[dcol + 1];
#pragma unroll
        for (int jj = 0; jj < 32; jj++) {
            float ca = __shfl_sync(0xffffffffu, c0, jj);
            float cb = __shfl_sync(0xffffffffu, c1, jj);
            float2 wA = __half22float2(Wos2[(2 * jj) * 32 + lane]);
            float2 wB = __half22float2(Wos2[(2 * jj + 1) * 32 + lane]);
            o0 += ca * wA.x + cb * wB.x;
            o1 += ca * wA.y + cb * wB.y;
        }
        float r0v = ys[wid][dcol] + o0, r1v = ys[wid][dcol + 1] + o1;
        float su = r0v + r1v, s2 = r0v * r0v + r1v * r1v;
#pragma unroll
        for (int off = 1; off < 32; off <<= 1) {
            su += __shfl_xor_sync(0xffffffffu, su, off);
            s2 += __shfl_xor_sync(0xffffffffu, s2, off);
        }
        float mu = su * (1.f / 64.f);
        float var = s2 * (1.f / 64.f) - mu * mu;
        float inv = rsqrtf(var + 1e-5f);
        float2 z;
        z.x = (r0v - mu) * inv * g1s[dcol] + b1s[dcol];
        z.y = (r1v - mu) * inv * g1s[dcol + 1] + b1s[dcol + 1];
        *(float2*)&g_z[(size_t)r * 64 + dcol] = z;
    }
}

// ---------------- fused FFN split-K(2) + last-block LN2 epilogue -------------
__global__ void __launch_bounds__(256) k_ffn(const float* __restrict__ b1,
                                             const float* __restrict__ b2,
                                             const float* __restrict__ ln2g,
                                             const float* __restrict__ ln2b,
                                             float* __restrict__ out) {
    __shared__ __half Ah[32 * SA_];
    __shared__ __half Sh[32 * SA_];
    __shared__ __half W1s[64 * SA_];
    __shared__ __half W2s[64 * SA_];
    __shared__ float b1s[1024];
    __shared__ bool last_s;
    int tid = threadIdx.x, wid = tid >> 5, lane = tid & 31;
    int rb = blockIdx.x * 32;
    int kc0 = blockIdx.y * 1024;
    for (int i = tid; i < 32 * 16; i += 256) {
        int r = i >> 4, s4 = i & 15;
        float4 v = *(const float4*)&g_z[((size_t)(rb + r)) * 64 + s4 * 4];
        HCvt h0, h1;
        h0.h2 = __floats2half2_rn(v.x, v.y);
        h1.h2 = __floats2half2_rn(v.z, v.w);
        *(uint2*)&Ah[r * SA_ + s4 * 4] = make_uint2(h0.u, h1.u);
    }
    for (int i = tid; i < 1024; i += 256) b1s[i] = b1[kc0 + i];
    int mi = wid & 1, ni = wid >> 1;
    float o[2][4];
#pragma unroll
    for (int n8 = 0; n8 < 2; n8++)
#pragma unroll
        for (int q = 0; q < 4; q++) o[n8][q] = 0.f;
    int r0 = lane >> 2, c0 = (lane & 3) * 2;
    uint32_t a1base = su32(Ah) + ((mi * 16 + (lane & 15)) * SA_ + (lane >> 4) * 8) * 2;
    uint32_t a2base = su32(Sh) + ((mi * 16 + (lane & 15)) * SA_ + (lane >> 4) * 8) * 2;
    uint32_t w1base = su32(W1s) + (((lane & 15)) * SA_ + ni * 16 + (lane >> 4) * 8) * 2;
    uint32_t w2base = su32(W2s) + (((lane & 15)) * SA_ + ni * 16 + (lane >> 4) * 8) * 2;
    for (int cb = kc0; cb < kc0 + 1024; cb += 64) {
        __syncthreads();
        for (int i = tid; i < 512; i += 256) {
            int r = i >> 3, s = i & 7;
            *(uint4*)&W1s[r * SA_ + s * 8] = *(const uint4*)&g_w1h[(size_t)r * FF_ + cb + s * 8];
            *(uint4*)&W2s[r * SA_ + s * 8] = *(const uint4*)&g_w2h[(size_t)(cb + r) * 64 + s * 8];
        }
        __syncthreads();
        float d[2][4];
#pragma unroll
        for (int n8 = 0; n8 < 2; n8++)
#pragma unroll
            for (int q = 0; q < 4; q++) d[n8][q] = 0.f;
#pragma unroll
        for (int k = 0; k < 4; k++) {
            uint32_t a0, a1, a2, a3, b0v, b1v, b2v, b3v;
            ldsm_x4(a0, a1, a2, a3, a1base + k * 32);
            ldsm_x4t(b0v, b1v, b2v, b3v, w1base + k * 16 * SA_ * 2);
            mma16816(d[0], a0, a1, a2, a3, b0v, b1v);
            mma16816(d[1], a0, a1, a2, a3, b2v, b3v);
        }
#pragma unroll
        for (int n8 = 0; n8 < 2; n8++) {
            int col = ni * 16 + n8 * 8 + c0;
            float bb0 = b1s[cb - kc0 + col], bb1 = b1s[cb - kc0 + col + 1];
            HCvt v0, v1;
            v0.h2 = __floats2half2_rn(fmaxf(d[n8][0] + bb0, 0.f), fmaxf(d[n8][1] + bb1, 0.f));
            v1.h2 = __floats2half2_rn(fmaxf(d[n8][2] + bb0, 0.f), fmaxf(d[n8][3] + bb1, 0.f));
            *(uint32_t*)&Sh[(mi * 16 + r0) * SA_ + col] = v0.u;
            *(uint32_t*)&Sh[(mi * 16 + r0 + 8) * SA_ + col] = v1.u;
        }
        __syncthreads();
#pragma unroll
        for (int k = 0; k < 4; k++) {
            uint32_t a0, a1, a2, a3, b0v, b1v, b2v, b3v;
            ldsm_x4(a0, a1, a2, a3, a2base + k * 32);
            ldsm_x4t(b0v, b1v, b2v, b3v, w2base + k * 16 * SA_ * 2);
            mma16816(o[0], a0, a1, a2, a3, b0v, b1v);
            mma16816(o[1], a0, a1, a2, a3, b2v, b3v);
        }
    }
    float* plane = g_acc[blockIdx.y];
#pragma unroll
    for (int n8 = 0; n8 < 2; n8++) {
        int col = ni * 16 + n8 * 8 + c0;
        *(float2*)&plane[(size_t)(rb + mi * 16 + r0) * 64 + col] = make_float2(o[n8][0], o[n8][1]);
        *(float2*)&plane[(size_t)(rb + mi * 16 + r0 + 8) * 64 + col] = make_float2(o[n8][2], o[n8][3]);
    }
    __threadfence();
    __syncthreads();
    if (tid == 0) {
        int old = atomicAdd(&g_cnt[blockIdx.x], 1);
        last_s = (old == 1);
        if (last_s) g_cnt[blockIdx.x] = 0;
    }
    __syncthreads();
    if (!last_s) return;
    int d2 = lane * 2;
    for (int rr = wid; rr < 32; rr += 8) {
        int r = rb + rr;
        float2 zr = *(const float2*)&g_z[(size_t)r * 64 + d2];
        float2 p0 = *(const float2*)&g_acc[0][(size_t)r * 64 + d2];
        float2 p1 = *(const float2*)&g_acc[1][(size_t)r * 64 + d2];
        float v0 = zr.x + p0.x + p1.x + b2[d2];
        float v1 = zr.y + p0.y + p1.y + b2[d2 + 1];
        float su = v0 + v1, s2 = v0 * v0 + v1 * v1;
#pragma unroll
        for (int off = 1; off < 32; off <<= 1) {
            su += __shfl_xor_sync(0xffffffffu, su, off);
            s2 += __shfl_xor_sync(0xffffffffu, s2, off);
        }
        float mu = su * (1.f / 64.f);
        float var = s2 * (1.f / 64.f) - mu * mu;
        float inv = rsqrtf(var + 1e-5f);
        float2 oo;
        oo.x = (v0 - mu) * inv * ln2g[d2] + ln2b[d2];
        oo.y = (v1 - mu) * inv * ln2g[d2 + 1] + ln2b[d2 + 1];
        *(float2*)&out[(size_t)r * 64 + d2] = oo;
    }
}

// ---------------- launch (graph-parallel branches via fork-join) -------------
extern "C" void kernel_launch(void* const* d_in, const int* in_sizes, int n_in,
                              void* d_out, int out_size) {
    const float* x_seq    = (const float*)d_in[0];
    const int*   eidx     = (const int*)d_in[1];
    const float* eweight  = (const float*)d_in[2];
    const float* W_gat    = (const float*)d_in[3];
    const float* att_src  = (const float*)d_in[4];
    const float* att_dst  = (const float*)d_in[5];
    const float* W_edge   = (const float*)d_in[6];
    const float* att_edge = (const float*)d_in[7];
    const float* gat_bias = (const float*)d_in[8];
    const float* W_proj   = (const float*)d_in[9];
    const float* b_proj   = (const float*)d_in[10];
    const float* Wqkv     = (const float*)d_in[11];
    const float* bqkv     = (const float*)d_in[12];
    const float* Wo       = (const float*)d_in[13];
    const float* bo       = (const float*)d_in[14];
    const float* ln1_g    = (const float*)d_in[15];
    const float* ln1_b    = (const float*)d_in[16];
    const float* W1       = (const float*)d_in[17];
    const float* b1       = (const float*)d_in[18];
    const float* W2       = (const float*)d_in[19];
    const float* b2       = (const float*)d_in[20];
    const float* ln2_g    = (const float*)d_in[21];
    const float* ln2_b    = (const float*)d_in[22];
    float* out = (float*)d_out;

    static cudaStream_t sB = nullptr, sC = nullptr;
    static cudaEvent_t evRoot = nullptr, evB = nullptr, evC = nullptr;
    if (sB == nullptr) {
        cudaStreamCreateWithFlags(&sB, cudaStreamNonBlocking);
        cudaStreamCreateWithFlags(&sC, cudaStreamNonBlocking);
        cudaEventCreateWithFlags(&evRoot, cudaEventDisableTiming);
        cudaEventCreateWithFlags(&evB, cudaEventDisableTiming);
        cudaEventCreateWithFlags(&evC, cudaEventDisableTiming);
    }

    cudaEventRecord(evRoot, 0);
    cudaStreamWaitEvent(sB, evRoot, 0);
    cudaStreamWaitEvent(sC, evRoot, 0);

    // branch B: CSR build (feeds k_agg)
    k_count<<<(ET_ + 255) / 256, 256, 0, sB>>>(eidx, eweight);
    k_scan<<<1, 1024, 0, sB>>>(W_edge, att_edge);
    k_scatter<<<(ET_ + 255) / 256, 256, 0, sB>>>(eidx);
    cudaEventRecord(evB, sB);

    // branch C: fp16 weight conversion
    k_cvt<<<512, 256, 0, sC>>>(Wqkv, W1, W2, Wo);
    cudaEventRecord(evC, sC);

    // main branch: node features
    k_h<<<GN_ / 8, 256>>>(x_seq, W_gat, att_src, att_dst);

    cudaStreamWaitEvent(0, evB, 0);
    k_agg<<<GN_ / 8, 256>>>(eidx, eweight, gat_bias, W_proj, b_proj);

    cudaStreamWaitEvent(0, evC, 0);
    k_qkv_mma<<<GN_ / 64, 256>>>(bqkv);
    k_attn2<<<BN_ / 16, 256>>>(bqkv, bo, ln1_g, ln1_b);
    {
        dim3 grid(BN_ / 32, 2);
        k_ffn<<<grid, 256>>>(b1, b2, ln2_g, ln2_b, out);
    }
}

// round 10
// speedup vs baseline: 2.0625x; 1.0589x over previous
#include <cuda_runtime.h>
#include <cuda_fp16.h>
#include <cstdint>

#define B_ 2
#define T_ 16
#define N_ 2000
#define F_ 16
#define E_ 32000
#define H_ 4
#define C_ 32
#define D_ 64
#define FF_ 2048
#define G_ (B_*T_)      /* 32  */
#define ET_ (E_+N_)     /* 34000 */
#define BN_ (B_*N_)     /* 4000 */
#define GN_ (G_*N_)     /* 64000 */

// ---------------- scratch (static device globals; no allocation) -------------
__device__ __half g_h[(size_t)GN_ * 128];  // h: [G,N,H*C] fp16
__device__ float g_asrc[GN_ * 4];
__device__ float g_adst[GN_ * 4];
__device__ float g_prep[8];               // c_edge[0..3], ew_mean at [4]
__device__ unsigned long long g_ewsum;    // fixed-point sum of edge weights
__device__ int   g_deg[2048];
__device__ int   g_off[N_ + 1];
__device__ int   g_cur[N_];
__device__ int   g_csr[ET_];
__device__ __half g_y[GN_ * D_];          // fp16 [bn][t][d]  (row rn = bn*16+t)
__device__ float g_z[BN_ * D_];           // post-LN1
__device__ __half g_wkvh[64 * 128];       // fp16 Wqkv[:,64:192]
__device__ __half g_wqh[64 * 64];         // fp16 Wqkv[:,0:64]
__device__ __half g_woh[64 * 64];         // fp16 Wo
__device__ __half g_w1h[64 * FF_];        // fp16 W1
__device__ __half g_w2h[FF_ * 64];        // fp16 W2
__device__ float g_acc[2][BN_ * D_];      // ffn split-K planes
__device__ int   g_cnt[BN_ / 32];         // per-row-block completion counters

union HCvt { __half2 h2; uint32_t u; };

// ---------------- mma helpers ------------------------------------------------
__device__ __forceinline__ uint32_t su32(const void* p) {
    uint32_t a;
    asm("{ .reg .u64 t; cvta.to.shared.u64 t, %1; cvt.u32.u64 %0, t; }" : "=r"(a) : "l"(p));
    return a;
}
__device__ __forceinline__ void ldsm_x4(uint32_t& r0, uint32_t& r1, uint32_t& r2, uint32_t& r3, uint32_t a) {
    asm volatile("ldmatrix.sync.aligned.m8n8.x4.shared.b16 {%0,%1,%2,%3}, [%4];"
                 : "=r"(r0), "=r"(r1), "=r"(r2), "=r"(r3) : "r"(a));
}
__device__ __forceinline__ void ldsm_x4t(uint32_t& r0, uint32_t& r1, uint32_t& r2, uint32_t& r3, uint32_t a) {
    asm volatile("ldmatrix.sync.aligned.m8n8.x4.trans.shared.b16 {%0,%1,%2,%3}, [%4];"
                 : "=r"(r0), "=r"(r1), "=r"(r2), "=r"(r3) : "r"(a));
}
__device__ __forceinline__ void mma16816(float* d, uint32_t a0, uint32_t a1, uint32_t a2, uint32_t a3,
                                         uint32_t b0, uint32_t b1) {
    asm volatile("mma.sync.aligned.m16n8k16.row.col.f32.f16.f16.f32 "
                 "{%0,%1,%2,%3}, {%4,%5,%6,%7}, {%8,%9}, {%0,%1,%2,%3};"
                 : "+f"(d[0]), "+f"(d[1]), "+f"(d[2]), "+f"(d[3])
                 : "r"(a0), "r"(a1), "r"(a2), "r"(a3), "r"(b0), "r"(b1));
}

// ---------------- weight conversion to fp16 ----------------------------------
__global__ void k_cvt(const float* __restrict__ Wqkv, const float* __restrict__ W1,
                      const float* __restrict__ W2, const float* __restrict__ Wo) {
    int i = blockIdx.x * 256 + threadIdx.x;
    if (i < 64 * 128) {
        int k = i >> 7, c = i & 127;
        g_wkvh[i] = __float2half(Wqkv[k * 192 + 64 + c]);
    }
    if (i < 64 * 64) {
        int k = i >> 6, c = i & 63;
        g_wqh[i] = __float2half(Wqkv[k * 192 + c]);
        g_woh[i] = __float2half(Wo[i]);
    }
    if (i < 64 * FF_) {
        g_w1h[i] = __float2half(W1[i]);
        g_w2h[i] = __float2half(W2[i]);
    }
}

// ---------------- count (fused with edge-weight sum) -------------------------
__global__ void k_count(const int* __restrict__ ei, const float* __restrict__ ew) {
    int e = blockIdx.x * blockDim.x + threadIdx.x;
    if (e >= ET_) return;
    int d;
    if (e < E_) {
        d = ei[E_ + e];
        atomicAdd(&g_ewsum, (unsigned long long)((double)ew[e] * 4294967296.0));
    } else {
        d = e - E_;
    }
    atomicAdd(&g_deg[d], 1);
}

// ---------------- scan (+ edge consts, self-zero deg & ewsum) ----------------
__global__ void k_scan(const float* __restrict__ W_edge,
                       const float* __restrict__ att_edge) {
    __shared__ int ws[32];
    int t = threadIdx.x;
    int i0 = 2 * t, i1 = 2 * t + 1;
    int a = (i0 < N_) ? g_deg[i0] : 0;
    int b = (i1 < N_) ? g_deg[i1] : 0;
    int v = a + b;
    int lane = t & 31, wid = t >> 5;
#pragma unroll
    for (int off = 1; off < 32; off <<= 1) {
        int n = __shfl_up_sync(0xffffffffu, v, off);
        if (lane >= off) v += n;
    }
    if (lane == 31) ws[wid] = v;
    __syncthreads();
    if (t < 32) {
        int u = ws[t];
#pragma unroll
        for (int off = 1; off < 32; off <<= 1) {
            int n = __shfl_up_sync(0xffffffffu, u, off);
            if (t >= off) u += n;
        }
        ws[t] = u;
    }
    __syncthreads();
    int base = (wid > 0) ? ws[wid - 1] : 0;
    int incl = v + base;
    int ex0 = incl - a - b;
    if (i0 <= N_) { g_off[i0] = ex0; if (i0 < N_) g_cur[i0] = ex0; }
    if (i1 <= N_) { g_off[i1] = ex0 + a; if (i1 < N_) g_cur[i1] = ex0 + a; }
    g_deg[i0] = 0; g_deg[i1] = 0;
    if (t < 4) {
        float c = 0.f;
        for (int j = 0; j < 32; j++) c += W_edge[t * 32 + j] * att_edge[t * 32 + j];
        g_prep[t] = c;
    }
    if (t == 4) {
        g_prep[4] = (float)((double)g_ewsum / 4294967296.0 / (double)E_);
        g_ewsum = 0ull;
    }
}

__global__ void k_scatter(const int* __restrict__ ei) {
    int e = blockIdx.x * blockDim.x + threadIdx.x;
    if (e >= ET_) return;
    int d = (e < E_) ? ei[E_ + e] : (e - E_);
    int pos = atomicAdd(&g_cur[d], 1);
    g_csr[pos] = e;
}

// ---------------- h = x @ W_gat (fp16 out); attn scalar terms (fp32) ---------
__global__ void __launch_bounds__(256) k_h(const float* __restrict__ x,
                                           const float* __restrict__ Wg,
                                           const float* __restrict__ as_w,
                                           const float* __restrict__ ad_w) {
    __shared__ float Wgs[16 * 128];
    __shared__ float s_as[128], s_ad[128];
    int tid = threadIdx.x;
    for (int i = tid; i < 2048; i += 256) Wgs[i] = Wg[i];
    for (int i = tid; i < 128; i += 256) { s_as[i] = as_w[i]; s_ad[i] = ad_w[i]; }
    __syncthreads();
    int w = blockIdx.x * 8 + (tid >> 5);
    if (w >= GN_) return;
    int lane = tid & 31;
    const float* xr = x + (size_t)w * 16;
    float xf = (lane < 16) ? xr[lane] : 0.f;
    float4 h4 = make_float4(0.f, 0.f, 0.f, 0.f);
    const float4* Wg4 = (const float4*)Wgs;
#pragma unroll
    for (int f = 0; f < 16; f++) {
        float xv = __shfl_sync(0xffffffffu, xf, f);
        float4 wv = Wg4[f * 32 + lane];
        h4.x += xv * wv.x; h4.y += xv * wv.y; h4.z += xv * wv.z; h4.w += xv * wv.w;
    }
    HCvt c0, c1;
    c0.h2 = __floats2half2_rn(h4.x, h4.y);
    c1.h2 = __floats2half2_rn(h4.z, h4.w);
    *(uint2*)&g_h[(size_t)w * 128 + lane * 4] = make_uint2(c0.u, c1.u);
    float4 a = ((const float4*)s_as)[lane];
    float4 d = ((const float4*)s_ad)[lane];
    float vs = h4.x * a.x + h4.y * a.y + h4.z * a.z + h4.w * a.w;
    float vd = h4.x * d.x + h4.y * d.y + h4.z * d.z + h4.w * d.w;
#pragma unroll
    for (int off = 1; off < 8; off <<= 1) {
        vs += __shfl_xor_sync(0xffffffffu, vs, off);
        vd += __shfl_xor_sync(0xffffffffu, vd, off);
    }
    if ((lane & 7) == 0) {
        g_asrc[w * 4 + (lane >> 3)] = vs;
        g_adst[w * 4 + (lane >> 3)] = vd;
    }
}

// ---------------- GAT aggregate v2: two edges/warp, 8 ch/lane ----------------
__global__ void __launch_bounds__(256) k_agg(const int* __restrict__ ei,
                                             const float* __restrict__ ew,
                                             const float* __restrict__ gbias,
                                             const float* __restrict__ Wp,
                                             const float* __restrict__ bp) {
    __shared__ float Wps[32 * 64];
    __shared__ float bias_s[32];
    __shared__ float bp_s[64];
    __shared__ float ce_s[4];
    __shared__ float ewm_sh;
    __shared__ float sog[8][32];
    int tid = threadIdx.x;
    for (int i = tid; i < 2048; i += 256) Wps[i] = Wp[i];
    if (tid < 32) bias_s[tid] = gbias[tid];
    if (tid < 64) bp_s[tid] = bp[tid];
    if (tid < 4)  ce_s[tid] = g_prep[tid];
    if (tid == 8) ewm_sh = g_prep[4];
    __syncthreads();
    int w = blockIdx.x * 8 + (tid >> 5);
    int wid = tid >> 5;
    float ewm_s = ewm_sh;
    int lane = tid & 31;
    int hf = lane >> 4;
    int ll = lane & 15;
    int hd = ll >> 2;
    int g = w / N_;
    int dst = w - g * N_;
    float ad = g_adst[((size_t)g * N_ + dst) * 4 + hd];
    float ce = ce_s[hd];
    float acc[8];
#pragma unroll
    for (int j = 0; j < 8; j++) acc[j] = 0.f;
    float den = 0.f;
    int beg = g_off[dst], end = g_off[dst + 1];
    const __half* hbase = g_h + (size_t)g * N_ * 128;
    const float* abase = g_asrc + (size_t)g * N_ * 4;
    int i = beg + hf;
    bool v = (i < end);
    int e0 = v ? g_csr[i] : 0;
    int s; float wgt;
    if (e0 < E_) { s = ei[e0]; wgt = ew[e0]; } else { s = e0 - E_; wgt = ewm_s; }
    float as = abase[s * 4 + hd];
    uint4 hr = *(const uint4*)(hbase + (size_t)s * 128 + ll * 8);
    int cnt = (end - beg + 1) >> 1;
    for (int it = 0; it < cnt; it++) {
        int in_ = i + 2;
        bool vn = (in_ < end);
        int en = vn ? g_csr[in_] : 0;
        int sn; float wn;
        if (en < E_) { sn = ei[en]; wn = ew[en]; } else { sn = en - E_; wn = ewm_s; }
        float asn = abase[sn * 4 + hd];
        uint4 hrn = *(const uint4*)(hbase + (size_t)sn * 128 + ll * 8);
        float lg = as + ad + ce * wgt;
        lg = (lg > 0.f) ? lg : 0.2f * lg;
        float p = v ? __expf(lg) : 0.f;
        den += p;
        const uint32_t* hw = &hr.x;
#pragma unroll
        for (int j2 = 0; j2 < 4; j2++) {
            float2 f = __half22float2(*(const __half2*)&hw[j2]);
            acc[j2 * 2 + 0] += p * f.x;
            acc[j2 * 2 + 1] += p * f.y;
        }
        i = in_; v = vn; s = sn; wgt = wn; as = asn; hr = hrn;
    }
    den += __shfl_xor_sync(0xffffffffu, den, 16);
    float inv = 1.f / (den + 1e-16f);
#pragma unroll
    for (int j = 0; j < 8; j++) {
        acc[j] += __shfl_xor_sync(0xffffffffu, acc[j], 16);
        acc[j] *= inv;
        acc[j] += __shfl_xor_sync(0xffffffffu, acc[j], 4);
        acc[j] += __shfl_xor_sync(0xffffffffu, acc[j], 8);
        acc[j] = acc[j] * 0.25f + bias_s[(ll & 3) * 8 + j];
    }
    if (lane < 4) {
#pragma unroll
        for (int j = 0; j < 8; j++) sog[wid][lane * 8 + j] = acc[j];
    }
    __syncwarp();
    int d0 = lane * 2;
    float y0 = bp_s[d0], y1 = bp_s[d0 + 1];
#pragma unroll
    for (int c = 0; c < 32; c++) {
        float vv = sog[wid][c];
        float2 wv = *(const float2*)&Wps[c * 64 + d0];
        y0 += vv * wv.x; y1 += vv * wv.y;
    }
    int b = g >> 4;
    int t = g & 15;
    HCvt yo; yo.h2 = __floats2half2_rn(y0, y1);
    *(uint32_t*)&g_y[(((size_t)(b * N_ + dst)) * T_ + t) * D_ + d0] = yo.u;
}

// ---------------- fused KV-MMA + attention + Wo + residual + LN1 -------------
// one block = 4 bn rows = 64 rn rows. KV computed via HMMA into smem; no g_kv.
#define SA_ 72
#define SB_ 136
#define KVP_ 136
__global__ void __launch_bounds__(256) k_attn_fused(const float* __restrict__ bqkv,
                                                    const float* __restrict__ bo,
                                                    const float* __restrict__ ln1g,
                                                    const float* __restrict__ ln1b) {
    __shared__ __half AB[64 * SA_ + 64 * SB_];   // A + B staging; KV overlays after MMA
    __shared__ float bqs[128];
    __shared__ __half2 Wqs2[64 * 32];
    __shared__ __half2 Wos2[64 * 32];
    __shared__ float bos[64], g1s[64], b1s[64], bq0[64];
    __shared__ float ys[4][64];
    __shared__ float sq[4][64];
    __half* Ah = AB;
    __half* Bs = AB + 64 * SA_;
    __half* KVs = AB;                            // 64 x KVP_ (17408 B <= 26624 B)
    int tid = threadIdx.x, wid = tid >> 5, lane = tid & 31;
    int rb = blockIdx.x * 64;                    // rn base
    for (int i = tid; i < 512; i += 256) {
        int r = i >> 3, s = i & 7;
        *(uint4*)&Ah[r * SA_ + s * 8] = *(const uint4*)&g_y[((size_t)(rb + r)) * 64 + s * 8];
    }
    for (int i = tid; i < 1024; i += 256) {
        int r = i >> 4, s = i & 15;
        *(uint4*)&Bs[r * SB_ + s * 8] = *(const uint4*)&g_wkvh[r * 128 + s * 8];
    }
    for (int i = tid; i < 512; i += 256) {
        ((uint4*)Wos2)[i] = ((const uint4*)g_woh)[i];
        ((uint4*)Wqs2)[i] = ((const uint4*)g_wqh)[i];
    }
    if (tid < 128) bqs[tid] = bqkv[64 + tid];
    if (tid < 64) { bos[tid] = bo[tid]; g1s[tid] = ln1g[tid]; b1s[tid] = ln1b[tid]; bq0[tid] = bqkv[tid]; }
    __syncthreads();
    // ---- KV MMA (same layout as old k_qkv_mma) ----
    int mi = wid >> 1;
    int nb = (wid & 1) * 64;
    float o[4][2][4];
#pragma unroll
    for (int j = 0; j < 4; j++)
#pragma unroll
        for (int n8 = 0; n8 < 2; n8++)
#pragma unroll
            for (int q = 0; q < 4; q++) o[j][n8][q] = 0.f;
    {
        uint32_t abase = su32(Ah) + ((mi * 16 + (lane & 15)) * SA_ + (lane >> 4) * 8) * 2;
        uint32_t bbase = su32(Bs) + (((lane & 15)) * SB_ + nb + (lane >> 4) * 8) * 2;
#pragma unroll
        for (int k = 0; k < 4; k++) {
            uint32_t a0, a1, a2, a3;
            ldsm_x4(a0, a1, a2, a3, abase + k * 32);
#pragma unroll
            for (int j = 0; j < 4; j++) {
                uint32_t b0, b1, b2, b3;
                ldsm_x4t(b0, b1, b2, b3, bbase + (k * 16 * SB_ + j * 16) * 2);
                mma16816(o[j][0], a0, a1, a2, a3, b0, b1);
                mma16816(o[j][1], a0, a1, a2, a3, b2, b3);
            }
        }
    }
    __syncthreads();   // all ldsm reads of A/B done; safe to overlay KV
    {
        int r0 = lane >> 2, c0 = (lane & 3) * 2;
#pragma unroll
        for (int j = 0; j < 4; j++)
#pragma unroll
            for (int n8 = 0; n8 < 2; n8++)
#pragma unroll
                for (int hm = 0; hm < 2; hm++) {
                    int row = mi * 16 + r0 + hm * 8;
                    int col = nb + j * 16 + n8 * 8 + c0;
                    HCvt v; v.h2 = __floats2half2_rn(o[j][n8][hm * 2 + 0] + bqs[col],
                                                     o[j][n8][hm * 2 + 1] + bqs[col + 1]);
                    *(uint32_t*)&KVs[row * KVP_ + col] = v.u;
                }
    }
    __syncthreads();
    // ---- attention: warps 0-3 handle 4 bn rows ----
    if (wid >= 4) return;
    int r = blockIdx.x * 4 + wid;                 // global bn row
    int lb = wid;                                 // local row
    int dcol = lane * 2;
    __half2 yh = *(const __half2*)&g_y[((size_t)(r * 16 + 15)) * 64 + dcol];
    float2 yv = __half22float2(yh);
    ys[lb][dcol] = yv.x; ys[lb][dcol + 1] = yv.y;
    __syncwarp();
    float q0 = bq0[dcol], q1 = bq0[dcol + 1];
#pragma unroll 16
    for (int j = 0; j < 64; j++) {
        float yj = ys[lb][j];
        float2 wv = __half22float2(Wqs2[j * 32 + lane]);
        q0 += yj * wv.x; q1 += yj * wv.y;
    }
    sq[lb][dcol] = q0; sq[lb][dcol + 1] = q1;
    __syncwarp();
    int t = lane & 15, grp = lane >> 4;
    const __half* kbase = &KVs[(lb * 16 + t) * KVP_ + grp * 32];
    const float* qq = &sq[lb][grp * 32];
    uint4 kr0 = *(const uint4*)&kbase[0];
    uint4 kr1 = *(const uint4*)&kbase[8];
    uint4 kr2 = *(const uint4*)&kbase[16];
    uint4 kr3 = *(const uint4*)&kbase[24];
    float s0 = 0.f, s1 = 0.f;
    {
        const uint32_t* kw0 = &kr0.x;
        const uint32_t* kw1 = &kr1.x;
#pragma unroll
        for (int j2 = 0; j2 < 4; j2++) {
            float2 f0 = __half22float2(*(const __half2*)&kw0[j2]);
            float2 f1 = __half22float2(*(const __half2*)&kw1[j2]);
            s0 += qq[j2 * 2 + 0] * f0.x + qq[j2 * 2 + 1] * f0.y;
            s0 += qq[8 + j2 * 2 + 0] * f1.x + qq[8 + j2 * 2 + 1] * f1.y;
        }
        const uint32_t* kw2 = &kr2.x;
        const uint32_t* kw3 = &kr3.x;
#pragma unroll
        for (int j2 = 0; j2 < 4; j2++) {
            float2 f2 = __half22float2(*(const __half2*)&kw2[j2]);
            float2 f3 = __half22float2(*(const __half2*)&kw3[j2]);
            s1 += qq[16 + j2 * 2 + 0] * f2.x + qq[16 + j2 * 2 + 1] * f2.y;
            s1 += qq[24 + j2 * 2 + 0] * f3.x + qq[24 + j2 * 2 + 1] * f3.y;
        }
    }
    s0 *= 0.25f; s1 *= 0.25f;
    float m0 = s0, m1 = s1;
#pragma unroll
    for (int off = 1; off < 16; off <<= 1) {
        m0 = fmaxf(m0, __shfl_xor_sync(0xffffffffu, m0, off));
        m1 = fmaxf(m1, __shfl_xor_sync(0xffffffffu, m1, off));
    }
    float p0 = __expf(s0 - m0), p1 = __expf(s1 - m1);
    float dn0 = p0, dn1 = p1;
#pragma unroll
    for (int off = 1; off < 16; off <<= 1) {
        dn0 += __shfl_xor_sync(0xffffffffu, dn0, off);
        dn1 += __shfl_xor_sync(0xffffffffu, dn1, off);
    }
    p0 /= dn0; p1 /= dn1;
    int hd = lane >> 3;
    int srcbase = (hd >> 1) * 16;
    int sel = hd & 1;
    float c0v = 0.f, c1v = 0.f;
#pragma unroll
    for (int tt = 0; tt < 16; tt++) {
        float pa = __shfl_sync(0xffffffffu, p0, srcbase + tt);
        float pb = __shfl_sync(0xffffffffu, p1, srcbase + tt);
        float pv = sel ? pb : pa;
        float2 v2 = __half22float2(*(const __half2*)&KVs[(lb * 16 + tt) * KVP_ + 64 + dcol]);
        c0v += pv * v2.x; c1v += pv * v2.y;
    }
    float o0 = bos[dcol], o1 = bos[dcol + 1];
#pragma unroll
    for (int jj = 0; jj < 32; jj++) {
        float ca = __shfl_sync(0xffffffffu, c0v, jj);
        float cb = __shfl_sync(0xffffffffu, c1v, jj);
        float2 wA = __half22float2(Wos2[(2 * jj) * 32 + lane]);
        float2 wB = __half22float2(Wos2[(2 * jj + 1) * 32 + lane]);
        o0 += ca * wA.x + cb * wB.x;
        o1 += ca * wA.y + cb * wB.y;
    }
    float r0v = ys[lb][dcol] + o0, r1v = ys[lb][dcol + 1] + o1;
    float su = r0v + r1v, s2 = r0v * r0v + r1v * r1v;
#pragma unroll
    for (int off = 1; off < 32; off <<= 1) {
        su += __shfl_xor_sync(0xffffffffu, su, off);
        s2 += __shfl_xor_sync(0xffffffffu, s2, off);
    }
    float mu = su * (1.f / 64.f);
    float var = s2 * (1.f / 64.f) - mu * mu;
    float inv = rsqrtf(var + 1e-5f);
    float2 z;
    z.x = (r0v - mu) * inv * g1s[dcol] + b1s[dcol];
    z.y = (r1v - mu) * inv * g1s[dcol + 1] + b1s[dcol + 1];
    *(float2*)&g_z[(size_t)r * 64 + dcol] = z;
}

// ---------------- fused FFN split-K(2) + last-block LN2 epilogue -------------
__global__ void __launch_bounds__(256) k_ffn(const float* __restrict__ b1,
                                             const float* __restrict__ b2,
                                             const float* __restrict__ ln2g,
                                             const float* __restrict__ ln2b,
                                             float* __restrict__ out) {
    __shared__ __half Ah[32 * SA_];
    __shared__ __half Sh[32 * SA_];
    __shared__ __half W1s[64 * SA_];
    __shared__ __half W2s[64 * SA_];
    __shared__ float b1s[1024];
    __shared__ bool last_s;
    int tid = threadIdx.x, wid = tid >> 5, lane = tid & 31;
    int rb = blockIdx.x * 32;
    int kc0 = blockIdx.y * 1024;
    for (int i = tid; i < 32 * 16; i += 256) {
        int r = i >> 4, s4 = i & 15;
        float4 v = *(const float4*)&g_z[((size_t)(rb + r)) * 64 + s4 * 4];
        HCvt h0, h1;
        h0.h2 = __floats2half2_rn(v.x, v.y);
        h1.h2 = __floats2half2_rn(v.z, v.w);
        *(uint2*)&Ah[r * SA_ + s4 * 4] = make_uint2(h0.u, h1.u);
    }
    for (int i = tid; i < 1024; i += 256) b1s[i] = b1[kc0 + i];
    int mi = wid & 1, ni = wid >> 1;
    float o[2][4];
#pragma unroll
    for (int n8 = 0; n8 < 2; n8++)
#pragma unroll
        for (int q = 0; q < 4; q++) o[n8][q] = 0.f;
    int r0 = lane >> 2, c0 = (lane & 3) * 2;
    uint32_t a1base = su32(Ah) + ((mi * 16 + (lane & 15)) * SA_ + (lane >> 4) * 8) * 2;
    uint32_t a2base = su32(Sh) + ((mi * 16 + (lane & 15)) * SA_ + (lane >> 4) * 8) * 2;
    uint32_t w1base = su32(W1s) + (((lane & 15)) * SA_ + ni * 16 + (lane >> 4) * 8) * 2;
    uint32_t w2base = su32(W2s) + (((lane & 15)) * SA_ + ni * 16 + (lane >> 4) * 8) * 2;
    for (int cb = kc0; cb < kc0 + 1024; cb += 64) {
        __syncthreads();
        for (int i = tid; i < 512; i += 256) {
            int r = i >> 3, s = i & 7;
            *(uint4*)&W1s[r * SA_ + s * 8] = *(const uint4*)&g_w1h[(size_t)r * FF_ + cb + s * 8];
            *(uint4*)&W2s[r * SA_ + s * 8] = *(const uint4*)&g_w2h[(size_t)(cb + r) * 64 + s * 8];
        }
        __syncthreads();
        float d[2][4];
#pragma unroll
        for (int n8 = 0; n8 < 2; n8++)
#pragma unroll
            for (int q = 0; q < 4; q++) d[n8][q] = 0.f;
#pragma unroll
        for (int k = 0; k < 4; k++) {
            uint32_t a0, a1, a2, a3, b0v, b1v, b2v, b3v;
            ldsm_x4(a0, a1, a2, a3, a1base + k * 32);
            ldsm_x4t(b0v, b1v, b2v, b3v, w1base + k * 16 * SA_ * 2);
            mma16816(d[0], a0, a1, a2, a3, b0v, b1v);
            mma16816(d[1], a0, a1, a2, a3, b2v, b3v);
        }
#pragma unroll
        for (int n8 = 0; n8 < 2; n8++) {
            int col = ni * 16 + n8 * 8 + c0;
            float bb0 = b1s[cb - kc0 + col], bb1 = b1s[cb - kc0 + col + 1];
            HCvt v0, v1;
            v0.h2 = __floats2half2_rn(fmaxf(d[n8][0] + bb0, 0.f), fmaxf(d[n8][1] + bb1, 0.f));
            v1.h2 = __floats2half2_rn(fmaxf(d[n8][2] + bb0, 0.f), fmaxf(d[n8][3] + bb1, 0.f));
            *(uint32_t*)&Sh[(mi * 16 + r0) * SA_ + col] = v0.u;
            *(uint32_t*)&Sh[(mi * 16 + r0 + 8) * SA_ + col] = v1.u;
        }
        __syncthreads();
#pragma unroll
        for (int k = 0; k < 4; k++) {
            uint32_t a0, a1, a2, a3, b0v, b1v, b2v, b3v;
            ldsm_x4(a0, a1, a2, a3, a2base + k * 32);
            ldsm_x4t(b0v, b1v, b2v, b3v, w2base + k * 16 * SA_ * 2);
            mma16816(o[0], a0, a1, a2, a3, b0v, b1v);
            mma16816(o[1], a0, a1, a2, a3, b2v, b3v);
        }
    }
    float* plane = g_acc[blockIdx.y];
#pragma unroll
    for (int n8 = 0; n8 < 2; n8++) {
        int col = ni * 16 + n8 * 8 + c0;
        *(float2*)&plane[(size_t)(rb + mi * 16 + r0) * 64 + col] = make_float2(o[n8][0], o[n8][1]);
        *(float2*)&plane[(size_t)(rb + mi * 16 + r0 + 8) * 64 + col] = make_float2(o[n8][2], o[n8][3]);
    }
    __threadfence();
    __syncthreads();
    if (tid == 0) {
        int old = atomicAdd(&g_cnt[blockIdx.x], 1);
        last_s = (old == 1);
        if (last_s) g_cnt[blockIdx.x] = 0;
    }
    __syncthreads();
    if (!last_s) return;
    int d2 = lane * 2;
    for (int rr = wid; rr < 32; rr += 8) {
        int r = rb + rr;
        float2 zr = *(const float2*)&g_z[(size_t)r * 64 + d2];
        float2 p0 = *(const float2*)&g_acc[0][(size_t)r * 64 + d2];
        float2 p1 = *(const float2*)&g_acc[1][(size_t)r * 64 + d2];
        float v0 = zr.x + p0.x + p1.x + b2[d2];
        float v1 = zr.y + p0.y + p1.y + b2[d2 + 1];
        float su = v0 + v1, s2 = v0 * v0 + v1 * v1;
#pragma unroll
        for (int off = 1; off < 32; off <<= 1) {
            su += __shfl_xor_sync(0xffffffffu, su, off);
            s2 += __shfl_xor_sync(0xffffffffu, s2, off);
        }
        float mu = su * (1.f / 64.f);
        float var = s2 * (1.f / 64.f) - mu * mu;
        float inv = rsqrtf(var + 1e-5f);
        float2 oo;
        oo.x = (v0 - mu) * inv * ln2g[d2] + ln2b[d2];
        oo.y = (v1 - mu) * inv * ln2g[d2 + 1] + ln2b[d2 + 1];
        *(float2*)&out[(size_t)r * 64 + d2] = oo;
    }
}

// ---------------- launch (graph-parallel branches via fork-join) -------------
extern "C" void kernel_launch(void* const* d_in, const int* in_sizes, int n_in,
                              void* d_out, int out_size) {
    const float* x_seq    = (const float*)d_in[0];
    const int*   eidx     = (const int*)d_in[1];
    const float* eweight  = (const float*)d_in[2];
    const float* W_gat    = (const float*)d_in[3];
    const float* att_src  = (const float*)d_in[4];
    const float* att_dst  = (const float*)d_in[5];
    const float* W_edge   = (const float*)d_in[6];
    const float* att_edge = (const float*)d_in[7];
    const float* gat_bias = (const float*)d_in[8];
    const float* W_proj   = (const float*)d_in[9];
    const float* b_proj   = (const float*)d_in[10];
    const float* Wqkv     = (const float*)d_in[11];
    const float* bqkv     = (const float*)d_in[12];
    const float* Wo       = (const float*)d_in[13];
    const float* bo       = (const float*)d_in[14];
    const float* ln1_g    = (const float*)d_in[15];
    const float* ln1_b    = (const float*)d_in[16];
    const float* W1       = (const float*)d_in[17];
    const float* b1       = (const float*)d_in[18];
    const float* W2       = (const float*)d_in[19];
    const float* b2       = (const float*)d_in[20];
    const float* ln2_g    = (const float*)d_in[21];
    const float* ln2_b    = (const float*)d_in[22];
    float* out = (float*)d_out;

    static cudaStream_t sB = nullptr, sC = nullptr;
    static cudaEvent_t evRoot = nullptr, evB = nullptr, evC = nullptr;
    if (sB == nullptr) {
        cudaStreamCreateWithFlags(&sB, cudaStreamNonBlocking);
        cudaStreamCreateWithFlags(&sC, cudaStreamNonBlocking);
        cudaEventCreateWithFlags(&evRoot, cudaEventDisableTiming);
        cudaEventCreateWithFlags(&evB, cudaEventDisableTiming);
        cudaEventCreateWithFlags(&evC, cudaEventDisableTiming);
    }

    cudaEventRecord(evRoot, 0);
    cudaStreamWaitEvent(sB, evRoot, 0);
    cudaStreamWaitEvent(sC, evRoot, 0);

    // branch B: CSR build (feeds k_agg)
    k_count<<<(ET_ + 255) / 256, 256, 0, sB>>>(eidx, eweight);
    k_scan<<<1, 1024, 0, sB>>>(W_edge, att_edge);
    k_scatter<<<(ET_ + 255) / 256, 256, 0, sB>>>(eidx);
    cudaEventRecord(evB, sB);

    // branch C: fp16 weight conversion
    k_cvt<<<512, 256, 0, sC>>>(Wqkv, W1, W2, Wo);
    cudaEventRecord(evC, sC);

    // main branch: node features
    k_h<<<GN_ / 8, 256>>>(x_seq, W_gat, att_src, att_dst);

    cudaStreamWaitEvent(0, evB, 0);
    k_agg<<<GN_ / 8, 256>>>(eidx, eweight, gat_bias, W_proj, b_proj);

    cudaStreamWaitEvent(0, evC, 0);
    k_attn_fused<<<BN_ / 4, 256>>>(bqkv, bo, ln1_g, ln1_b);
    {
        dim3 grid(BN_ / 32, 2);
        k_ffn<<<grid, 256>>>(b1, b2, ln2_g, ln2_b, out);
    }
}

// round 11
// speedup vs baseline: 2.1130x; 1.0245x over previous
#include <cuda_runtime.h>
#include <cuda_fp16.h>
#include <cstdint>

#define B_ 2
#define T_ 16
#define N_ 2000
#define F_ 16
#define E_ 32000
#define H_ 4
#define C_ 32
#define D_ 64
#define FF_ 2048
#define G_ (B_*T_)      /* 32  */
#define ET_ (E_+N_)     /* 34000 */
#define BN_ (B_*N_)     /* 4000 */
#define GN_ (G_*N_)     /* 64000 */

// ---------------- scratch (static device globals; no allocation) -------------
__device__ __half g_h[(size_t)GN_ * 128];  // h: [G,N,H*C] fp16
__device__ float g_asrc[GN_ * 4];
__device__ float g_adst[GN_ * 4];
__device__ float g_prep[8];               // c_edge[0..3], ew_mean at [4]
__device__ int   g_off[N_ + 1];
__device__ int   g_cur[N_];
__device__ int   g_csr[ET_];
__device__ __half g_y[GN_ * D_];          // fp16 [bn][t][d]  (row rn = bn*16+t)
__device__ float g_z[BN_ * D_];           // post-LN1
__device__ __half g_wkvh[64 * 128];       // fp16 Wqkv[:,64:192]
__device__ __half g_wqh[64 * 64];         // fp16 Wqkv[:,0:64]
__device__ __half g_woh[64 * 64];         // fp16 Wo
__device__ __half g_w1h[64 * FF_];        // fp16 W1
__device__ __half g_w2h[FF_ * 64];        // fp16 W2
__device__ float g_acc[4][BN_ * D_];      // ffn split-K planes
__device__ int   g_cnt[BN_ / 32];         // per-row-block completion counters

union HCvt { __half2 h2; uint32_t u; };

// ---------------- mma helpers ------------------------------------------------
__device__ __forceinline__ uint32_t su32(const void* p) {
    uint32_t a;
    asm("{ .reg .u64 t; cvta.to.shared.u64 t, %1; cvt.u32.u64 %0, t; }" : "=r"(a) : "l"(p));
    return a;
}
__device__ __forceinline__ void ldsm_x4(uint32_t& r0, uint32_t& r1, uint32_t& r2, uint32_t& r3, uint32_t a) {
    asm volatile("ldmatrix.sync.aligned.m8n8.x4.shared.b16 {%0,%1,%2,%3}, [%4];"
                 : "=r"(r0), "=r"(r1), "=r"(r2), "=r"(r3) : "r"(a));
}
__device__ __forceinline__ void ldsm_x4t(uint32_t& r0, uint32_t& r1, uint32_t& r2, uint32_t& r3, uint32_t a) {
    asm volatile("ldmatrix.sync.aligned.m8n8.x4.trans.shared.b16 {%0,%1,%2,%3}, [%4];"
                 : "=r"(r0), "=r"(r1), "=r"(r2), "=r"(r3) : "r"(a));
}
__device__ __forceinline__ void mma16816(float* d, uint32_t a0, uint32_t a1, uint32_t a2, uint32_t a3,
                                         uint32_t b0, uint32_t b1) {
    asm volatile("mma.sync.aligned.m16n8k16.row.col.f32.f16.f16.f32 "
                 "{%0,%1,%2,%3}, {%4,%5,%6,%7}, {%8,%9}, {%0,%1,%2,%3};"
                 : "+f"(d[0]), "+f"(d[1]), "+f"(d[2]), "+f"(d[3])
                 : "r"(a0), "r"(a1), "r"(a2), "r"(a3), "r"(b0), "r"(b1));
}

// ---------------- weight conversion to fp16 ----------------------------------
__global__ void k_cvt(const float* __restrict__ Wqkv, const float* __restrict__ W1,
                      const float* __restrict__ W2, const float* __restrict__ Wo) {
    int i = blockIdx.x * 256 + threadIdx.x;
    if (i < 64 * 128) {
        int k = i >> 7, c = i & 127;
        g_wkvh[i] = __float2half(Wqkv[k * 192 + 64 + c]);
    }
    if (i < 64 * 64) {
        int k = i >> 6, c = i & 63;
        g_wqh[i] = __float2half(Wqkv[k * 192 + c]);
        g_woh[i] = __float2half(Wo[i]);
    }
    if (i < 64 * FF_) {
        g_w1h[i] = __float2half(W1[i]);
        g_w2h[i] = __float2half(W2[i]);
    }
}

// ---------------- hist + scan + edge consts (one kernel) ---------------------
__global__ void k_hist(const int* __restrict__ ei, const float* __restrict__ ew,
                       const float* __restrict__ W_edge,
                       const float* __restrict__ att_edge) {
    __shared__ int hist[2048];
    __shared__ float red[1024];
    __shared__ int ws[32];
    int t = threadIdx.x;
    hist[t] = 0; hist[t + 1024] = 0;
    __syncthreads();
    float s = 0.f;
    for (int i = t; i < ET_; i += 1024) {
        int d;
        if (i < E_) { d = ei[E_ + i]; s += ew[i]; }
        else d = i - E_;
        atomicAdd(&hist[d], 1);
    }
    red[t] = s;
    __syncthreads();
    for (int o = 512; o > 0; o >>= 1) {
        if (t < o) red[t] += red[t + o];
        __syncthreads();
    }
    if (t == 0) g_prep[4] = red[0] / (float)E_;
    if (t < 4) {
        float c = 0.f;
        for (int j = 0; j < 32; j++) c += W_edge[t * 32 + j] * att_edge[t * 32 + j];
        g_prep[t] = c;
    }
    // exclusive scan over hist[0..N_)
    int i0 = 2 * t, i1 = 2 * t + 1;
    int a = (i0 < N_) ? hist[i0] : 0;
    int b = (i1 < N_) ? hist[i1] : 0;
    int v = a + b;
    int lane = t & 31, wid = t >> 5;
#pragma unroll
    for (int off = 1; off < 32; off <<= 1) {
        int n = __shfl_up_sync(0xffffffffu, v, off);
        if (lane >= off) v += n;
    }
    if (lane == 31) ws[wid] = v;
    __syncthreads();
    if (t < 32) {
        int u = ws[t];
#pragma unroll
        for (int off = 1; off < 32; off <<= 1) {
            int n = __shfl_up_sync(0xffffffffu, u, off);
            if (t >= off) u += n;
        }
        ws[t] = u;
    }
    __syncthreads();
    int base = (wid > 0) ? ws[wid - 1] : 0;
    int incl = v + base;
    int ex0 = incl - a - b;
    if (i0 <= N_) { g_off[i0] = ex0; if (i0 < N_) g_cur[i0] = ex0; }
    if (i1 <= N_) { g_off[i1] = ex0 + a; if (i1 < N_) g_cur[i1] = ex0 + a; }
}

__global__ void k_scatter(const int* __restrict__ ei) {
    int e = blockIdx.x * blockDim.x + threadIdx.x;
    if (e >= ET_) return;
    int d = (e < E_) ? ei[E_ + e] : (e - E_);
    int pos = atomicAdd(&g_cur[d], 1);
    g_csr[pos] = e;
}

// ---------------- h = x @ W_gat (fp16 out); attn scalar terms (fp32) ---------
__global__ void __launch_bounds__(256) k_h(const float* __restrict__ x,
                                           const float* __restrict__ Wg,
                                           const float* __restrict__ as_w,
                                           const float* __restrict__ ad_w) {
    __shared__ float Wgs[16 * 128];
    __shared__ float s_as[128], s_ad[128];
    int tid = threadIdx.x;
    for (int i = tid; i < 2048; i += 256) Wgs[i] = Wg[i];
    for (int i = tid; i < 128; i += 256) { s_as[i] = as_w[i]; s_ad[i] = ad_w[i]; }
    __syncthreads();
    int w = blockIdx.x * 8 + (tid >> 5);
    if (w >= GN_) return;
    int lane = tid & 31;
    const float* xr = x + (size_t)w * 16;
    float xf = (lane < 16) ? xr[lane] : 0.f;
    float4 h4 = make_float4(0.f, 0.f, 0.f, 0.f);
    const float4* Wg4 = (const float4*)Wgs;
#pragma unroll
    for (int f = 0; f < 16; f++) {
        float xv = __shfl_sync(0xffffffffu, xf, f);
        float4 wv = Wg4[f * 32 + lane];
        h4.x += xv * wv.x; h4.y += xv * wv.y; h4.z += xv * wv.z; h4.w += xv * wv.w;
    }
    HCvt c0, c1;
    c0.h2 = __floats2half2_rn(h4.x, h4.y);
    c1.h2 = __floats2half2_rn(h4.z, h4.w);
    *(uint2*)&g_h[(size_t)w * 128 + lane * 4] = make_uint2(c0.u, c1.u);
    float4 a = ((const float4*)s_as)[lane];
    float4 d = ((const float4*)s_ad)[lane];
    float vs = h4.x * a.x + h4.y * a.y + h4.z * a.z + h4.w * a.w;
    float vd = h4.x * d.x + h4.y * d.y + h4.z * d.z + h4.w * d.w;
#pragma unroll
    for (int off = 1; off < 8; off <<= 1) {
        vs += __shfl_xor_sync(0xffffffffu, vs, off);
        vd += __shfl_xor_sync(0xffffffffu, vd, off);
    }
    if ((lane & 7) == 0) {
        g_asrc[w * 4 + (lane >> 3)] = vs;
        g_adst[w * 4 + (lane >> 3)] = vd;
    }
}

// ---------------- GAT aggregate v3: FOUR edges/warp, 16 ch/lane --------------
__global__ void __launch_bounds__(256) k_agg(const int* __restrict__ ei,
                                             const float* __restrict__ ew,
                                             const float* __restrict__ gbias,
                                             const float* __restrict__ Wp,
                                             const float* __restrict__ bp) {
    __shared__ float Wps[32 * 64];
    __shared__ float bias_s[32];
    __shared__ float bp_s[64];
    __shared__ float ce_s[4];
    __shared__ float ewm_sh;
    __shared__ float sog[8][32];
    int tid = threadIdx.x;
    for (int i = tid; i < 2048; i += 256) Wps[i] = Wp[i];
    if (tid < 32) bias_s[tid] = gbias[tid];
    if (tid < 64) bp_s[tid] = bp[tid];
    if (tid < 4)  ce_s[tid] = g_prep[tid];
    if (tid == 8) ewm_sh = g_prep[4];
    __syncthreads();
    int wid = tid >> 5;
    int w = blockIdx.x * 8 + wid;
    float ewm_s = ewm_sh;
    int lane = tid & 31;
    int grp = lane >> 3;          // edge slot 0..3
    int ll = lane & 7;            // channel group: halves ll*16 .. ll*16+15
    int hd = ll >> 1;             // head of these channels
    int g = w / N_;
    int dst = w - g * N_;
    float ad = g_adst[((size_t)g * N_ + dst) * 4 + hd];
    float ce = ce_s[hd];
    float acc[16];
#pragma unroll
    for (int j = 0; j < 16; j++) acc[j] = 0.f;
    float den = 0.f;
    int beg = g_off[dst], end = g_off[dst + 1];
    const __half* hbase = g_h + (size_t)g * N_ * 128;
    const float* abase = g_asrc + (size_t)g * N_ * 4;
    int i = beg + grp;
    bool v = (i < end);
    int e0 = v ? g_csr[i] : 0;
    int s; float wgt;
    if (e0 < E_) { s = ei[e0]; wgt = ew[e0]; } else { s = e0 - E_; wgt = ewm_s; }
    float as = abase[s * 4 + hd];
    uint4 h0 = *(const uint4*)(hbase + (size_t)s * 128 + ll * 16);
    uint4 h1 = *(const uint4*)(hbase + (size_t)s * 128 + ll * 16 + 8);
    int cnt = (end - beg + 3) >> 2;
    for (int it = 0; it < cnt; it++) {
        int in_ = i + 4;
        bool vn = (in_ < end);
        int en = vn ? g_csr[in_] : 0;
        int sn; float wn;
        if (en < E_) { sn = ei[en]; wn = ew[en]; } else { sn = en - E_; wn = ewm_s; }
        float asn = abase[sn * 4 + hd];
        uint4 hn0 = *(const uint4*)(hbase + (size_t)sn * 128 + ll * 16);
        uint4 hn1 = *(const uint4*)(hbase + (size_t)sn * 128 + ll * 16 + 8);
        float lg = as + ad + ce * wgt;
        lg = (lg > 0.f) ? lg : 0.2f * lg;
        float p = v ? __expf(lg) : 0.f;
        den += p;
        const uint32_t* hw0 = &h0.x;
        const uint32_t* hw1 = &h1.x;
#pragma unroll
        for (int j2 = 0; j2 < 4; j2++) {
            float2 f0 = __half22float2(*(const __half2*)&hw0[j2]);
            float2 f1 = __half22float2(*(const __half2*)&hw1[j2]);
            acc[j2 * 2 + 0] += p * f0.x;
            acc[j2 * 2 + 1] += p * f0.y;
            acc[8 + j2 * 2 + 0] += p * f1.x;
            acc[8 + j2 * 2 + 1] += p * f1.y;
        }
        i = in_; v = vn; s = sn; wgt = wn; as = asn; h0 = hn0; h1 = hn1;
    }
    // sum edge groups (same ll, same head across grp)
    den += __shfl_xor_sync(0xffffffffu, den, 8);
    den += __shfl_xor_sync(0xffffffffu, den, 16);
    float inv = 1.f / (den + 1e-16f);
#pragma unroll
    for (int j = 0; j < 16; j++) {
        acc[j] += __shfl_xor_sync(0xffffffffu, acc[j], 8);
        acc[j] += __shfl_xor_sync(0xffffffffu, acc[j], 16);
        acc[j] *= inv;                                        // per-head normalize
        acc[j] += __shfl_xor_sync(0xffffffffu, acc[j], 2);    // sum heads (ll bit1)
        acc[j] += __shfl_xor_sync(0xffffffffu, acc[j], 4);    // sum heads (ll bit2)
        acc[j] = acc[j] * 0.25f + bias_s[(ll & 1) * 16 + j];  // mean + bias
    }
    if (lane < 2) {
#pragma unroll
        for (int j = 0; j < 16; j++) sog[wid][lane * 16 + j] = acc[j];
    }
    __syncwarp();
    int d0 = lane * 2;
    float y0 = bp_s[d0], y1 = bp_s[d0 + 1];
#pragma unroll
    for (int c = 0; c < 32; c++) {
        float vv = sog[wid][c];
        float2 wv = *(const float2*)&Wps[c * 64 + d0];
        y0 += vv * wv.x; y1 += vv * wv.y;
    }
    int b = g >> 4;
    int t = g & 15;
    HCvt yo; yo.h2 = __floats2half2_rn(y0, y1);
    *(uint32_t*)&g_y[(((size_t)(b * N_ + dst)) * T_ + t) * D_ + d0] = yo.u;
}

// ---------------- fused KV-MMA + attention + Wo + residual + LN1 -------------
#define SA_ 72
#define SB_ 136
#define KVP_ 136
__global__ void __launch_bounds__(256) k_attn_fused(const float* __restrict__ bqkv,
                                                    const float* __restrict__ bo,
                                                    const float* __restrict__ ln1g,
                                                    const float* __restrict__ ln1b) {
    __shared__ __half AB[64 * SA_ + 64 * SB_];
    __shared__ float bqs[128];
    __shared__ __half2 Wqs2[64 * 32];
    __shared__ __half2 Wos2[64 * 32];
    __shared__ float bos[64], g1s[64], b1s[64], bq0[64];
    __shared__ float ys[4][64];
    __shared__ float sq[4][64];
    __half* Ah = AB;
    __half* Bs = AB + 64 * SA_;
    __half* KVs = AB;
    int tid = threadIdx.x, wid = tid >> 5, lane = tid & 31;
    int rb = blockIdx.x * 64;
    for (int i = tid; i < 512; i += 256) {
        int r = i >> 3, s = i & 7;
        *(uint4*)&Ah[r * SA_ + s * 8] = *(const uint4*)&g_y[((size_t)(rb + r)) * 64 + s * 8];
    }
    for (int i = tid; i < 1024; i += 256) {
        int r = i >> 4, s = i & 15;
        *(uint4*)&Bs[r * SB_ + s * 8] = *(const uint4*)&g_wkvh[r * 128 + s * 8];
    }
    for (int i = tid; i < 512; i += 256) {
        ((uint4*)Wos2)[i] = ((const uint4*)g_woh)[i];
        ((uint4*)Wqs2)[i] = ((const uint4*)g_wqh)[i];
    }
    if (tid < 128) bqs[tid] = bqkv[64 + tid];
    if (tid < 64) { bos[tid] = bo[tid]; g1s[tid] = ln1g[tid]; b1s[tid] = ln1b[tid]; bq0[tid] = bqkv[tid]; }
    __syncthreads();
    int mi = wid >> 1;
    int nb = (wid & 1) * 64;
    float o[4][2][4];
#pragma unroll
    for (int j = 0; j < 4; j++)
#pragma unroll
        for (int n8 = 0; n8 < 2; n8++)
#pragma unroll
            for (int q = 0; q < 4; q++) o[j][n8][q] = 0.f;
    {
        uint32_t abase = su32(Ah) + ((mi * 16 + (lane & 15)) * SA_ + (lane >> 4) * 8) * 2;
        uint32_t bbase = su32(Bs) + (((lane & 15)) * SB_ + nb + (lane >> 4) * 8) * 2;
#pragma unroll
        for (int k = 0; k < 4; k++) {
            uint32_t a0, a1, a2, a3;
            ldsm_x4(a0, a1, a2, a3, abase + k * 32);
#pragma unroll
            for (int j = 0; j < 4; j++) {
                uint32_t b0, b1, b2, b3;
                ldsm_x4t(b0, b1, b2, b3, bbase + (k * 16 * SB_ + j * 16) * 2);
                mma16816(o[j][0], a0, a1, a2, a3, b0, b1);
                mma16816(o[j][1], a0, a1, a2, a3, b2, b3);
            }
        }
    }
    __syncthreads();
    {
        int r0 = lane >> 2, c0 = (lane & 3) * 2;
#pragma unroll
        for (int j = 0; j < 4; j++)
#pragma unroll
            for (int n8 = 0; n8 < 2; n8++)
#pragma unroll
                for (int hm = 0; hm < 2; hm++) {
                    int row = mi * 16 + r0 + hm * 8;
                    int col = nb + j * 16 + n8 * 8 + c0;
                    HCvt v; v.h2 = __floats2half2_rn(o[j][n8][hm * 2 + 0] + bqs[col],
                                                     o[j][n8][hm * 2 + 1] + bqs[col + 1]);
                    *(uint32_t*)&KVs[row * KVP_ + col] = v.u;
                }
    }
    __syncthreads();
    if (wid >= 4) return;
    int r = blockIdx.x * 4 + wid;
    int lb = wid;
    int dcol = lane * 2;
    __half2 yh = *(const __half2*)&g_y[((size_t)(r * 16 + 15)) * 64 + dcol];
    float2 yv = __half22float2(yh);
    ys[lb][dcol] = yv.x; ys[lb][dcol + 1] = yv.y;
    __syncwarp();
    float q0 = bq0[dcol], q1 = bq0[dcol + 1];
#pragma unroll 16
    for (int j = 0; j < 64; j++) {
        float yj = ys[lb][j];
        float2 wv = __half22float2(Wqs2[j * 32 + lane]);
        q0 += yj * wv.x; q1 += yj * wv.y;
    }
    sq[lb][dcol] = q0; sq[lb][dcol + 1] = q1;
    __syncwarp();
    int t = lane & 15, grp = lane >> 4;
    const __half* kbase = &KVs[(lb * 16 + t) * KVP_ + grp * 32];
    const float* qq = &sq[lb][grp * 32];
    uint4 kr0 = *(const uint4*)&kbase[0];
    uint4 kr1 = *(const uint4*)&kbase[8];
    uint4 kr2 = *(const uint4*)&kbase[16];
    uint4 kr3 = *(const uint4*)&kbase[24];
    float s0 = 0.f, s1 = 0.f;
    {
        const uint32_t* kw0 = &kr0.x;
        const uint32_t* kw1 = &kr1.x;
#pragma unroll
        for (int j2 = 0; j2 < 4; j2++) {
            float2 f0 = __half22float2(*(const __half2*)&kw0[j2]);
            float2 f1 = __half22float2(*(const __half2*)&kw1[j2]);
            s0 += qq[j2 * 2 + 0] * f0.x + qq[j2 * 2 + 1] * f0.y;
            s0 += qq[8 + j2 * 2 + 0] * f1.x + qq[8 + j2 * 2 + 1] * f1.y;
        }
        const uint32_t* kw2 = &kr2.x;
        const uint32_t* kw3 = &kr3.x;
#pragma unroll
        for (int j2 = 0; j2 < 4; j2++) {
            float2 f2 = __half22float2(*(const __half2*)&kw2[j2]);
            float2 f3 = __half22float2(*(const __half2*)&kw3[j2]);
            s1 += qq[16 + j2 * 2 + 0] * f2.x + qq[16 + j2 * 2 + 1] * f2.y;
            s1 += qq[24 + j2 * 2 + 0] * f3.x + qq[24 + j2 * 2 + 1] * f3.y;
        }
    }
    s0 *= 0.25f; s1 *= 0.25f;
    float m0 = s0, m1 = s1;
#pragma unroll
    for (int off = 1; off < 16; off <<= 1) {
        m0 = fmaxf(m0, __shfl_xor_sync(0xffffffffu, m0, off));
        m1 = fmaxf(m1, __shfl_xor_sync(0xffffffffu, m1, off));
    }
    float p0 = __expf(s0 - m0), p1 = __expf(s1 - m1);
    float dn0 = p0, dn1 = p1;
#pragma unroll
    for (int off = 1; off < 16; off <<= 1) {
        dn0 += __shfl_xor_sync(0xffffffffu, dn0, off);
        dn1 += __shfl_xor_sync(0xffffffffu, dn1, off);
    }
    p0 /= dn0; p1 /= dn1;
    int hd = lane >> 3;
    int srcbase = (hd >> 1) * 16;
    int sel = hd & 1;
    float c0v = 0.f, c1v = 0.f;
#pragma unroll
    for (int tt = 0; tt < 16; tt++) {
        float pa = __shfl_sync(0xffffffffu, p0, srcbase + tt);
        float pb = __shfl_sync(0xffffffffu, p1, srcbase + tt);
        float pv = sel ? pb : pa;
        float2 v2 = __half22float2(*(const __half2*)&KVs[(lb * 16 + tt) * KVP_ + 64 + dcol]);
        c0v += pv * v2.x; c1v += pv * v2.y;
    }
    float o0 = bos[dcol], o1 = bos[dcol + 1];
#pragma unroll
    for (int jj = 0; jj < 32; jj++) {
        float ca = __shfl_sync(0xffffffffu, c0v, jj);
        float cb = __shfl_sync(0xffffffffu, c1v, jj);
        float2 wA = __half22float2(Wos2[(2 * jj) * 32 + lane]);
        float2 wB = __half22float2(Wos2[(2 * jj + 1) * 32 + lane]);
        o0 += ca * wA.x + cb * wB.x;
        o1 += ca * wA.y + cb * wB.y;
    }
    float r0v = ys[lb][dcol] + o0, r1v = ys[lb][dcol + 1] + o1;
    float su = r0v + r1v, s2 = r0v * r0v + r1v * r1v;
#pragma unroll
    for (int off = 1; off < 32; off <<= 1) {
        su += __shfl_xor_sync(0xffffffffu, su, off);
        s2 += __shfl_xor_sync(0xffffffffu, s2, off);
    }
    float mu = su * (1.f / 64.f);
    float var = s2 * (1.f / 64.f) - mu * mu;
    float inv = rsqrtf(var + 1e-5f);
    float2 z;
    z.x = (r0v - mu) * inv * g1s[dcol] + b1s[dcol];
    z.y = (r1v - mu) * inv * g1s[dcol + 1] + b1s[dcol + 1];
    *(float2*)&g_z[(size_t)r * 64 + dcol] = z;
}

// ---------------- fused FFN split-K(4) + last-block LN2 epilogue -------------
__global__ void __launch_bounds__(256) k_ffn(const float* __restrict__ b1,
                                             const float* __restrict__ b2,
                                             const float* __restrict__ ln2g,
                                             const float* __restrict__ ln2b,
                                             float* __restrict__ out) {
    __shared__ __half Ah[32 * SA_];
    __shared__ __half Sh[32 * SA_];
    __shared__ __half W1s[64 * SA_];
    __shared__ __half W2s[64 * SA_];
    __shared__ float b1s[512];
    __shared__ bool last_s;
    int tid = threadIdx.x, wid = tid >> 5, lane = tid & 31;
    int rb = blockIdx.x * 32;
    int kc0 = blockIdx.y * 512;
    for (int i = tid; i < 32 * 16; i += 256) {
        int r = i >> 4, s4 = i & 15;
        float4 v = *(const float4*)&g_z[((size_t)(rb + r)) * 64 + s4 * 4];
        HCvt h0, h1;
        h0.h2 = __floats2half2_rn(v.x, v.y);
        h1.h2 = __floats2half2_rn(v.z, v.w);
        *(uint2*)&Ah[r * SA_ + s4 * 4] = make_uint2(h0.u, h1.u);
    }
    for (int i = tid; i < 512; i += 256) b1s[i] = b1[kc0 + i];
    int mi = wid & 1, ni = wid >> 1;
    float o[2][4];
#pragma unroll
    for (int n8 = 0; n8 < 2; n8++)
#pragma unroll
        for (int q = 0; q < 4; q++) o[n8][q] = 0.f;
    int r0 = lane >> 2, c0 = (lane & 3) * 2;
    uint32_t a1base = su32(Ah) + ((mi * 16 + (lane & 15)) * SA_ + (lane >> 4) * 8) * 2;
    uint32_t a2base = su32(Sh) + ((mi * 16 + (lane & 15)) * SA_ + (lane >> 4) * 8) * 2;
    uint32_t w1base = su32(W1s) + (((lane & 15)) * SA_ + ni * 16 + (lane >> 4) * 8) * 2;
    uint32_t w2base = su32(W2s) + (((lane & 15)) * SA_ + ni * 16 + (lane >> 4) * 8) * 2;
    for (int cb = kc0; cb < kc0 + 512; cb += 64) {
        __syncthreads();
        for (int i = tid; i < 512; i += 256) {
            int r = i >> 3, s = i & 7;
            *(uint4*)&W1s[r * SA_ + s * 8] = *(const uint4*)&g_w1h[(size_t)r * FF_ + cb + s * 8];
            *(uint4*)&W2s[r * SA_ + s * 8] = *(const uint4*)&g_w2h[(size_t)(cb + r) * 64 + s * 8];
        }
        __syncthreads();
        float d[2][4];
#pragma unroll
        for (int n8 = 0; n8 < 2; n8++)
#pragma unroll
            for (int q = 0; q < 4; q++) d[n8][q] = 0.f;
#pragma unroll
        for (int k = 0; k < 4; k++) {
            uint32_t a0, a1, a2, a3, b0v, b1v, b2v, b3v;
            ldsm_x4(a0, a1, a2, a3, a1base + k * 32);
            ldsm_x4t(b0v, b1v, b2v, b3v, w1base + k * 16 * SA_ * 2);
            mma16816(d[0], a0, a1, a2, a3, b0v, b1v);
            mma16816(d[1], a0, a1, a2, a3, b2v, b3v);
        }
#pragma unroll
        for (int n8 = 0; n8 < 2; n8++) {
            int col = ni * 16 + n8 * 8 + c0;
            float bb0 = b1s[cb - kc0 + col], bb1 = b1s[cb - kc0 + col + 1];
            HCvt v0, v1;
            v0.h2 = __floats2half2_rn(fmaxf(d[n8][0] + bb0, 0.f), fmaxf(d[n8][1] + bb1, 0.f));
            v1.h2 = __floats2half2_rn(fmaxf(d[n8][2] + bb0, 0.f), fmaxf(d[n8][3] + bb1, 0.f));
            *(uint32_t*)&Sh[(mi * 16 + r0) * SA_ + col] = v0.u;
            *(uint32_t*)&Sh[(mi * 16 + r0 + 8) * SA_ + col] = v1.u;
        }
        __syncthreads();
#pragma unroll
        for (int k = 0; k < 4; k++) {
            uint32_t a0, a1, a2, a3, b0v, b1v, b2v, b3v;
            ldsm_x4(a0, a1, a2, a3, a2base + k * 32);
            ldsm_x4t(b0v, b1v, b2v, b3v, w2base + k * 16 * SA_ * 2);
            mma16816(o[0], a0, a1, a2, a3, b0v, b1v);
            mma16816(o[1], a0, a1, a2, a3, b2v, b3v);
        }
    }
    float* plane = g_acc[blockIdx.y];
#pragma unroll
    for (int n8 = 0; n8 < 2; n8++) {
        int col = ni * 16 + n8 * 8 + c0;
        *(float2*)&plane[(size_t)(rb + mi * 16 + r0) * 64 + col] = make_float2(o[n8][0], o[n8][1]);
        *(float2*)&plane[(size_t)(rb + mi * 16 + r0 + 8) * 64 + col] = make_float2(o[n8][2], o[n8][3]);
    }
    __threadfence();
    __syncthreads();
    if (tid == 0) {
        int old = atomicAdd(&g_cnt[blockIdx.x], 1);
        last_s = (old == 3);
        if (last_s) g_cnt[blockIdx.x] = 0;
    }
    __syncthreads();
    if (!last_s) return;
    int d2 = lane * 2;
    for (int rr = wid; rr < 32; rr += 8) {
        int r = rb + rr;
        float2 zr = *(const float2*)&g_z[(size_t)r * 64 + d2];
        float v0 = zr.x + b2[d2];
        float v1 = zr.y + b2[d2 + 1];
#pragma unroll
        for (int pp = 0; pp < 4; pp++) {
            float2 pv = *(const float2*)&g_acc[pp][(size_t)r * 64 + d2];
            v0 += pv.x; v1 += pv.y;
        }
        float su = v0 + v1, s2 = v0 * v0 + v1 * v1;
#pragma unroll
        for (int off = 1; off < 32; off <<= 1) {
            su += __shfl_xor_sync(0xffffffffu, su, off);
            s2 += __shfl_xor_sync(0xffffffffu, s2, off);
        }
        float mu = su * (1.f / 64.f);
        float var = s2 * (1.f / 64.f) - mu * mu;
        float inv = rsqrtf(var + 1e-5f);
        float2 oo;
        oo.x = (v0 - mu) * inv * ln2g[d2] + ln2b[d2];
        oo.y = (v1 - mu) * inv * ln2g[d2 + 1] + ln2b[d2 + 1];
        *(float2*)&out[(size_t)r * 64 + d2] = oo;
    }
}

// ---------------- launch (graph-parallel branches via fork-join) -------------
extern "C" void kernel_launch(void* const* d_in, const int* in_sizes, int n_in,
                              void* d_out, int out_size) {
    const float* x_seq    = (const float*)d_in[0];
    const int*   eidx     = (const int*)d_in[1];
    const float* eweight  = (const float*)d_in[2];
    const float* W_gat    = (const float*)d_in[3];
    const float* att_src  = (const float*)d_in[4];
    const float* att_dst  = (const float*)d_in[5];
    const float* W_edge   = (const float*)d_in[6];
    const float* att_edge = (const float*)d_in[7];
    const float* gat_bias = (const float*)d_in[8];
    const float* W_proj   = (const float*)d_in[9];
    const float* b_proj   = (const float*)d_in[10];
    const float* Wqkv     = (const float*)d_in[11];
    const float* bqkv     = (const float*)d_in[12];
    const float* Wo       = (const float*)d_in[13];
    const float* bo       = (const float*)d_in[14];
    const float* ln1_g    = (const float*)d_in[15];
    const float* ln1_b    = (const float*)d_in[16];
    const float* W1       = (const float*)d_in[17];
    const float* b1       = (const float*)d_in[18];
    const float* W2       = (const float*)d_in[19];
    const float* b2       = (const float*)d_in[20];
    const float* ln2_g    = (const float*)d_in[21];
    const float* ln2_b    = (const float*)d_in[22];
    float* out = (float*)d_out;

    static cudaStream_t sB = nullptr, sC = nullptr;
    static cudaEvent_t evRoot = nullptr, evB = nullptr, evC = nullptr;
    if (sB == nullptr) {
        cudaStreamCreateWithFlags(&sB, cudaStreamNonBlocking);
        cudaStreamCreateWithFlags(&sC, cudaStreamNonBlocking);
        cudaEventCreateWithFlags(&evRoot, cudaEventDisableTiming);
        cudaEventCreateWithFlags(&evB, cudaEventDisableTiming);
        cudaEventCreateWithFlags(&evC, cudaEventDisableTiming);
    }

    cudaEventRecord(evRoot, 0);
    cudaStreamWaitEvent(sB, evRoot, 0);
    cudaStreamWaitEvent(sC, evRoot, 0);

    // branch B: CSR build (feeds k_agg)
    k_hist<<<1, 1024, 0, sB>>>(eidx, eweight, W_edge, att_edge);
    k_scatter<<<(ET_ + 255) / 256, 256, 0, sB>>>(eidx);
    cudaEventRecord(evB, sB);

    // branch C: fp16 weight conversion
    k_cvt<<<512, 256, 0, sC>>>(Wqkv, W1, W2, Wo);
    cudaEventRecord(evC, sC);

    // main branch: node features
    k_h<<<GN_ / 8, 256>>>(x_seq, W_gat, att_src, att_dst);

    cudaStreamWaitEvent(0, evB, 0);
    k_agg<<<GN_ / 8, 256>>>(eidx, eweight, gat_bias, W_proj, b_proj);

    cudaStreamWaitEvent(0, evC, 0);
    k_attn_fused<<<BN_ / 4, 256>>>(bqkv, bo, ln1_g, ln1_b);
    {
        dim3 grid(BN_ / 32, 4);
        k_ffn<<<grid, 256>>>(b1, b2, ln2_g, ln2_b, out);
    }
}

// round 12
// speedup vs baseline: 2.4099x; 1.1405x over previous
#include <cuda_runtime.h>
#include <cuda_fp16.h>
#include <cstdint>

#define B_ 2
#define T_ 16
#define N_ 2000
#define F_ 16
#define E_ 32000
#define H_ 4
#define C_ 32
#define D_ 64
#define FF_ 2048
#define G_ (B_*T_)      /* 32  */
#define ET_ (E_+N_)     /* 34000 */
#define BN_ (B_*N_)     /* 4000 */
#define GN_ (G_*N_)     /* 64000 */

// ---------------- scratch (static device globals; no allocation) -------------
__device__ __half g_h[(size_t)GN_ * 128];  // h: [G,N,H*C] fp16
__device__ float g_asrc[GN_ * 4];
__device__ float g_adst[GN_ * 4];
__device__ float g_prep[8];               // c_edge[0..3], ew_mean at [4]
__device__ int   g_off[N_ + 1];
__device__ int   g_cur[N_];
__device__ int   g_csr[ET_];
__device__ __half g_y[GN_ * D_];          // fp16 [bn][t][d]  (row rn = bn*16+t)
__device__ float g_z[BN_ * D_];           // post-LN1
__device__ __half g_wkvh[64 * 128];       // fp16 Wqkv[:,64:192]
__device__ __half g_wqh[64 * 64];         // fp16 Wqkv[:,0:64]
__device__ __half g_woh[64 * 64];         // fp16 Wo
__device__ __half g_w1h[64 * FF_];        // fp16 W1
__device__ __half g_w2h[FF_ * 64];        // fp16 W2
__device__ float g_acc[4][BN_ * D_];      // ffn split-K planes
__device__ int   g_cnt[BN_ / 32];         // per-row-block completion counters

union HCvt { __half2 h2; uint32_t u; };

// ---------------- mma helpers ------------------------------------------------
__device__ __forceinline__ uint32_t su32(const void* p) {
    uint32_t a;
    asm("{ .reg .u64 t; cvta.to.shared.u64 t, %1; cvt.u32.u64 %0, t; }" : "=r"(a) : "l"(p));
    return a;
}
__device__ __forceinline__ void ldsm_x4(uint32_t& r0, uint32_t& r1, uint32_t& r2, uint32_t& r3, uint32_t a) {
    asm volatile("ldmatrix.sync.aligned.m8n8.x4.shared.b16 {%0,%1,%2,%3}, [%4];"
                 : "=r"(r0), "=r"(r1), "=r"(r2), "=r"(r3) : "r"(a));
}
__device__ __forceinline__ void ldsm_x4t(uint32_t& r0, uint32_t& r1, uint32_t& r2, uint32_t& r3, uint32_t a) {
    asm volatile("ldmatrix.sync.aligned.m8n8.x4.trans.shared.b16 {%0,%1,%2,%3}, [%4];"
                 : "=r"(r0), "=r"(r1), "=r"(r2), "=r"(r3) : "r"(a));
}
__device__ __forceinline__ void mma16816(float* d, uint32_t a0, uint32_t a1, uint32_t a2, uint32_t a3,
                                         uint32_t b0, uint32_t b1) {
    asm volatile("mma.sync.aligned.m16n8k16.row.col.f32.f16.f16.f32 "
                 "{%0,%1,%2,%3}, {%4,%5,%6,%7}, {%8,%9}, {%0,%1,%2,%3};"
                 : "+f"(d[0]), "+f"(d[1]), "+f"(d[2]), "+f"(d[3])
                 : "r"(a0), "r"(a1), "r"(a2), "r"(a3), "r"(b0), "r"(b1));
}

// ---------------- weight conversion to fp16 ----------------------------------
__global__ void k_cvt(const float* __restrict__ Wqkv, const float* __restrict__ W1,
                      const float* __restrict__ W2, const float* __restrict__ Wo) {
    int i = blockIdx.x * 256 + threadIdx.x;
    if (i < 64 * 128) {
        int k = i >> 7, c = i & 127;
        g_wkvh[i] = __float2half(Wqkv[k * 192 + 64 + c]);
    }
    if (i < 64 * 64) {
        int k = i >> 6, c = i & 63;
        g_wqh[i] = __float2half(Wqkv[k * 192 + c]);
        g_woh[i] = __float2half(Wo[i]);
    }
    if (i < 64 * FF_) {
        g_w1h[i] = __float2half(W1[i]);
        g_w2h[i] = __float2half(W2[i]);
    }
}

// ---------------- hist + scan + edge consts (one kernel) ---------------------
__global__ void k_hist(const int* __restrict__ ei, const float* __restrict__ ew,
                       const float* __restrict__ W_edge,
                       const float* __restrict__ att_edge) {
    __shared__ int hist[2048];
    __shared__ float red[1024];
    __shared__ int ws[32];
    int t = threadIdx.x;
    hist[t] = 0; hist[t + 1024] = 0;
    __syncthreads();
    float s = 0.f;
    for (int i = t; i < ET_; i += 1024) {
        int d;
        if (i < E_) { d = ei[E_ + i]; s += ew[i]; }
        else d = i - E_;
        atomicAdd(&hist[d], 1);
    }
    red[t] = s;
    __syncthreads();
    for (int o = 512; o > 0; o >>= 1) {
        if (t < o) red[t] += red[t + o];
        __syncthreads();
    }
    if (t == 0) g_prep[4] = red[0] / (float)E_;
    if (t < 4) {
        float c = 0.f;
        for (int j = 0; j < 32; j++) c += W_edge[t * 32 + j] * att_edge[t * 32 + j];
        g_prep[t] = c;
    }
    int i0 = 2 * t, i1 = 2 * t + 1;
    int a = (i0 < N_) ? hist[i0] : 0;
    int b = (i1 < N_) ? hist[i1] : 0;
    int v = a + b;
    int lane = t & 31, wid = t >> 5;
#pragma unroll
    for (int off = 1; off < 32; off <<= 1) {
        int n = __shfl_up_sync(0xffffffffu, v, off);
        if (lane >= off) v += n;
    }
    if (lane == 31) ws[wid] = v;
    __syncthreads();
    if (t < 32) {
        int u = ws[t];
#pragma unroll
        for (int off = 1; off < 32; off <<= 1) {
            int n = __shfl_up_sync(0xffffffffu, u, off);
            if (t >= off) u += n;
        }
        ws[t] = u;
    }
    __syncthreads();
    int base = (wid > 0) ? ws[wid - 1] : 0;
    int incl = v + base;
    int ex0 = incl - a - b;
    if (i0 <= N_) { g_off[i0] = ex0; if (i0 < N_) g_cur[i0] = ex0; }
    if (i1 <= N_) { g_off[i1] = ex0 + a; if (i1 < N_) g_cur[i1] = ex0 + a; }
}

__global__ void k_scatter(const int* __restrict__ ei) {
    int e = blockIdx.x * blockDim.x + threadIdx.x;
    if (e >= ET_) return;
    int d = (e < E_) ? ei[E_ + e] : (e - E_);
    int pos = atomicAdd(&g_cur[d], 1);
    g_csr[pos] = e;
}

// ---------------- h = x @ W_gat via HMMA; asrc/adst from fragments -----------
#define XA_ 24
#define XB_ 136
__global__ void __launch_bounds__(256) k_h(const float* __restrict__ x,
                                           const float* __restrict__ Wg,
                                           const float* __restrict__ as_w,
                                           const float* __restrict__ ad_w) {
    __shared__ __half xs[64 * XA_];
    __shared__ __half Bs[16 * XB_];
    __shared__ float s_as[128], s_ad[128];
    int tid = threadIdx.x, wid = tid >> 5, lane = tid & 31;
    int rb = blockIdx.x * 64;
    // stage x rows (fp32 -> fp16)
    for (int i = tid; i < 256; i += 256) {
        int r = i >> 2, s4 = i & 3;
        float4 v = *(const float4*)&x[((size_t)(rb + r)) * 16 + s4 * 4];
        HCvt h0, h1;
        h0.h2 = __floats2half2_rn(v.x, v.y);
        h1.h2 = __floats2half2_rn(v.z, v.w);
        *(uint2*)&xs[r * XA_ + s4 * 4] = make_uint2(h0.u, h1.u);
    }
    // stage W_gat (fp32 -> fp16) and att vectors
    for (int i = tid; i < 512; i += 256) {
        int r = i >> 5, c4 = i & 31;
        float4 v = *(const float4*)&Wg[r * 128 + c4 * 4];
        HCvt h0, h1;
        h0.h2 = __floats2half2_rn(v.x, v.y);
        h1.h2 = __floats2half2_rn(v.z, v.w);
        *(uint2*)&Bs[r * XB_ + c4 * 4] = make_uint2(h0.u, h1.u);
    }
    if (tid < 128) { s_as[tid] = as_w[tid]; s_ad[tid] = ad_w[tid]; }
    __syncthreads();
    int mi = wid >> 1;            // m16 tile 0..3
    int nb = (wid & 1) * 64;      // n base
    float o[4][2][4];
#pragma unroll
    for (int j = 0; j < 4; j++)
#pragma unroll
        for (int n8 = 0; n8 < 2; n8++)
#pragma unroll
            for (int q = 0; q < 4; q++) o[j][n8][q] = 0.f;
    {
        uint32_t abase = su32(xs) + ((mi * 16 + (lane & 15)) * XA_ + (lane >> 4) * 8) * 2;
        uint32_t bbase = su32(Bs) + (((lane & 15)) * XB_ + nb + (lane >> 4) * 8) * 2;
        uint32_t a0, a1, a2, a3;
        ldsm_x4(a0, a1, a2, a3, abase);
#pragma unroll
        for (int j = 0; j < 4; j++) {
            uint32_t b0, b1, b2, b3;
            ldsm_x4t(b0, b1, b2, b3, bbase + (j * 16) * 2);
            mma16816(o[j][0], a0, a1, a2, a3, b0, b1);
            mma16816(o[j][1], a0, a1, a2, a3, b2, b3);
        }
    }
    // epilogue: store h fp16 + per-head attn dots
    int r0 = lane >> 2, c0 = (lane & 3) * 2;
    float vs[2][2] = {{0.f, 0.f}, {0.f, 0.f}};   // [hm][head-within-warp]
    float vd[2][2] = {{0.f, 0.f}, {0.f, 0.f}};
#pragma unroll
    for (int j = 0; j < 4; j++)
#pragma unroll
        for (int n8 = 0; n8 < 2; n8++) {
            int col = nb + j * 16 + n8 * 8 + c0;
            float a0c = s_as[col], a1c = s_as[col + 1];
            float d0c = s_ad[col], d1c = s_ad[col + 1];
            int hj = j >> 1;
#pragma unroll
            for (int hm = 0; hm < 2; hm++) {
                float e0 = o[j][n8][hm * 2 + 0];
                float e1 = o[j][n8][hm * 2 + 1];
                vs[hm][hj] += e0 * a0c + e1 * a1c;
                vd[hm][hj] += e0 * d0c + e1 * d1c;
                int row = rb + mi * 16 + r0 + hm * 8;
                HCvt v; v.h2 = __floats2half2_rn(e0, e1);
                *(uint32_t*)&g_h[(size_t)row * 128 + col] = v.u;
            }
        }
#pragma unroll
    for (int hm = 0; hm < 2; hm++)
#pragma unroll
        for (int hj = 0; hj < 2; hj++) {
            vs[hm][hj] += __shfl_xor_sync(0xffffffffu, vs[hm][hj], 1);
            vs[hm][hj] += __shfl_xor_sync(0xffffffffu, vs[hm][hj], 2);
            vd[hm][hj] += __shfl_xor_sync(0xffffffffu, vd[hm][hj], 1);
            vd[hm][hj] += __shfl_xor_sync(0xffffffffu, vd[hm][hj], 2);
        }
    if ((lane & 3) == 0) {
        int hb = (nb >> 5);       // 0 or 2
#pragma unroll
        for (int hm = 0; hm < 2; hm++) {
            int row = rb + mi * 16 + r0 + hm * 8;
#pragma unroll
            for (int hj = 0; hj < 2; hj++) {
                g_asrc[(size_t)row * 4 + hb + hj] = vs[hm][hj];
                g_adst[(size_t)row * 4 + hb + hj] = vd[hm][hj];
            }
        }
    }
}

// ---------------- GAT aggregate v3: FOUR edges/warp, 16 ch/lane --------------
__global__ void __launch_bounds__(256) k_agg(const int* __restrict__ ei,
                                             const float* __restrict__ ew,
                                             const float* __restrict__ gbias,
                                             const float* __restrict__ Wp,
                                             const float* __restrict__ bp) {
    __shared__ float Wps[32 * 64];
    __shared__ float bias_s[32];
    __shared__ float bp_s[64];
    __shared__ float ce_s[4];
    __shared__ float ewm_sh;
    __shared__ float sog[8][32];
    int tid = threadIdx.x;
    for (int i = tid; i < 2048; i += 256) Wps[i] = Wp[i];
    if (tid < 32) bias_s[tid] = gbias[tid];
    if (tid < 64) bp_s[tid] = bp[tid];
    if (tid < 4)  ce_s[tid] = g_prep[tid];
    if (tid == 8) ewm_sh = g_prep[4];
    __syncthreads();
    int wid = tid >> 5;
    int w = blockIdx.x * 8 + wid;
    float ewm_s = ewm_sh;
    int lane = tid & 31;
    int grp = lane >> 3;
    int ll = lane & 7;
    int hd = ll >> 1;
    int g = w / N_;
    int dst = w - g * N_;
    float ad = g_adst[((size_t)g * N_ + dst) * 4 + hd];
    float ce = ce_s[hd];
    float acc[16];
#pragma unroll
    for (int j = 0; j < 16; j++) acc[j] = 0.f;
    float den = 0.f;
    int beg = g_off[dst], end = g_off[dst + 1];
    const __half* hbase = g_h + (size_t)g * N_ * 128;
    const float* abase = g_asrc + (size_t)g * N_ * 4;
    int i = beg + grp;
    bool v = (i < end);
    int e0 = v ? g_csr[i] : 0;
    int s; float wgt;
    if (e0 < E_) { s = ei[e0]; wgt = ew[e0]; } else { s = e0 - E_; wgt = ewm_s; }
    float as = abase[s * 4 + hd];
    uint4 h0 = *(const uint4*)(hbase + (size_t)s * 128 + ll * 16);
    uint4 h1 = *(const uint4*)(hbase + (size_t)s * 128 + ll * 16 + 8);
    int cnt = (end - beg + 3) >> 2;
    for (int it = 0; it < cnt; it++) {
        int in_ = i + 4;
        bool vn = (in_ < end);
        int en = vn ? g_csr[in_] : 0;
        int sn; float wn;
        if (en < E_) { sn = ei[en]; wn = ew[en]; } else { sn = en - E_; wn = ewm_s; }
        float asn = abase[sn * 4 + hd];
        uint4 hn0 = *(const uint4*)(hbase + (size_t)sn * 128 + ll * 16);
        uint4 hn1 = *(const uint4*)(hbase + (size_t)sn * 128 + ll * 16 + 8);
        float lg = as + ad + ce * wgt;
        lg = (lg > 0.f) ? lg : 0.2f * lg;
        float p = v ? __expf(lg) : 0.f;
        den += p;
        const uint32_t* hw0 = &h0.x;
        const uint32_t* hw1 = &h1.x;
#pragma unroll
        for (int j2 = 0; j2 < 4; j2++) {
            float2 f0 = __half22float2(*(const __half2*)&hw0[j2]);
            float2 f1 = __half22float2(*(const __half2*)&hw1[j2]);
            acc[j2 * 2 + 0] += p * f0.x;
            acc[j2 * 2 + 1] += p * f0.y;
            acc[8 + j2 * 2 + 0] += p * f1.x;
            acc[8 + j2 * 2 + 1] += p * f1.y;
        }
        i = in_; v = vn; s = sn; wgt = wn; as = asn; h0 = hn0; h1 = hn1;
    }
    den += __shfl_xor_sync(0xffffffffu, den, 8);
    den += __shfl_xor_sync(0xffffffffu, den, 16);
    float inv = 1.f / (den + 1e-16f);
#pragma unroll
    for (int j = 0; j < 16; j++) {
        acc[j] += __shfl_xor_sync(0xffffffffu, acc[j], 8);
        acc[j] += __shfl_xor_sync(0xffffffffu, acc[j], 16);
        acc[j] *= inv;
        acc[j] += __shfl_xor_sync(0xffffffffu, acc[j], 2);
        acc[j] += __shfl_xor_sync(0xffffffffu, acc[j], 4);
        acc[j] = acc[j] * 0.25f + bias_s[(ll & 1) * 16 + j];
    }
    if (lane < 2) {
#pragma unroll
        for (int j = 0; j < 16; j++) sog[wid][lane * 16 + j] = acc[j];
    }
    __syncwarp();
    int d0 = lane * 2;
    float y0 = bp_s[d0], y1 = bp_s[d0 + 1];
#pragma unroll
    for (int c = 0; c < 32; c++) {
        float vv = sog[wid][c];
        float2 wv = *(const float2*)&Wps[c * 64 + d0];
        y0 += vv * wv.x; y1 += vv * wv.y;
    }
    int b = g >> 4;
    int t = g & 15;
    HCvt yo; yo.h2 = __floats2half2_rn(y0, y1);
    *(uint32_t*)&g_y[(((size_t)(b * N_ + dst)) * T_ + t) * D_ + d0] = yo.u;
}

// ---------------- fused KV-MMA + attention + Wo + residual + LN1 -------------
#define SA_ 72
#define SB_ 136
#define KVP_ 136
__global__ void __launch_bounds__(256) k_attn_fused(const float* __restrict__ bqkv,
                                                    const float* __restrict__ bo,
                                                    const float* __restrict__ ln1g,
                                                    const float* __restrict__ ln1b) {
    __shared__ __half AB[64 * SA_ + 64 * SB_];
    __shared__ float bqs[128];
    __shared__ __half2 Wqs2[64 * 32];
    __shared__ __half2 Wos2[64 * 32];
    __shared__ float bos[64], g1s[64], b1s[64], bq0[64];
    __shared__ float ys[4][64];
    __shared__ float sq[4][64];
    __half* Ah = AB;
    __half* Bs = AB + 64 * SA_;
    __half* KVs = AB;
    int tid = threadIdx.x, wid = tid >> 5, lane = tid & 31;
    int rb = blockIdx.x * 64;
    for (int i = tid; i < 512; i += 256) {
        int r = i >> 3, s = i & 7;
        *(uint4*)&Ah[r * SA_ + s * 8] = *(const uint4*)&g_y[((size_t)(rb + r)) * 64 + s * 8];
    }
    for (int i = tid; i < 1024; i += 256) {
        int r = i >> 4, s = i & 15;
        *(uint4*)&Bs[r * SB_ + s * 8] = *(const uint4*)&g_wkvh[r * 128 + s * 8];
    }
    for (int i = tid; i < 512; i += 256) {
        ((uint4*)Wos2)[i] = ((const uint4*)g_woh)[i];
        ((uint4*)Wqs2)[i] = ((const uint4*)g_wqh)[i];
    }
    if (tid < 128) bqs[tid] = bqkv[64 + tid];
    if (tid < 64) { bos[tid] = bo[tid]; g1s[tid] = ln1g[tid]; b1s[tid] = ln1b[tid]; bq0[tid] = bqkv[tid]; }
    __syncthreads();
    int mi = wid >> 1;
    int nb = (wid & 1) * 64;
    float o[4][2][4];
#pragma unroll
    for (int j = 0; j < 4; j++)
#pragma unroll
        for (int n8 = 0; n8 < 2; n8++)
#pragma unroll
            for (int q = 0; q < 4; q++) o[j][n8][q] = 0.f;
    {
        uint32_t abase = su32(Ah) + ((mi * 16 + (lane & 15)) * SA_ + (lane >> 4) * 8) * 2;
        uint32_t bbase = su32(Bs) + (((lane & 15)) * SB_ + nb + (lane >> 4) * 8) * 2;
#pragma unroll
        for (int k = 0; k < 4; k++) {
            uint32_t a0, a1, a2, a3;
            ldsm_x4(a0, a1, a2, a3, abase + k * 32);
#pragma unroll
            for (int j = 0; j < 4; j++) {
                uint32_t b0, b1, b2, b3;
                ldsm_x4t(b0, b1, b2, b3, bbase + (k * 16 * SB_ + j * 16) * 2);
                mma16816(o[j][0], a0, a1, a2, a3, b0, b1);
                mma16816(o[j][1], a0, a1, a2, a3, b2, b3);
            }
        }
    }
    __syncthreads();
    {
        int r0 = lane >> 2, c0 = (lane & 3) * 2;
#pragma unroll
        for (int j = 0; j < 4; j++)
#pragma unroll
            for (int n8 = 0; n8 < 2; n8++)
#pragma unroll
                for (int hm = 0; hm < 2; hm++) {
                    int row = mi * 16 + r0 + hm * 8;
                    int col = nb + j * 16 + n8 * 8 + c0;
                    HCvt v; v.h2 = __floats2half2_rn(o[j][n8][hm * 2 + 0] + bqs[col],
                                                     o[j][n8][hm * 2 + 1] + bqs[col + 1]);
                    *(uint32_t*)&KVs[row * KVP_ + col] = v.u;
                }
    }
    __syncthreads();
    if (wid >= 4) return;
    int r = blockIdx.x * 4 + wid;
    int lb = wid;
    int dcol = lane * 2;
    __half2 yh = *(const __half2*)&g_y[((size_t)(r * 16 + 15)) * 64 + dcol];
    float2 yv = __half22float2(yh);
    ys[lb][dcol] = yv.x; ys[lb][dcol + 1] = yv.y;
    __syncwarp();
    float q0 = bq0[dcol], q1 = bq0[dcol + 1];
#pragma unroll 16
    for (int j = 0; j < 64; j++) {
        float yj = ys[lb][j];
        float2 wv = __half22float2(Wqs2[j * 32 + lane]);
        q0 += yj * wv.x; q1 += yj * wv.y;
    }
    sq[lb][dcol] = q0; sq[lb][dcol + 1] = q1;
    __syncwarp();
    int t = lane & 15, grp = lane >> 4;
    const __half* kbase = &KVs[(lb * 16 + t) * KVP_ + grp * 32];
    const float* qq = &sq[lb][grp * 32];
    uint4 kr0 = *(const uint4*)&kbase[0];
    uint4 kr1 = *(const uint4*)&kbase[8];
    uint4 kr2 = *(const uint4*)&kbase[16];
    uint4 kr3 = *(const uint4*)&kbase[24];
    float s0 = 0.f, s1 = 0.f;
    {
        const uint32_t* kw0 = &kr0.x;
        const uint32_t* kw1 = &kr1.x;
#pragma unroll
        for (int j2 = 0; j2 < 4; j2++) {
            float2 f0 = __half22float2(*(const __half2*)&kw0[j2]);
            float2 f1 = __half22float2(*(const __half2*)&kw1[j2]);
            s0 += qq[j2 * 2 + 0] * f0.x + qq[j2 * 2 + 1] * f0.y;
            s0 += qq[8 + j2 * 2 + 0] * f1.x + qq[8 + j2 * 2 + 1] * f1.y;
        }
        const uint32_t* kw2 = &kr2.x;
        const uint32_t* kw3 = &kr3.x;
#pragma unroll
        for (int j2 = 0; j2 < 4; j2++) {
            float2 f2 = __half22float2(*(const __half2*)&kw2[j2]);
            float2 f3 = __half22float2(*(const __half2*)&kw3[j2]);
            s1 += qq[16 + j2 * 2 + 0] * f2.x + qq[16 + j2 * 2 + 1] * f2.y;
            s1 += qq[24 + j2 * 2 + 0] * f3.x + qq[24 + j2 * 2 + 1] * f3.y;
        }
    }
    s0 *= 0.25f; s1 *= 0.25f;
    float m0 = s0, m1 = s1;
#pragma unroll
    for (int off = 1; off < 16; off <<= 1) {
        m0 = fmaxf(m0, __shfl_xor_sync(0xffffffffu, m0, off));
        m1 = fmaxf(m1, __shfl_xor_sync(0xffffffffu, m1, off));
    }
    float p0 = __expf(s0 - m0), p1 = __expf(s1 - m1);
    float dn0 = p0, dn1 = p1;
#pragma unroll
    for (int off = 1; off < 16; off <<= 1) {
        dn0 += __shfl_xor_sync(0xffffffffu, dn0, off);
        dn1 += __shfl_xor_sync(0xffffffffu, dn1, off);
    }
    p0 /= dn0; p1 /= dn1;
    int hd = lane >> 3;
    int srcbase = (hd >> 1) * 16;
    int sel = hd & 1;
    float c0v = 0.f, c1v = 0.f;
#pragma unroll
    for (int tt = 0; tt < 16; tt++) {
        float pa = __shfl_sync(0xffffffffu, p0, srcbase + tt);
        float pb = __shfl_sync(0xffffffffu, p1, srcbase + tt);
        float pv = sel ? pb : pa;
        float2 v2 = __half22float2(*(const __half2*)&KVs[(lb * 16 + tt) * KVP_ + 64 + dcol]);
        c0v += pv * v2.x; c1v += pv * v2.y;
    }
    float o0 = bos[dcol], o1 = bos[dcol + 1];
#pragma unroll
    for (int jj = 0; jj < 32; jj++) {
        float ca = __shfl_sync(0xffffffffu, c0v, jj);
        float cb = __shfl_sync(0xffffffffu, c1v, jj);
        float2 wA = __half22float2(Wos2[(2 * jj) * 32 + lane]);
        float2 wB = __half22float2(Wos2[(2 * jj + 1) * 32 + lane]);
        o0 += ca * wA.x + cb * wB.x;
        o1 += ca * wA.y + cb * wB.y;
    }
    float r0v = ys[lb][dcol] + o0, r1v = ys[lb][dcol + 1] + o1;
    float su = r0v + r1v, s2 = r0v * r0v + r1v * r1v;
#pragma unroll
    for (int off = 1; off < 32; off <<= 1) {
        su += __shfl_xor_sync(0xffffffffu, su, off);
        s2 += __shfl_xor_sync(0xffffffffu, s2, off);
    }
    float mu = su * (1.f / 64.f);
    float var = s2 * (1.f / 64.f) - mu * mu;
    float inv = rsqrtf(var + 1e-5f);
    float2 z;
    z.x = (r0v - mu) * inv * g1s[dcol] + b1s[dcol];
    z.y = (r1v - mu) * inv * g1s[dcol + 1] + b1s[dcol + 1];
    *(float2*)&g_z[(size_t)r * 64 + dcol] = z;
}

// ---------------- fused FFN split-K(4) + last-block LN2 epilogue -------------
__global__ void __launch_bounds__(256) k_ffn(const float* __restrict__ b1,
                                             const float* __restrict__ b2,
                                             const float* __restrict__ ln2g,
                                             const float* __restrict__ ln2b,
                                             float* __restrict__ out) {
    __shared__ __half Ah[32 * SA_];
    __shared__ __half Sh[32 * SA_];
    __shared__ __half W1s[64 * SA_];
    __shared__ __half W2s[64 * SA_];
    __shared__ float b1s[512];
    __shared__ bool last_s;
    int tid = threadIdx.x, wid = tid >> 5, lane = tid & 31;
    int rb = blockIdx.x * 32;
    int kc0 = blockIdx.y * 512;
    for (int i = tid; i < 32 * 16; i += 256) {
        int r = i >> 4, s4 = i & 15;
        float4 v = *(const float4*)&g_z[((size_t)(rb + r)) * 64 + s4 * 4];
        HCvt h0, h1;
        h0.h2 = __floats2half2_rn(v.x, v.y);
        h1.h2 = __floats2half2_rn(v.z, v.w);
        *(uint2*)&Ah[r * SA_ + s4 * 4] = make_uint2(h0.u, h1.u);
    }
    for (int i = tid; i < 512; i += 256) b1s[i] = b1[kc0 + i];
    int mi = wid & 1, ni = wid >> 1;
    float o[2][4];
#pragma unroll
    for (int n8 = 0; n8 < 2; n8++)
#pragma unroll
        for (int q = 0; q < 4; q++) o[n8][q] = 0.f;
    int r0 = lane >> 2, c0 = (lane & 3) * 2;
    uint32_t a1base = su32(Ah) + ((mi * 16 + (lane & 15)) * SA_ + (lane >> 4) * 8) * 2;
    uint32_t a2base = su32(Sh) + ((mi * 16 + (lane & 15)) * SA_ + (lane >> 4) * 8) * 2;
    uint32_t w1base = su32(W1s) + (((lane & 15)) * SA_ + ni * 16 + (lane >> 4) * 8) * 2;
    uint32_t w2base = su32(W2s) + (((lane & 15)) * SA_ + ni * 16 + (lane >> 4) * 8) * 2;
    for (int cb = kc0; cb < kc0 + 512; cb += 64) {
        __syncthreads();
        for (int i = tid; i < 512; i += 256) {
            int r = i >> 3, s = i & 7;
            *(uint4*)&W1s[r * SA_ + s * 8] = *(const uint4*)&g_w1h[(size_t)r * FF_ + cb + s * 8];
            *(uint4*)&W2s[r * SA_ + s * 8] = *(const uint4*)&g_w2h[(size_t)(cb + r) * 64 + s * 8];
        }
        __syncthreads();
        float d[2][4];
#pragma unroll
        for (int n8 = 0; n8 < 2; n8++)
#pragma unroll
            for (int q = 0; q < 4; q++) d[n8][q] = 0.f;
#pragma unroll
        for (int k = 0; k < 4; k++) {
            uint32_t a0, a1, a2, a3, b0v, b1v, b2v, b3v;
            ldsm_x4(a0, a1, a2, a3, a1base + k * 32);
            ldsm_x4t(b0v, b1v, b2v, b3v, w1base + k * 16 * SA_ * 2);
            mma16816(d[0], a0, a1, a2, a3, b0v, b1v);
            mma16816(d[1], a0, a1, a2, a3, b2v, b3v);
        }
#pragma unroll
        for (int n8 = 0; n8 < 2; n8++) {
            int col = ni * 16 + n8 * 8 + c0;
            float bb0 = b1s[cb - kc0 + col], bb1 = b1s[cb - kc0 + col + 1];
            HCvt v0, v1;
            v0.h2 = __floats2half2_rn(fmaxf(d[n8][0] + bb0, 0.f), fmaxf(d[n8][1] + bb1, 0.f));
            v1.h2 = __floats2half2_rn(fmaxf(d[n8][2] + bb0, 0.f), fmaxf(d[n8][3] + bb1, 0.f));
            *(uint32_t*)&Sh[(mi * 16 + r0) * SA_ + col] = v0.u;
            *(uint32_t*)&Sh[(mi * 16 + r0 + 8) * SA_ + col] = v1.u;
        }
        __syncthreads();
#pragma unroll
        for (int k = 0; k < 4; k++) {
            uint32_t a0, a1, a2, a3, b0v, b1v, b2v, b3v;
            ldsm_x4(a0, a1, a2, a3, a2base + k * 32);
            ldsm_x4t(b0v, b1v, b2v, b3v, w2base + k * 16 * SA_ * 2);
            mma16816(o[0], a0, a1, a2, a3, b0v, b1v);
            mma16816(o[1], a0, a1, a2, a3, b2v, b3v);
        }
    }
    float* plane = g_acc[blockIdx.y];
#pragma unroll
    for (int n8 = 0; n8 < 2; n8++) {
        int col = ni * 16 + n8 * 8 + c0;
        *(float2*)&plane[(size_t)(rb + mi * 16 + r0) * 64 + col] = make_float2(o[n8][0], o[n8][1]);
        *(float2*)&plane[(size_t)(rb + mi * 16 + r0 + 8) * 64 + col] = make_float2(o[n8][2], o[n8][3]);
    }
    __threadfence();
    __syncthreads();
    if (tid == 0) {
        int old = atomicAdd(&g_cnt[blockIdx.x], 1);
        last_s = (old == 3);
        if (last_s) g_cnt[blockIdx.x] = 0;
    }
    __syncthreads();
    if (!last_s) return;
    int d2 = lane * 2;
    for (int rr = wid; rr < 32; rr += 8) {
        int r = rb + rr;
        float2 zr = *(const float2*)&g_z[(size_t)r * 64 + d2];
        float v0 = zr.x + b2[d2];
        float v1 = zr.y + b2[d2 + 1];
#pragma unroll
        for (int pp = 0; pp < 4; pp++) {
            float2 pv = *(const float2*)&g_acc[pp][(size_t)r * 64 + d2];
            v0 += pv.x; v1 += pv.y;
        }
        float su = v0 + v1, s2 = v0 * v0 + v1 * v1;
#pragma unroll
        for (int off = 1; off < 32; off <<= 1) {
            su += __shfl_xor_sync(0xffffffffu, su, off);
            s2 += __shfl_xor_sync(0xffffffffu, s2, off);
        }
        float mu = su * (1.f / 64.f);
        float var = s2 * (1.f / 64.f) - mu * mu;
        float inv = rsqrtf(var + 1e-5f);
        float2 oo;
        oo.x = (v0 - mu) * inv * ln2g[d2] + ln2b[d2];
        oo.y = (v1 - mu) * inv * ln2g[d2 + 1] + ln2b[d2 + 1];
        *(float2*)&out[(size_t)r * 64 + d2] = oo;
    }
}

// ---------------- launch (graph-parallel branches via fork-join) -------------
extern "C" void kernel_launch(void* const* d_in, const int* in_sizes, int n_in,
                              void* d_out, int out_size) {
    const float* x_seq    = (const float*)d_in[0];
    const int*   eidx     = (const int*)d_in[1];
    const float* eweight  = (const float*)d_in[2];
    const float* W_gat    = (const float*)d_in[3];
    const float* att_src  = (const float*)d_in[4];
    const float* att_dst  = (const float*)d_in[5];
    const float* W_edge   = (const float*)d_in[6];
    const float* att_edge = (const float*)d_in[7];
    const float* gat_bias = (const float*)d_in[8];
    const float* W_proj   = (const float*)d_in[9];
    const float* b_proj   = (const float*)d_in[10];
    const float* Wqkv     = (const float*)d_in[11];
    const float* bqkv     = (const float*)d_in[12];
    const float* Wo       = (const float*)d_in[13];
    const float* bo       = (const float*)d_in[14];
    const float* ln1_g    = (const float*)d_in[15];
    const float* ln1_b    = (const float*)d_in[16];
    const float* W1       = (const float*)d_in[17];
    const float* b1       = (const float*)d_in[18];
    const float* W2       = (const float*)d_in[19];
    const float* b2       = (const float*)d_in[20];
    const float* ln2_g    = (const float*)d_in[21];
    const float* ln2_b    = (const float*)d_in[22];
    float* out = (float*)d_out;

    static cudaStream_t sB = nullptr, sC = nullptr;
    static cudaEvent_t evRoot = nullptr, evB = nullptr, evC = nullptr;
    if (sB == nullptr) {
        cudaStreamCreateWithFlags(&sB, cudaStreamNonBlocking);
        cudaStreamCreateWithFlags(&sC, cudaStreamNonBlocking);
        cudaEventCreateWithFlags(&evRoot, cudaEventDisableTiming);
        cudaEventCreateWithFlags(&evB, cudaEventDisableTiming);
        cudaEventCreateWithFlags(&evC, cudaEventDisableTiming);
    }

    cudaEventRecord(evRoot, 0);
    cudaStreamWaitEvent(sB, evRoot, 0);
    cudaStreamWaitEvent(sC, evRoot, 0);

    // branch B: CSR build (feeds k_agg)
    k_hist<<<1, 1024, 0, sB>>>(eidx, eweight, W_edge, att_edge);
    k_scatter<<<(ET_ + 255) / 256, 256, 0, sB>>>(eidx);
    cudaEventRecord(evB, sB);

    // branch C: fp16 weight conversion
    k_cvt<<<512, 256, 0, sC>>>(Wqkv, W1, W2, Wo);
    cudaEventRecord(evC, sC);

    // main branch: node features via HMMA
    k_h<<<GN_ / 64, 256>>>(x_seq, W_gat, att_src, att_dst);

    cudaStreamWaitEvent(0, evB, 0);
    k_agg<<<GN_ / 8, 256>>>(eidx, eweight, gat_bias, W_proj, b_proj);

    cudaStreamWaitEvent(0, evC, 0);
    k_attn_fused<<<BN_ / 4, 256>>>(bqkv, bo, ln1_g, ln1_b);
    {
        dim3 grid(BN_ / 32, 4);
        k_ffn<<<grid, 256>>>(b1, b2, ln2_g, ln2_b, out);
    }
}

// round 13
// speedup vs baseline: 2.5207x; 1.0460x over previous
#include <cuda_runtime.h>
#include <cuda_fp16.h>
#include <cstdint>

#define B_ 2
#define T_ 16
#define N_ 2000
#define F_ 16
#define E_ 32000
#define H_ 4
#define C_ 32
#define D_ 64
#define FF_ 2048
#define G_ (B_*T_)      /* 32  */
#define ET_ (E_+N_)     /* 34000 */
#define BN_ (B_*N_)     /* 4000 */
#define BNP_ (BN_+64)   /* padded rows for 64-row ffn tiles */
#define GN_ (G_*N_)     /* 64000 */

// ---------------- scratch (static device globals; no allocation) -------------
__device__ __half g_h[(size_t)GN_ * 128];  // h: [G,N,H*C] fp16
__device__ float g_asrc[GN_ * 4];
__device__ float g_adst[GN_ * 4];
__device__ float g_prep[8];               // c_edge[0..3], ew_mean at [4]
__device__ int   g_off[N_ + 1];
__device__ int   g_cur[N_];
__device__ int2  g_csr2[ET_];             // packed {src, weight-bits}
__device__ __half g_y[GN_ * D_];          // fp16 [bn][t][d]  (row rn = bn*16+t)
__device__ float g_z[BNP_ * D_];          // post-LN1 (zero-padded tail)
__device__ __half g_wkvh[64 * 128];       // fp16 Wqkv[:,64:192]
__device__ __half g_wqh[64 * 64];         // fp16 Wqkv[:,0:64]
__device__ __half g_woh[64 * 64];         // fp16 Wo
__device__ __half g_w1h[64 * FF_];        // fp16 W1
__device__ __half g_w2h[FF_ * 64];        // fp16 W2
__device__ float g_acc[4][BNP_ * D_];     // ffn split-K planes
__device__ int   g_cnt[64];               // per-row-block completion counters

union HCvt { __half2 h2; uint32_t u; };

// ---------------- mma helpers ------------------------------------------------
__device__ __forceinline__ uint32_t su32(const void* p) {
    uint32_t a;
    asm("{ .reg .u64 t; cvta.to.shared.u64 t, %1; cvt.u32.u64 %0, t; }" : "=r"(a) : "l"(p));
    return a;
}
__device__ __forceinline__ void ldsm_x4(uint32_t& r0, uint32_t& r1, uint32_t& r2, uint32_t& r3, uint32_t a) {
    asm volatile("ldmatrix.sync.aligned.m8n8.x4.shared.b16 {%0,%1,%2,%3}, [%4];"
                 : "=r"(r0), "=r"(r1), "=r"(r2), "=r"(r3) : "r"(a));
}
__device__ __forceinline__ void ldsm_x4t(uint32_t& r0, uint32_t& r1, uint32_t& r2, uint32_t& r3, uint32_t a) {
    asm volatile("ldmatrix.sync.aligned.m8n8.x4.trans.shared.b16 {%0,%1,%2,%3}, [%4];"
                 : "=r"(r0), "=r"(r1), "=r"(r2), "=r"(r3) : "r"(a));
}
__device__ __forceinline__ void mma16816(float* d, uint32_t a0, uint32_t a1, uint32_t a2, uint32_t a3,
                                         uint32_t b0, uint32_t b1) {
    asm volatile("mma.sync.aligned.m16n8k16.row.col.f32.f16.f16.f32 "
                 "{%0,%1,%2,%3}, {%4,%5,%6,%7}, {%8,%9}, {%0,%1,%2,%3};"
                 : "+f"(d[0]), "+f"(d[1]), "+f"(d[2]), "+f"(d[3])
                 : "r"(a0), "r"(a1), "r"(a2), "r"(a3), "r"(b0), "r"(b1));
}

// ---------------- weight conversion to fp16 ----------------------------------
__global__ void k_cvt(const float* __restrict__ Wqkv, const float* __restrict__ W1,
                      const float* __restrict__ W2, const float* __restrict__ Wo) {
    int i = blockIdx.x * 256 + threadIdx.x;
    if (i < 64 * 128) {
        int k = i >> 7, c = i & 127;
        g_wkvh[i] = __float2half(Wqkv[k * 192 + 64 + c]);
    }
    if (i < 64 * 64) {
        int k = i >> 6, c = i & 63;
        g_wqh[i] = __float2half(Wqkv[k * 192 + c]);
        g_woh[i] = __float2half(Wo[i]);
    }
    if (i < 64 * FF_) {
        g_w1h[i] = __float2half(W1[i]);
        g_w2h[i] = __float2half(W2[i]);
    }
}

// ---------------- hist + scan + edge consts (one kernel) ---------------------
__global__ void k_hist(const int* __restrict__ ei, const float* __restrict__ ew,
                       const float* __restrict__ W_edge,
                       const float* __restrict__ att_edge) {
    __shared__ int hist[2048];
    __shared__ float red[1024];
    __shared__ int ws[32];
    int t = threadIdx.x;
    hist[t] = 0; hist[t + 1024] = 0;
    __syncthreads();
    float s = 0.f;
    for (int i = t; i < ET_; i += 1024) {
        int d;
        if (i < E_) { d = ei[E_ + i]; s += ew[i]; }
        else d = i - E_;
        atomicAdd(&hist[d], 1);
    }
    red[t] = s;
    __syncthreads();
    for (int o = 512; o > 0; o >>= 1) {
        if (t < o) red[t] += red[t + o];
        __syncthreads();
    }
    if (t == 0) g_prep[4] = red[0] / (float)E_;
    if (t < 4) {
        float c = 0.f;
        for (int j = 0; j < 32; j++) c += W_edge[t * 32 + j] * att_edge[t * 32 + j];
        g_prep[t] = c;
    }
    int i0 = 2 * t, i1 = 2 * t + 1;
    int a = (i0 < N_) ? hist[i0] : 0;
    int b = (i1 < N_) ? hist[i1] : 0;
    int v = a + b;
    int lane = t & 31, wid = t >> 5;
#pragma unroll
    for (int off = 1; off < 32; off <<= 1) {
        int n = __shfl_up_sync(0xffffffffu, v, off);
        if (lane >= off) v += n;
    }
    if (lane == 31) ws[wid] = v;
    __syncthreads();
    if (t < 32) {
        int u = ws[t];
#pragma unroll
        for (int off = 1; off < 32; off <<= 1) {
            int n = __shfl_up_sync(0xffffffffu, u, off);
            if (t >= off) u += n;
        }
        ws[t] = u;
    }
    __syncthreads();
    int base = (wid > 0) ? ws[wid - 1] : 0;
    int incl = v + base;
    int ex0 = incl - a - b;
    if (i0 <= N_) { g_off[i0] = ex0; if (i0 < N_) g_cur[i0] = ex0; }
    if (i1 <= N_) { g_off[i1] = ex0 + a; if (i1 < N_) g_cur[i1] = ex0 + a; }
}

// ---------------- scatter: pack {src, weight} --------------------------------
__global__ void k_scatter(const int* __restrict__ ei, const float* __restrict__ ew) {
    int e = blockIdx.x * blockDim.x + threadIdx.x;
    if (e >= ET_) return;
    int d, src; float wgt;
    if (e < E_) { src = ei[e]; d = ei[E_ + e]; wgt = ew[e]; }
    else        { src = d = e - E_; wgt = g_prep[4]; }
    int pos = atomicAdd(&g_cur[d], 1);
    g_csr2[pos] = make_int2(src, __float_as_int(wgt));
}

// ---------------- h = x @ W_gat via HMMA; asrc/adst from fragments -----------
#define XA_ 24
#define XB_ 136
__global__ void __launch_bounds__(256) k_h(const float* __restrict__ x,
                                           const float* __restrict__ Wg,
                                           const float* __restrict__ as_w,
                                           const float* __restrict__ ad_w) {
    __shared__ __half xs[64 * XA_];
    __shared__ __half Bs[16 * XB_];
    __shared__ float s_as[128], s_ad[128];
    int tid = threadIdx.x, wid = tid >> 5, lane = tid & 31;
    int rb = blockIdx.x * 64;
    for (int i = tid; i < 256; i += 256) {
        int r = i >> 2, s4 = i & 3;
        float4 v = *(const float4*)&x[((size_t)(rb + r)) * 16 + s4 * 4];
        HCvt h0, h1;
        h0.h2 = __floats2half2_rn(v.x, v.y);
        h1.h2 = __floats2half2_rn(v.z, v.w);
        *(uint2*)&xs[r * XA_ + s4 * 4] = make_uint2(h0.u, h1.u);
    }
    for (int i = tid; i < 512; i += 256) {
        int r = i >> 5, c4 = i & 31;
        float4 v = *(const float4*)&Wg[r * 128 + c4 * 4];
        HCvt h0, h1;
        h0.h2 = __floats2half2_rn(v.x, v.y);
        h1.h2 = __floats2half2_rn(v.z, v.w);
        *(uint2*)&Bs[r * XB_ + c4 * 4] = make_uint2(h0.u, h1.u);
    }
    if (tid < 128) { s_as[tid] = as_w[tid]; s_ad[tid] = ad_w[tid]; }
    __syncthreads();
    int mi = wid >> 1;
    int nb = (wid & 1) * 64;
    float o[4][2][4];
#pragma unroll
    for (int j = 0; j < 4; j++)
#pragma unroll
        for (int n8 = 0; n8 < 2; n8++)
#pragma unroll
            for (int q = 0; q < 4; q++) o[j][n8][q] = 0.f;
    {
        uint32_t abase = su32(xs) + ((mi * 16 + (lane & 15)) * XA_ + (lane >> 4) * 8) * 2;
        uint32_t bbase = su32(Bs) + (((lane & 15)) * XB_ + nb + (lane >> 4) * 8) * 2;
        uint32_t a0, a1, a2, a3;
        ldsm_x4(a0, a1, a2, a3, abase);
#pragma unroll
        for (int j = 0; j < 4; j++) {
            uint32_t b0, b1, b2, b3;
            ldsm_x4t(b0, b1, b2, b3, bbase + (j * 16) * 2);
            mma16816(o[j][0], a0, a1, a2, a3, b0, b1);
            mma16816(o[j][1], a0, a1, a2, a3, b2, b3);
        }
    }
    int r0 = lane >> 2, c0 = (lane & 3) * 2;
    float vs[2][2] = {{0.f, 0.f}, {0.f, 0.f}};
    float vd[2][2] = {{0.f, 0.f}, {0.f, 0.f}};
#pragma unroll
    for (int j = 0; j < 4; j++)
#pragma unroll
        for (int n8 = 0; n8 < 2; n8++) {
            int col = nb + j * 16 + n8 * 8 + c0;
            float a0c = s_as[col], a1c = s_as[col + 1];
            float d0c = s_ad[col], d1c = s_ad[col + 1];
            int hj = j >> 1;
#pragma unroll
            for (int hm = 0; hm < 2; hm++) {
                float e0 = o[j][n8][hm * 2 + 0];
                float e1 = o[j][n8][hm * 2 + 1];
                vs[hm][hj] += e0 * a0c + e1 * a1c;
                vd[hm][hj] += e0 * d0c + e1 * d1c;
                int row = rb + mi * 16 + r0 + hm * 8;
                HCvt v; v.h2 = __floats2half2_rn(e0, e1);
                *(uint32_t*)&g_h[(size_t)row * 128 + col] = v.u;
            }
        }
#pragma unroll
    for (int hm = 0; hm < 2; hm++)
#pragma unroll
        for (int hj = 0; hj < 2; hj++) {
            vs[hm][hj] += __shfl_xor_sync(0xffffffffu, vs[hm][hj], 1);
            vs[hm][hj] += __shfl_xor_sync(0xffffffffu, vs[hm][hj], 2);
            vd[hm][hj] += __shfl_xor_sync(0xffffffffu, vd[hm][hj], 1);
            vd[hm][hj] += __shfl_xor_sync(0xffffffffu, vd[hm][hj], 2);
        }
    if ((lane & 3) == 0) {
        int hb = (nb >> 5);
#pragma unroll
        for (int hm = 0; hm < 2; hm++) {
            int row = rb + mi * 16 + r0 + hm * 8;
#pragma unroll
            for (int hj = 0; hj < 2; hj++) {
                g_asrc[(size_t)row * 4 + hb + hj] = vs[hm][hj];
                g_adst[(size_t)row * 4 + hb + hj] = vd[hm][hj];
            }
        }
    }
}

// ---------------- GAT aggregate v4: packed csr, 4 edges/warp -----------------
__global__ void __launch_bounds__(256) k_agg(const float* __restrict__ gbias,
                                             const float* __restrict__ Wp,
                                             const float* __restrict__ bp) {
    __shared__ float Wps[32 * 64];
    __shared__ float bias_s[32];
    __shared__ float bp_s[64];
    __shared__ float ce_s[4];
    __shared__ float sog[8][32];
    int tid = threadIdx.x;
    for (int i = tid; i < 2048; i += 256) Wps[i] = Wp[i];
    if (tid < 32) bias_s[tid] = gbias[tid];
    if (tid < 64) bp_s[tid] = bp[tid];
    if (tid < 4)  ce_s[tid] = g_prep[tid];
    __syncthreads();
    int wid = tid >> 5;
    int w = blockIdx.x * 8 + wid;
    int lane = tid & 31;
    int grp = lane >> 3;
    int ll = lane & 7;
    int hd = ll >> 1;
    int g = w / N_;
    int dst = w - g * N_;
    float ad = g_adst[((size_t)g * N_ + dst) * 4 + hd];
    float ce = ce_s[hd];
    float acc[16];
#pragma unroll
    for (int j = 0; j < 16; j++) acc[j] = 0.f;
    float den = 0.f;
    int beg = g_off[dst], end = g_off[dst + 1];
    const __half* hbase = g_h + (size_t)g * N_ * 128;
    const float* abase = g_asrc + (size_t)g * N_ * 4;
    int i = beg + grp;
    bool v = (i < end);
    int2 sw = v ? g_csr2[i] : make_int2(0, 0);
    int s = sw.x; float wgt = __int_as_float(sw.y);
    float as = abase[s * 4 + hd];
    uint4 h0 = *(const uint4*)(hbase + (size_t)s * 128 + ll * 16);
    uint4 h1 = *(const uint4*)(hbase + (size_t)s * 128 + ll * 16 + 8);
    int cnt = (end - beg + 3) >> 2;
    for (int it = 0; it < cnt; it++) {
        int in_ = i + 4;
        bool vn = (in_ < end);
        int2 swn = vn ? g_csr2[in_] : make_int2(0, 0);
        int sn = swn.x; float wn = __int_as_float(swn.y);
        float asn = abase[sn * 4 + hd];
        uint4 hn0 = *(const uint4*)(hbase + (size_t)sn * 128 + ll * 16);
        uint4 hn1 = *(const uint4*)(hbase + (size_t)sn * 128 + ll * 16 + 8);
        float lg = as + ad + ce * wgt;
        lg = (lg > 0.f) ? lg : 0.2f * lg;
        float p = v ? __expf(lg) : 0.f;
        den += p;
        const uint32_t* hw0 = &h0.x;
        const uint32_t* hw1 = &h1.x;
#pragma unroll
        for (int j2 = 0; j2 < 4; j2++) {
            float2 f0 = __half22float2(*(const __half2*)&hw0[j2]);
            float2 f1 = __half22float2(*(const __half2*)&hw1[j2]);
            acc[j2 * 2 + 0] += p * f0.x;
            acc[j2 * 2 + 1] += p * f0.y;
            acc[8 + j2 * 2 + 0] += p * f1.x;
            acc[8 + j2 * 2 + 1] += p * f1.y;
        }
        i = in_; v = vn; s = sn; wgt = wn; as = asn; h0 = hn0; h1 = hn1;
    }
    den += __shfl_xor_sync(0xffffffffu, den, 8);
    den += __shfl_xor_sync(0xffffffffu, den, 16);
    float inv = 1.f / (den + 1e-16f);
#pragma unroll
    for (int j = 0; j < 16; j++) {
        acc[j] += __shfl_xor_sync(0xffffffffu, acc[j], 8);
        acc[j] += __shfl_xor_sync(0xffffffffu, acc[j], 16);
        acc[j] *= inv;
        acc[j] += __shfl_xor_sync(0xffffffffu, acc[j], 2);
        acc[j] += __shfl_xor_sync(0xffffffffu, acc[j], 4);
        acc[j] = acc[j] * 0.25f + bias_s[(ll & 1) * 16 + j];
    }
    if (lane < 2) {
#pragma unroll
        for (int j = 0; j < 16; j++) sog[wid][lane * 16 + j] = acc[j];
    }
    __syncwarp();
    int d0 = lane * 2;
    float y0 = bp_s[d0], y1 = bp_s[d0 + 1];
#pragma unroll
    for (int c = 0; c < 32; c++) {
        float vv = sog[wid][c];
        float2 wv = *(const float2*)&Wps[c * 64 + d0];
        y0 += vv * wv.x; y1 += vv * wv.y;
    }
    int b = g >> 4;
    int t = g & 15;
    HCvt yo; yo.h2 = __floats2half2_rn(y0, y1);
    *(uint32_t*)&g_y[(((size_t)(b * N_ + dst)) * T_ + t) * D_ + d0] = yo.u;
}

// ---------------- fused KV-MMA + attention + Wo + residual + LN1 -------------
#define SA_ 72
#define SB_ 136
#define KVP_ 136
__global__ void __launch_bounds__(256) k_attn_fused(const float* __restrict__ bqkv,
                                                    const float* __restrict__ bo,
                                                    const float* __restrict__ ln1g,
                                                    const float* __restrict__ ln1b) {
    __shared__ __half AB[64 * SA_ + 64 * SB_];
    __shared__ float bqs[128];
    __shared__ __half2 Wqs2[64 * 32];
    __shared__ __half2 Wos2[64 * 32];
    __shared__ float bos[64], g1s[64], b1s[64], bq0[64];
    __shared__ float ys[4][64];
    __shared__ float sq[4][64];
    __half* Ah = AB;
    __half* Bs = AB + 64 * SA_;
    __half* KVs = AB;
    int tid = threadIdx.x, wid = tid >> 5, lane = tid & 31;
    int rb = blockIdx.x * 64;
    for (int i = tid; i < 512; i += 256) {
        int r = i >> 3, s = i & 7;
        *(uint4*)&Ah[r * SA_ + s * 8] = *(const uint4*)&g_y[((size_t)(rb + r)) * 64 + s * 8];
    }
    for (int i = tid; i < 1024; i += 256) {
        int r = i >> 4, s = i & 15;
        *(uint4*)&Bs[r * SB_ + s * 8] = *(const uint4*)&g_wkvh[r * 128 + s * 8];
    }
    for (int i = tid; i < 512; i += 256) {
        ((uint4*)Wos2)[i] = ((const uint4*)g_woh)[i];
        ((uint4*)Wqs2)[i] = ((const uint4*)g_wqh)[i];
    }
    if (tid < 128) bqs[tid] = bqkv[64 + tid];
    if (tid < 64) { bos[tid] = bo[tid]; g1s[tid] = ln1g[tid]; b1s[tid] = ln1b[tid]; bq0[tid] = bqkv[tid]; }
    __syncthreads();
    int mi = wid >> 1;
    int nb = (wid & 1) * 64;
    float o[4][2][4];
#pragma unroll
    for (int j = 0; j < 4; j++)
#pragma unroll
        for (int n8 = 0; n8 < 2; n8++)
#pragma unroll
            for (int q = 0; q < 4; q++) o[j][n8][q] = 0.f;
    {
        uint32_t abase = su32(Ah) + ((mi * 16 + (lane & 15)) * SA_ + (lane >> 4) * 8) * 2;
        uint32_t bbase = su32(Bs) + (((lane & 15)) * SB_ + nb + (lane >> 4) * 8) * 2;
#pragma unroll
        for (int k = 0; k < 4; k++) {
            uint32_t a0, a1, a2, a3;
            ldsm_x4(a0, a1, a2, a3, abase + k * 32);
#pragma unroll
            for (int j = 0; j < 4; j++) {
                uint32_t b0, b1, b2, b3;
                ldsm_x4t(b0, b1, b2, b3, bbase + (k * 16 * SB_ + j * 16) * 2);
                mma16816(o[j][0], a0, a1, a2, a3, b0, b1);
                mma16816(o[j][1], a0, a1, a2, a3, b2, b3);
            }
        }
    }
    __syncthreads();
    {
        int r0 = lane >> 2, c0 = (lane & 3) * 2;
#pragma unroll
        for (int j = 0; j < 4; j++)
#pragma unroll
            for (int n8 = 0; n8 < 2; n8++)
#pragma unroll
                for (int hm = 0; hm < 2; hm++) {
                    int row = mi * 16 + r0 + hm * 8;
                    int col = nb + j * 16 + n8 * 8 + c0;
                    HCvt v; v.h2 = __floats2half2_rn(o[j][n8][hm * 2 + 0] + bqs[col],
                                                     o[j][n8][hm * 2 + 1] + bqs[col + 1]);
                    *(uint32_t*)&KVs[row * KVP_ + col] = v.u;
                }
    }
    __syncthreads();
    if (wid >= 4) return;
    int r = blockIdx.x * 4 + wid;
    int lb = wid;
    int dcol = lane * 2;
    __half2 yh = *(const __half2*)&g_y[((size_t)(r * 16 + 15)) * 64 + dcol];
    float2 yv = __half22float2(yh);
    ys[lb][dcol] = yv.x; ys[lb][dcol + 1] = yv.y;
    __syncwarp();
    float q0 = bq0[dcol], q1 = bq0[dcol + 1];
#pragma unroll 16
    for (int j = 0; j < 64; j++) {
        float yj = ys[lb][j];
        float2 wv = __half22float2(Wqs2[j * 32 + lane]);
        q0 += yj * wv.x; q1 += yj * wv.y;
    }
    sq[lb][dcol] = q0; sq[lb][dcol + 1] = q1;
    __syncwarp();
    int t = lane & 15, grp = lane >> 4;
    const __half* kbase = &KVs[(lb * 16 + t) * KVP_ + grp * 32];
    const float* qq = &sq[lb][grp * 32];
    uint4 kr0 = *(const uint4*)&kbase[0];
    uint4 kr1 = *(const uint4*)&kbase[8];
    uint4 kr2 = *(const uint4*)&kbase[16];
    uint4 kr3 = *(const uint4*)&kbase[24];
    float s0 = 0.f, s1 = 0.f;
    {
        const uint32_t* kw0 = &kr0.x;
        const uint32_t* kw1 = &kr1.x;
#pragma unroll
        for (int j2 = 0; j2 < 4; j2++) {
            float2 f0 = __half22float2(*(const __half2*)&kw0[j2]);
            float2 f1 = __half22float2(*(const __half2*)&kw1[j2]);
            s0 += qq[j2 * 2 + 0] * f0.x + qq[j2 * 2 + 1] * f0.y;
            s0 += qq[8 + j2 * 2 + 0] * f1.x + qq[8 + j2 * 2 + 1] * f1.y;
        }
        const uint32_t* kw2 = &kr2.x;
        const uint32_t* kw3 = &kr3.x;
#pragma unroll
        for (int j2 = 0; j2 < 4; j2++) {
            float2 f2 = __half22float2(*(const __half2*)&kw2[j2]);
            float2 f3 = __half22float2(*(const __half2*)&kw3[j2]);
            s1 += qq[16 + j2 * 2 + 0] * f2.x + qq[16 + j2 * 2 + 1] * f2.y;
            s1 += qq[24 + j2 * 2 + 0] * f3.x + qq[24 + j2 * 2 + 1] * f3.y;
        }
    }
    s0 *= 0.25f; s1 *= 0.25f;
    float m0 = s0, m1 = s1;
#pragma unroll
    for (int off = 1; off < 16; off <<= 1) {
        m0 = fmaxf(m0, __shfl_xor_sync(0xffffffffu, m0, off));
        m1 = fmaxf(m1, __shfl_xor_sync(0xffffffffu, m1, off));
    }
    float p0 = __expf(s0 - m0), p1 = __expf(s1 - m1);
    float dn0 = p0, dn1 = p1;
#pragma unroll
    for (int off = 1; off < 16; off <<= 1) {
        dn0 += __shfl_xor_sync(0xffffffffu, dn0, off);
        dn1 += __shfl_xor_sync(0xffffffffu, dn1, off);
    }
    p0 /= dn0; p1 /= dn1;
    int hd = lane >> 3;
    int srcbase = (hd >> 1) * 16;
    int sel = hd & 1;
    float c0v = 0.f, c1v = 0.f;
#pragma unroll
    for (int tt = 0; tt < 16; tt++) {
        float pa = __shfl_sync(0xffffffffu, p0, srcbase + tt);
        float pb = __shfl_sync(0xffffffffu, p1, srcbase + tt);
        float pv = sel ? pb : pa;
        float2 v2 = __half22float2(*(const __half2*)&KVs[(lb * 16 + tt) * KVP_ + 64 + dcol]);
        c0v += pv * v2.x; c1v += pv * v2.y;
    }
    float o0 = bos[dcol], o1 = bos[dcol + 1];
#pragma unroll
    for (int jj = 0; jj < 32; jj++) {
        float ca = __shfl_sync(0xffffffffu, c0v, jj);
        float cb = __shfl_sync(0xffffffffu, c1v, jj);
        float2 wA = __half22float2(Wos2[(2 * jj) * 32 + lane]);
        float2 wB = __half22float2(Wos2[(2 * jj + 1) * 32 + lane]);
        o0 += ca * wA.x + cb * wB.x;
        o1 += ca * wA.y + cb * wB.y;
    }
    float r0v = ys[lb][dcol] + o0, r1v = ys[lb][dcol + 1] + o1;
    float su = r0v + r1v, s2 = r0v * r0v + r1v * r1v;
#pragma unroll
    for (int off = 1; off < 32; off <<= 1) {
        su += __shfl_xor_sync(0xffffffffu, su, off);
        s2 += __shfl_xor_sync(0xffffffffu, s2, off);
    }
    float mu = su * (1.f / 64.f);
    float var = s2 * (1.f / 64.f) - mu * mu;
    float inv = rsqrtf(var + 1e-5f);
    float2 z;
    z.x = (r0v - mu) * inv * g1s[dcol] + b1s[dcol];
    z.y = (r1v - mu) * inv * g1s[dcol + 1] + b1s[dcol + 1];
    *(float2*)&g_z[(size_t)r * 64 + dcol] = z;
}

// ---------------- fused FFN 64-row tiles, split-K(4), LN2 epilogue -----------
__global__ void __launch_bounds__(256) k_ffn(const float* __restrict__ b1,
                                             const float* __restrict__ b2,
                                             const float* __restrict__ ln2g,
                                             const float* __restrict__ ln2b,
                                             float* __restrict__ out) {
    __shared__ __half Ah[64 * SA_];
    __shared__ __half Sh[64 * SA_];
    __shared__ __half W1s[64 * SA_];
    __shared__ __half W2s[64 * SA_];
    __shared__ float b1s[512];
    __shared__ bool last_s;
    int tid = threadIdx.x, wid = tid >> 5, lane = tid & 31;
    int rb = blockIdx.x * 64;
    int kc0 = blockIdx.y * 512;
    for (int i = tid; i < 64 * 16; i += 256) {
        int r = i >> 4, s4 = i & 15;
        float4 v = *(const float4*)&g_z[((size_t)(rb + r)) * 64 + s4 * 4];
        HCvt h0, h1;
        h0.h2 = __floats2half2_rn(v.x, v.y);
        h1.h2 = __floats2half2_rn(v.z, v.w);
        *(uint2*)&Ah[r * SA_ + s4 * 4] = make_uint2(h0.u, h1.u);
    }
    for (int i = tid; i < 512; i += 256) b1s[i] = b1[kc0 + i];
    int mi = wid & 3, nj = wid >> 2;     // mi: m16 tile (0..3), nj: n32 tile (0..1)
    float o[2][2][4];
#pragma unroll
    for (int n16 = 0; n16 < 2; n16++)
#pragma unroll
        for (int n8 = 0; n8 < 2; n8++)
#pragma unroll
            for (int q = 0; q < 4; q++) o[n16][n8][q] = 0.f;
    int r0 = lane >> 2, c0 = (lane & 3) * 2;
    uint32_t a1base = su32(Ah) + ((mi * 16 + (lane & 15)) * SA_ + (lane >> 4) * 8) * 2;
    uint32_t a2base = su32(Sh) + ((mi * 16 + (lane & 15)) * SA_ + (lane >> 4) * 8) * 2;
    uint32_t w1base = su32(W1s) + (((lane & 15)) * SA_ + nj * 32 + (lane >> 4) * 8) * 2;
    uint32_t w2base = su32(W2s) + (((lane & 15)) * SA_ + nj * 32 + (lane >> 4) * 8) * 2;
    for (int cb = kc0; cb < kc0 + 512; cb += 64) {
        __syncthreads();
        for (int i = tid; i < 512; i += 256) {
            int r = i >> 3, s = i & 7;
            *(uint4*)&W1s[r * SA_ + s * 8] = *(const uint4*)&g_w1h[(size_t)r * FF_ + cb + s * 8];
            *(uint4*)&W2s[r * SA_ + s * 8] = *(const uint4*)&g_w2h[(size_t)(cb + r) * 64 + s * 8];
        }
        __syncthreads();
        float d[2][2][4];
#pragma unroll
        for (int n16 = 0; n16 < 2; n16++)
#pragma unroll
            for (int n8 = 0; n8 < 2; n8++)
#pragma unroll
                for (int q = 0; q < 4; q++) d[n16][n8][q] = 0.f;
#pragma unroll
        for (int k = 0; k < 4; k++) {
            uint32_t a0, a1, a2, a3, b0v, b1v, b2v, b3v, c0v, c1v, c2v, c3v;
            ldsm_x4(a0, a1, a2, a3, a1base + k * 32);
            ldsm_x4t(b0v, b1v, b2v, b3v, w1base + (k * 16 * SA_) * 2);
            ldsm_x4t(c0v, c1v, c2v, c3v, w1base + (k * 16 * SA_ + 16) * 2);
            mma16816(d[0][0], a0, a1, a2, a3, b0v, b1v);
            mma16816(d[0][1], a0, a1, a2, a3, b2v, b3v);
            mma16816(d[1][0], a0, a1, a2, a3, c0v, c1v);
            mma16816(d[1][1], a0, a1, a2, a3, c2v, c3v);
        }
#pragma unroll
        for (int n16 = 0; n16 < 2; n16++)
#pragma unroll
            for (int n8 = 0; n8 < 2; n8++) {
                int col = nj * 32 + n16 * 16 + n8 * 8 + c0;
                float bb0 = b1s[cb - kc0 + col], bb1 = b1s[cb - kc0 + col + 1];
                HCvt v0, v1;
                v0.h2 = __floats2half2_rn(fmaxf(d[n16][n8][0] + bb0, 0.f), fmaxf(d[n16][n8][1] + bb1, 0.f));
                v1.h2 = __floats2half2_rn(fmaxf(d[n16][n8][2] + bb0, 0.f), fmaxf(d[n16][n8][3] + bb1, 0.f));
                *(uint32_t*)&Sh[(mi * 16 + r0) * SA_ + col] = v0.u;
                *(uint32_t*)&Sh[(mi * 16 + r0 + 8) * SA_ + col] = v1.u;
            }
        __syncthreads();
#pragma unroll
        for (int k = 0; k < 4; k++) {
            uint32_t a0, a1, a2, a3, b0v, b1v, b2v, b3v, c0v, c1v, c2v, c3v;
            ldsm_x4(a0, a1, a2, a3, a2base + k * 32);
            ldsm_x4t(b0v, b1v, b2v, b3v, w2base + (k * 16 * SA_) * 2);
            ldsm_x4t(c0v, c1v, c2v, c3v, w2base + (k * 16 * SA_ + 16) * 2);
            mma16816(o[0][0], a0, a1, a2, a3, b0v, b1v);
            mma16816(o[0][1], a0, a1, a2, a3, b2v, b3v);
            mma16816(o[1][0], a0, a1, a2, a3, c0v, c1v);
            mma16816(o[1][1], a0, a1, a2, a3, c2v, c3v);
        }
    }
    float* plane = g_acc[blockIdx.y];
#pragma unroll
    for (int n16 = 0; n16 < 2; n16++)
#pragma unroll
        for (int n8 = 0; n8 < 2; n8++) {
            int col = nj * 32 + n16 * 16 + n8 * 8 + c0;
            int row = rb + mi * 16 + r0;
            *(float2*)&plane[(size_t)row * 64 + col] = make_float2(o[n16][n8][0], o[n16][n8][1]);
            *(float2*)&plane[(size_t)(row + 8) * 64 + col] = make_float2(o[n16][n8][2], o[n16][n8][3]);
        }
    __threadfence();
    __syncthreads();
    if (tid == 0) {
        int old = atomicAdd(&g_cnt[blockIdx.x], 1);
        last_s = (old == 3);
        if (last_s) g_cnt[blockIdx.x] = 0;
    }
    __syncthreads();
    if (!last_s) return;
    int d2 = lane * 2;
    for (int rr = wid; rr < 64; rr += 8) {
        int r = rb + rr;
        if (r >= BN_) break;
        float2 zr = *(const float2*)&g_z[(size_t)r * 64 + d2];
        float v0 = zr.x + b2[d2];
        float v1 = zr.y + b2[d2 + 1];
#pragma unroll
        for (int pp = 0; pp < 4; pp++) {
            float2 pv = *(const float2*)&g_acc[pp][(size_t)r * 64 + d2];
            v0 += pv.x; v1 += pv.y;
        }
        float su = v0 + v1, s2 = v0 * v0 + v1 * v1;
#pragma unroll
        for (int off = 1; off < 32; off <<= 1) {
            su += __shfl_xor_sync(0xffffffffu, su, off);
            s2 += __shfl_xor_sync(0xffffffffu, s2, off);
        }
        float mu = su * (1.f / 64.f);
        float var = s2 * (1.f / 64.f) - mu * mu;
        float inv = rsqrtf(var + 1e-5f);
        float2 oo;
        oo.x = (v0 - mu) * inv * ln2g[d2] + ln2b[d2];
        oo.y = (v1 - mu) * inv * ln2g[d2 + 1] + ln2b[d2 + 1];
        *(float2*)&out[(size_t)r * 64 + d2] = oo;
    }
}

// ---------------- launch (graph-parallel branches via fork-join) -------------
extern "C" void kernel_launch(void* const* d_in, const int* in_sizes, int n_in,
                              void* d_out, int out_size) {
    const float* x_seq    = (const float*)d_in[0];
    const int*   eidx     = (const int*)d_in[1];
    const float* eweight  = (const float*)d_in[2];
    const float* W_gat    = (const float*)d_in[3];
    const float* att_src  = (const float*)d_in[4];
    const float* att_dst  = (const float*)d_in[5];
    const float* W_edge   = (const float*)d_in[6];
    const float* att_edge = (const float*)d_in[7];
    const float* gat_bias = (const float*)d_in[8];
    const float* W_proj   = (const float*)d_in[9];
    const float* b_proj   = (const float*)d_in[10];
    const float* Wqkv     = (const float*)d_in[11];
    const float* bqkv     = (const float*)d_in[12];
    const float* Wo       = (const float*)d_in[13];
    const float* bo       = (const float*)d_in[14];
    const float* ln1_g    = (const float*)d_in[15];
    const float* ln1_b    = (const float*)d_in[16];
    const float* W1       = (const float*)d_in[17];
    const float* b1       = (const float*)d_in[18];
    const float* W2       = (const float*)d_in[19];
    const float* b2       = (const float*)d_in[20];
    const float* ln2_g    = (const float*)d_in[21];
    const float* ln2_b    = (const float*)d_in[22];
    float* out = (float*)d_out;

    static cudaStream_t sB = nullptr, sC = nullptr;
    static cudaEvent_t evRoot = nullptr, evB = nullptr, evC = nullptr;
    if (sB == nullptr) {
        cudaStreamCreateWithFlags(&sB, cudaStreamNonBlocking);
        cudaStreamCreateWithFlags(&sC, cudaStreamNonBlocking);
        cudaEventCreateWithFlags(&evRoot, cudaEventDisableTiming);
        cudaEventCreateWithFlags(&evB, cudaEventDisableTiming);
        cudaEventCreateWithFlags(&evC, cudaEventDisableTiming);
    }

    cudaEventRecord(evRoot, 0);
    cudaStreamWaitEvent(sB, evRoot, 0);
    cudaStreamWaitEvent(sC, evRoot, 0);

    // branch B: CSR build (feeds k_agg)
    k_hist<<<1, 1024, 0, sB>>>(eidx, eweight, W_edge, att_edge);
    k_scatter<<<(ET_ + 255) / 256, 256, 0, sB>>>(eidx, eweight);
    cudaEventRecord(evB, sB);

    // branch C: fp16 weight conversion
    k_cvt<<<512, 256, 0, sC>>>(Wqkv, W1, W2, Wo);
    cudaEventRecord(evC, sC);

    // main branch: node features via HMMA
    k_h<<<GN_ / 64, 256>>>(x_seq, W_gat, att_src, att_dst);

    cudaStreamWaitEvent(0, evB, 0);
    k_agg<<<GN_ / 8, 256>>>(gat_bias, W_proj, b_proj);

    cudaStreamWaitEvent(0, evC, 0);
    k_attn_fused<<<BN_ / 4, 256>>>(bqkv, bo, ln1_g, ln1_b);
    {
        dim3 grid((BN_ + 63) / 64, 4);
        k_ffn<<<grid, 256>>>(b1, b2, ln2_g, ln2_b, out);
    }
}